// round 1
// baseline (speedup 1.0000x reference)
#include <cuda_runtime.h>
#include <cuda_bf16.h>
#include <math.h>

// ---------------------------------------------------------------------------
// Problem constants
// ---------------------------------------------------------------------------
#define LAYERS 4
#define BATCH  64
#define NTOK   196
#define CDIM   768
#define CNEW   960
#define HIDDIM 3072
#define NHEAD  12
#define HD     64
#define HDK    80
#define MTOK   49      // reduced tokens 7x7
#define HW     14

#define ROWS_X (BATCH * NTOK)   // 12544
#define ROWS_R (BATCH * MTOK)   // 3136

// ---------------------------------------------------------------------------
// Scratch (device globals; allocation is forbidden)
// ---------------------------------------------------------------------------
__device__ float g_y[ROWS_X * CDIM];       // ln1(x) / reused as z = ln2(x)
__device__ float g_q[ROWS_X * CNEW];       // q projection
__device__ float g_rconv[ROWS_R * CDIM];   // depthwise-conv output, (b,m,c)
__device__ float g_r0[ROWS_R * CNEW];      // pw conv output (pre-LN)
__device__ float g_r[ROWS_R * CNEW];       // gelu(LN(r0))
__device__ float g_k[ROWS_R * CNEW];
__device__ float g_v[ROWS_R * CDIM];
__device__ float g_o[ROWS_X * CDIM];       // attention output
__device__ float g_h[ROWS_X * HIDDIM];     // mlp hidden

// ---------------------------------------------------------------------------
// Helpers
// ---------------------------------------------------------------------------
__device__ __forceinline__ float gelu_exact(float x) {
    return 0.5f * x * (1.0f + erff(x * 0.7071067811865476f));
}

// ---------------------------------------------------------------------------
// LayerNorm (optionally fused exact-GELU).  One block per row.
// ---------------------------------------------------------------------------
__global__ void ln_kernel(const float* __restrict__ in, float* __restrict__ out,
                          const float* __restrict__ gamma, const float* __restrict__ beta,
                          int W, float eps, int do_gelu) {
    const int row = blockIdx.x;
    const float* p = in + (size_t)row * W;
    float s = 0.f, ss = 0.f;
    for (int i = threadIdx.x; i < W; i += blockDim.x) {
        float v = p[i];
        s += v; ss += v * v;
    }
    __shared__ float red_s[32], red_ss[32];
    int lane = threadIdx.x & 31, wid = threadIdx.x >> 5;
    #pragma unroll
    for (int off = 16; off; off >>= 1) {
        s  += __shfl_xor_sync(0xffffffffu, s, off);
        ss += __shfl_xor_sync(0xffffffffu, ss, off);
    }
    if (lane == 0) { red_s[wid] = s; red_ss[wid] = ss; }
    __syncthreads();
    int nw = blockDim.x >> 5;
    if (wid == 0) {
        s  = (lane < nw) ? red_s[lane]  : 0.f;
        ss = (lane < nw) ? red_ss[lane] : 0.f;
        #pragma unroll
        for (int off = 16; off; off >>= 1) {
            s  += __shfl_xor_sync(0xffffffffu, s, off);
            ss += __shfl_xor_sync(0xffffffffu, ss, off);
        }
        if (lane == 0) { red_s[0] = s; red_ss[0] = ss; }
    }
    __syncthreads();
    float mean = red_s[0] / (float)W;
    float var  = red_ss[0] / (float)W - mean * mean;
    float inv  = rsqrtf(var + eps);
    float* q = out + (size_t)row * W;
    for (int i = threadIdx.x; i < W; i += blockDim.x) {
        float v = (p[i] - mean) * inv * gamma[i] + beta[i];
        if (do_gelu) v = gelu_exact(v);
        q[i] = v;
    }
}

// ---------------------------------------------------------------------------
// Strided depthwise 2x2/stride-2 conv.  y is (B, N=196, C) token-major;
// output rconv is (B, M=49, C).
// ---------------------------------------------------------------------------
__global__ void dwconv_kernel(const float* __restrict__ y,
                              const float* __restrict__ w4,   // (C,4)
                              const float* __restrict__ bias, // (C)
                              float* __restrict__ out) {
    const int m = blockIdx.x;   // 0..48
    const int b = blockIdx.y;   // 0..63
    const int h7 = m / 7, w7 = m % 7;
    const int p00 = (h7 * 2) * HW + w7 * 2;
    const float* yb = y + (size_t)b * NTOK * CDIM;
    float* ob = out + ((size_t)b * MTOK + m) * CDIM;
    for (int c = threadIdx.x; c < CDIM; c += blockDim.x) {
        float acc = yb[(size_t)(p00     ) * CDIM + c] * w4[c * 4 + 0]
                  + yb[(size_t)(p00 + 1 ) * CDIM + c] * w4[c * 4 + 1]
                  + yb[(size_t)(p00 + HW) * CDIM + c] * w4[c * 4 + 2]
                  + yb[(size_t)(p00 + HW + 1) * CDIM + c] * w4[c * 4 + 3]
                  + bias[c];
        ob[c] = acc;
    }
}

// ---------------------------------------------------------------------------
// Tiled fp32 GEMM:  C[M,N] = A[M,K] @ W[K,N]  (+bias / +gelu / +residual)
// BM=128 BN=64 BK=16, 256 threads, 8x4 accum per thread.
// EPI: 0 = store, 1 = +bias, 2 = +bias then gelu, 3 = +bias + residual
// Requires: N % 64 == 0, K % 16 == 0 (M arbitrary).
// ---------------------------------------------------------------------------
#define BM 128
#define BN 64
#define BK 16

template <int EPI>
__global__ __launch_bounds__(256) void sgemm_kernel(
        const float* __restrict__ A, const float* __restrict__ W,
        const float* __restrict__ bias, const float* __restrict__ resid,
        float* __restrict__ C, int M, int N, int K) {
    __shared__ float As[BK][BM];
    __shared__ float Bs[BK][BN];

    const int tid = threadIdx.x;
    const int tx = tid & 15;        // 0..15 -> N
    const int ty = tid >> 4;        // 0..15 -> M
    const int row0 = blockIdx.y * BM;
    const int col0 = blockIdx.x * BN;

    float acc[8][4];
    #pragma unroll
    for (int i = 0; i < 8; i++)
        #pragma unroll
        for (int j = 0; j < 4; j++) acc[i][j] = 0.f;

    for (int k0 = 0; k0 < K; k0 += BK) {
        // load A tile (128x16) as 512 float4, 2 per thread, store transposed
        #pragma unroll
        for (int i = 0; i < 2; i++) {
            int f  = tid + i * 256;
            int m  = f >> 2;
            int kq = (f & 3) * 4;
            int gm = row0 + m;
            float4 v;
            if (gm < M) v = *(const float4*)&A[(size_t)gm * K + k0 + kq];
            else        v = make_float4(0.f, 0.f, 0.f, 0.f);
            As[kq + 0][m] = v.x; As[kq + 1][m] = v.y;
            As[kq + 2][m] = v.z; As[kq + 3][m] = v.w;
        }
        // load B tile (16x64) as 256 float4, 1 per thread
        {
            int kb = tid >> 4;
            int nq = (tid & 15) * 4;
            *(float4*)&Bs[kb][nq] = *(const float4*)&W[(size_t)(k0 + kb) * N + col0 + nq];
        }
        __syncthreads();
        #pragma unroll
        for (int kk = 0; kk < BK; kk++) {
            float a[8], bb[4];
            #pragma unroll
            for (int i = 0; i < 8; i++) a[i] = As[kk][ty * 8 + i];
            #pragma unroll
            for (int j = 0; j < 4; j++) bb[j] = Bs[kk][tx * 4 + j];
            #pragma unroll
            for (int i = 0; i < 8; i++)
                #pragma unroll
                for (int j = 0; j < 4; j++)
                    acc[i][j] = fmaf(a[i], bb[j], acc[i][j]);
        }
        __syncthreads();
    }

    #pragma unroll
    for (int i = 0; i < 8; i++) {
        int gm = row0 + ty * 8 + i;
        if (gm >= M) continue;
        #pragma unroll
        for (int j = 0; j < 4; j++) {
            int gn = col0 + tx * 4 + j;
            float v = acc[i][j];
            if (EPI >= 1) v += bias[gn];
            if (EPI == 2) v = gelu_exact(v);
            if (EPI == 3) v += resid[(size_t)gm * N + gn];
            C[(size_t)gm * N + gn] = v;
        }
    }
}

// ---------------------------------------------------------------------------
// Attention: per (b,h) block.  q:(B,N,960) k:(B,49,960) v:(B,49,768)
// o:(B,N,768).  scale = 1/sqrt(80).
// ---------------------------------------------------------------------------
__global__ __launch_bounds__(128) void attn_kernel(
        const float* __restrict__ q, const float* __restrict__ k,
        const float* __restrict__ v, float* __restrict__ o) {
    const int b = blockIdx.x / NHEAD;
    const int h = blockIdx.x % NHEAD;
    __shared__ float ks[MTOK][HDK + 1];  // pad to 81 (odd stride -> conflict-free)
    __shared__ float vs[MTOK][HD + 1];   // pad to 65
    __shared__ float qs[4][HDK];
    __shared__ float ps[4][MTOK];

    const int tid = threadIdx.x, w = tid >> 5, lane = tid & 31;
    const float* kb = k + (size_t)b * MTOK * CNEW + h * HDK;
    const float* vb = v + (size_t)b * MTOK * CDIM + h * HD;
    for (int i = tid; i < MTOK * HDK; i += 128) {
        int m = i / HDK, d = i % HDK;
        ks[m][d] = kb[(size_t)m * CNEW + d];
    }
    for (int i = tid; i < MTOK * HD; i += 128) {
        int m = i / HD, d = i % HD;
        vs[m][d] = vb[(size_t)m * CDIM + d];
    }
    __syncthreads();

    const float scale = rsqrtf(80.0f);
    for (int n = w; n < NTOK; n += 4) {
        const float* qp = q + ((size_t)(b * NTOK + n)) * CNEW + h * HDK;
        for (int i = lane; i < HDK; i += 32) qs[w][i] = qp[i];
        __syncwarp();
        float s0 = 0.f, s1 = 0.f;
        #pragma unroll
        for (int d = 0; d < HDK; d++) {
            float qv = qs[w][d];
            s0 = fmaf(qv, ks[lane][d], s0);
            if (lane < MTOK - 32) s1 = fmaf(qv, ks[lane + 32][d], s1);
        }
        s0 *= scale; s1 *= scale;
        float mx = fmaxf(s0, (lane < MTOK - 32) ? s1 : -1e30f);
        #pragma unroll
        for (int off = 16; off; off >>= 1)
            mx = fmaxf(mx, __shfl_xor_sync(0xffffffffu, mx, off));
        float e0 = expf(s0 - mx);
        float e1 = (lane < MTOK - 32) ? expf(s1 - mx) : 0.f;
        float sm = e0 + e1;
        #pragma unroll
        for (int off = 16; off; off >>= 1)
            sm += __shfl_xor_sync(0xffffffffu, sm, off);
        float inv = 1.f / sm;
        ps[w][lane] = e0 * inv;
        if (lane < MTOK - 32) ps[w][lane + 32] = e1 * inv;
        __syncwarp();
        float a0 = 0.f, a1 = 0.f;
        #pragma unroll
        for (int m = 0; m < MTOK; m++) {
            float p = ps[w][m];
            a0 = fmaf(p, vs[m][lane], a0);
            a1 = fmaf(p, vs[m][lane + 32], a1);
        }
        float* op = o + ((size_t)(b * NTOK + n)) * CDIM + h * HD;
        op[lane] = a0;
        op[lane + 32] = a1;
        __syncwarp();
    }
}

// ---------------------------------------------------------------------------
// Host launch
// ---------------------------------------------------------------------------
static inline int cdiv(int a, int b) { return (a + b - 1) / b; }

extern "C" void kernel_launch(void* const* d_in, const int* in_sizes, int n_in,
                              void* d_out, int out_size) {
    const float* x_in   = (const float*)d_in[0];
    const float* q_w    = (const float*)d_in[1];
    const float* dw_w   = (const float*)d_in[2];
    const float* dw_b   = (const float*)d_in[3];
    const float* pw_w   = (const float*)d_in[4];
    const float* pw_b   = (const float*)d_in[5];
    const float* lnr_g  = (const float*)d_in[6];
    const float* lnr_b  = (const float*)d_in[7];
    const float* k_w    = (const float*)d_in[8];
    const float* v_w    = (const float*)d_in[9];
    const float* proj_w = (const float*)d_in[10];
    const float* proj_b = (const float*)d_in[11];
    const float* ln1_g  = (const float*)d_in[12];
    const float* ln1_b  = (const float*)d_in[13];
    const float* ln2_g  = (const float*)d_in[14];
    const float* ln2_b  = (const float*)d_in[15];
    const float* fc1_w  = (const float*)d_in[16];
    const float* fc1_b  = (const float*)d_in[17];
    const float* fc2_w  = (const float*)d_in[18];
    const float* fc2_b  = (const float*)d_in[19];

    float* xcur = (float*)d_out;

    float *p_y, *p_q, *p_rconv, *p_r0, *p_r, *p_k, *p_v, *p_o, *p_h;
    cudaGetSymbolAddress((void**)&p_y,     g_y);
    cudaGetSymbolAddress((void**)&p_q,     g_q);
    cudaGetSymbolAddress((void**)&p_rconv, g_rconv);
    cudaGetSymbolAddress((void**)&p_r0,    g_r0);
    cudaGetSymbolAddress((void**)&p_r,     g_r);
    cudaGetSymbolAddress((void**)&p_k,     g_k);
    cudaGetSymbolAddress((void**)&p_v,     g_v);
    cudaGetSymbolAddress((void**)&p_o,     g_o);
    cudaGetSymbolAddress((void**)&p_h,     g_h);

    // x working copy lives in d_out
    cudaMemcpyAsync(xcur, x_in, (size_t)ROWS_X * CDIM * sizeof(float),
                    cudaMemcpyDeviceToDevice, 0);

    for (int l = 0; l < LAYERS; l++) {
        // --- attention branch ---
        // y = LN(x) with eps 1e-6
        ln_kernel<<<ROWS_X, 256>>>(xcur, p_y, ln1_g + l * CDIM, ln1_b + l * CDIM,
                                   CDIM, 1e-6f, 0);
        // depthwise 2x2 stride-2 reduction -> (B,49,C)
        dwconv_kernel<<<dim3(MTOK, BATCH), 256>>>(p_y, dw_w + (size_t)l * CDIM * 4,
                                                  dw_b + l * CDIM, p_rconv);
        // pointwise conv: r0 = rconv @ pw_w + pw_b   (3136 x 960, K=768)
        sgemm_kernel<1><<<dim3(CNEW / BN, cdiv(ROWS_R, BM)), 256>>>(
            p_rconv, pw_w + (size_t)l * CDIM * CNEW, pw_b + l * CNEW, nullptr,
            p_r0, ROWS_R, CNEW, CDIM);
        // r = gelu(LN(r0)) eps 1e-5
        ln_kernel<<<ROWS_R, 256>>>(p_r0, p_r, lnr_g + l * CNEW, lnr_b + l * CNEW,
                                   CNEW, 1e-5f, 1);
        // q = y @ q_w            (12544 x 960, K=768)
        sgemm_kernel<0><<<dim3(CNEW / BN, cdiv(ROWS_X, BM)), 256>>>(
            p_y, q_w + (size_t)l * CDIM * CNEW, nullptr, nullptr,
            p_q, ROWS_X, CNEW, CDIM);
        // k = r @ k_w            (3136 x 960, K=960)
        sgemm_kernel<0><<<dim3(CNEW / BN, cdiv(ROWS_R, BM)), 256>>>(
            p_r, k_w + (size_t)l * CNEW * CNEW, nullptr, nullptr,
            p_k, ROWS_R, CNEW, CNEW);
        // v = r @ v_w            (3136 x 768, K=960)
        sgemm_kernel<0><<<dim3(CDIM / BN, cdiv(ROWS_R, BM)), 256>>>(
            p_r, v_w + (size_t)l * CNEW * CDIM, nullptr, nullptr,
            p_v, ROWS_R, CDIM, CNEW);
        // attention -> o
        attn_kernel<<<BATCH * NHEAD, 128>>>(p_q, p_k, p_v, p_o);
        // x += o @ proj_w + proj_b
        sgemm_kernel<3><<<dim3(CDIM / BN, cdiv(ROWS_X, BM)), 256>>>(
            p_o, proj_w + (size_t)l * CDIM * CDIM, proj_b + l * CDIM, xcur,
            xcur, ROWS_X, CDIM, CDIM);

        // --- MLP branch ---
        // z = LN(x) eps 1e-6 (reuse g_y)
        ln_kernel<<<ROWS_X, 256>>>(xcur, p_y, ln2_g + l * CDIM, ln2_b + l * CDIM,
                                   CDIM, 1e-6f, 0);
        // h = gelu(z @ fc1 + b)  (12544 x 3072, K=768)
        sgemm_kernel<2><<<dim3(HIDDIM / BN, cdiv(ROWS_X, BM)), 256>>>(
            p_y, fc1_w + (size_t)l * CDIM * HIDDIM, fc1_b + l * HIDDIM, nullptr,
            p_h, ROWS_X, HIDDIM, CDIM);
        // x += h @ fc2 + b       (12544 x 768, K=3072)
        sgemm_kernel<3><<<dim3(CDIM / BN, cdiv(ROWS_X, BM)), 256>>>(
            p_h, fc2_w + (size_t)l * HIDDIM * CDIM, fc2_b + l * CDIM, xcur,
            xcur, ROWS_X, CDIM, HIDDIM);
    }
}

// round 2
// speedup vs baseline: 1.0025x; 1.0025x over previous
#include <cuda_runtime.h>
#include <cuda_bf16.h>
#include <math.h>

// ---------------------------------------------------------------------------
// Problem constants
// ---------------------------------------------------------------------------
#define LAYERS 4
#define BATCH  64
#define NTOK   196
#define CDIM   768
#define CNEW   960
#define HIDDIM 3072
#define NHEAD  12
#define HD     64
#define HDK    80
#define MTOK   49      // reduced tokens 7x7
#define HW     14

#define ROWS_X (BATCH * NTOK)   // 12544
#define ROWS_R (BATCH * MTOK)   // 3136

// ---------------------------------------------------------------------------
// Scratch (device globals; allocation is forbidden)
// ---------------------------------------------------------------------------
__device__ float g_y[ROWS_X * CDIM];       // ln1(x) / reused as z = ln2(x)
__device__ float g_q[ROWS_X * CNEW];       // q projection
__device__ float g_rconv[ROWS_R * CDIM];   // depthwise-conv output, (b,m,c)
__device__ float g_r0[ROWS_R * CNEW];      // pw conv output (pre-LN)
__device__ float g_r[ROWS_R * CNEW];       // gelu(LN(r0))
__device__ float g_k[ROWS_R * CNEW];
__device__ float g_v[ROWS_R * CDIM];
__device__ float g_o[ROWS_X * CDIM];       // attention output
__device__ float g_h[ROWS_X * HIDDIM];     // mlp hidden

// ---------------------------------------------------------------------------
// Helpers
// ---------------------------------------------------------------------------
__device__ __forceinline__ float gelu_exact(float x) {
    return 0.5f * x * (1.0f + erff(x * 0.7071067811865476f));
}

// ---------------------------------------------------------------------------
// LayerNorm (optionally fused exact-GELU).  One block per row.
// ---------------------------------------------------------------------------
__global__ void ln_kernel(const float* __restrict__ in, float* __restrict__ out,
                          const float* __restrict__ gamma, const float* __restrict__ beta,
                          int W, float eps, int do_gelu) {
    const int row = blockIdx.x;
    const float* p = in + (size_t)row * W;
    float s = 0.f, ss = 0.f;
    for (int i = threadIdx.x; i < W; i += blockDim.x) {
        float v = p[i];
        s += v; ss += v * v;
    }
    __shared__ float red_s[32], red_ss[32];
    int lane = threadIdx.x & 31, wid = threadIdx.x >> 5;
    #pragma unroll
    for (int off = 16; off; off >>= 1) {
        s  += __shfl_xor_sync(0xffffffffu, s, off);
        ss += __shfl_xor_sync(0xffffffffu, ss, off);
    }
    if (lane == 0) { red_s[wid] = s; red_ss[wid] = ss; }
    __syncthreads();
    int nw = blockDim.x >> 5;
    if (wid == 0) {
        s  = (lane < nw) ? red_s[lane]  : 0.f;
        ss = (lane < nw) ? red_ss[lane] : 0.f;
        #pragma unroll
        for (int off = 16; off; off >>= 1) {
            s  += __shfl_xor_sync(0xffffffffu, s, off);
            ss += __shfl_xor_sync(0xffffffffu, ss, off);
        }
        if (lane == 0) { red_s[0] = s; red_ss[0] = ss; }
    }
    __syncthreads();
    float mean = red_s[0] / (float)W;
    float var  = red_ss[0] / (float)W - mean * mean;
    float inv  = rsqrtf(var + eps);
    float* q = out + (size_t)row * W;
    for (int i = threadIdx.x; i < W; i += blockDim.x) {
        float v = (p[i] - mean) * inv * gamma[i] + beta[i];
        if (do_gelu) v = gelu_exact(v);
        q[i] = v;
    }
}

// ---------------------------------------------------------------------------
// Strided depthwise 2x2/stride-2 conv.  y is (B, N=196, C) token-major;
// output rconv is (B, M=49, C).
// ---------------------------------------------------------------------------
__global__ void dwconv_kernel(const float* __restrict__ y,
                              const float* __restrict__ w4,   // (C,4)
                              const float* __restrict__ bias, // (C)
                              float* __restrict__ out) {
    const int m = blockIdx.x;   // 0..48
    const int b = blockIdx.y;   // 0..63
    const int h7 = m / 7, w7 = m % 7;
    const int p00 = (h7 * 2) * HW + w7 * 2;
    const float* yb = y + (size_t)b * NTOK * CDIM;
    float* ob = out + ((size_t)b * MTOK + m) * CDIM;
    for (int c = threadIdx.x; c < CDIM; c += blockDim.x) {
        float acc = yb[(size_t)(p00     ) * CDIM + c] * w4[c * 4 + 0]
                  + yb[(size_t)(p00 + 1 ) * CDIM + c] * w4[c * 4 + 1]
                  + yb[(size_t)(p00 + HW) * CDIM + c] * w4[c * 4 + 2]
                  + yb[(size_t)(p00 + HW + 1) * CDIM + c] * w4[c * 4 + 3]
                  + bias[c];
        ob[c] = acc;
    }
}

// ---------------------------------------------------------------------------
// Tiled fp32 GEMM:  C[M,N] = A[M,K] @ W[K,N]  (+bias / +gelu / +residual)
// BM=128 BN=64 BK=16, 256 threads, 8x4 accum per thread.
// EPI: 0 = store, 1 = +bias, 2 = +bias then gelu, 3 = +bias + residual
// Requires: N % 64 == 0, K % 16 == 0 (M arbitrary).
// ---------------------------------------------------------------------------
#define BM 128
#define BN 64
#define BK 16

template <int EPI>
__global__ __launch_bounds__(256) void sgemm_kernel(
        const float* __restrict__ A, const float* __restrict__ W,
        const float* __restrict__ bias, const float* __restrict__ resid,
        float* __restrict__ C, int M, int N, int K) {
    __shared__ float As[BK][BM];
    __shared__ float Bs[BK][BN];

    const int tid = threadIdx.x;
    const int tx = tid & 15;        // 0..15 -> N
    const int ty = tid >> 4;        // 0..15 -> M
    const int row0 = blockIdx.y * BM;
    const int col0 = blockIdx.x * BN;

    float acc[8][4];
    #pragma unroll
    for (int i = 0; i < 8; i++)
        #pragma unroll
        for (int j = 0; j < 4; j++) acc[i][j] = 0.f;

    for (int k0 = 0; k0 < K; k0 += BK) {
        // load A tile (128x16) as 512 float4, 2 per thread, store transposed
        #pragma unroll
        for (int i = 0; i < 2; i++) {
            int f  = tid + i * 256;
            int m  = f >> 2;
            int kq = (f & 3) * 4;
            int gm = row0 + m;
            float4 v;
            if (gm < M) v = *(const float4*)&A[(size_t)gm * K + k0 + kq];
            else        v = make_float4(0.f, 0.f, 0.f, 0.f);
            As[kq + 0][m] = v.x; As[kq + 1][m] = v.y;
            As[kq + 2][m] = v.z; As[kq + 3][m] = v.w;
        }
        // load B tile (16x64) as 256 float4, 1 per thread
        {
            int kb = tid >> 4;
            int nq = (tid & 15) * 4;
            *(float4*)&Bs[kb][nq] = *(const float4*)&W[(size_t)(k0 + kb) * N + col0 + nq];
        }
        __syncthreads();
        #pragma unroll
        for (int kk = 0; kk < BK; kk++) {
            float a[8], bb[4];
            #pragma unroll
            for (int i = 0; i < 8; i++) a[i] = As[kk][ty * 8 + i];
            #pragma unroll
            for (int j = 0; j < 4; j++) bb[j] = Bs[kk][tx * 4 + j];
            #pragma unroll
            for (int i = 0; i < 8; i++)
                #pragma unroll
                for (int j = 0; j < 4; j++)
                    acc[i][j] = fmaf(a[i], bb[j], acc[i][j]);
        }
        __syncthreads();
    }

    #pragma unroll
    for (int i = 0; i < 8; i++) {
        int gm = row0 + ty * 8 + i;
        if (gm >= M) continue;
        #pragma unroll
        for (int j = 0; j < 4; j++) {
            int gn = col0 + tx * 4 + j;
            float v = acc[i][j];
            if (EPI >= 1) v += bias[gn];
            if (EPI == 2) v = gelu_exact(v);
            if (EPI == 3) v += resid[(size_t)gm * N + gn];
            C[(size_t)gm * N + gn] = v;
        }
    }
}

// ---------------------------------------------------------------------------
// Attention: per (b,h) block.  q:(B,N,960) k:(B,49,960) v:(B,49,768)
// o:(B,N,768).  scale = 1/sqrt(80).
// ---------------------------------------------------------------------------
__global__ __launch_bounds__(128) void attn_kernel(
        const float* __restrict__ q, const float* __restrict__ k,
        const float* __restrict__ v, float* __restrict__ o) {
    const int b = blockIdx.x / NHEAD;
    const int h = blockIdx.x % NHEAD;
    __shared__ float ks[MTOK][HDK + 1];  // pad to 81 (odd stride -> conflict-free)
    __shared__ float vs[MTOK][HD + 1];   // pad to 65
    __shared__ float qs[4][HDK];
    __shared__ float ps[4][MTOK];

    const int tid = threadIdx.x, w = tid >> 5, lane = tid & 31;
    const float* kb = k + (size_t)b * MTOK * CNEW + h * HDK;
    const float* vb = v + (size_t)b * MTOK * CDIM + h * HD;
    for (int i = tid; i < MTOK * HDK; i += 128) {
        int m = i / HDK, d = i % HDK;
        ks[m][d] = kb[(size_t)m * CNEW + d];
    }
    for (int i = tid; i < MTOK * HD; i += 128) {
        int m = i / HD, d = i % HD;
        vs[m][d] = vb[(size_t)m * CDIM + d];
    }
    __syncthreads();

    const float scale = rsqrtf(80.0f);
    for (int n = w; n < NTOK; n += 4) {
        const float* qp = q + ((size_t)(b * NTOK + n)) * CNEW + h * HDK;
        for (int i = lane; i < HDK; i += 32) qs[w][i] = qp[i];
        __syncwarp();
        float s0 = 0.f, s1 = 0.f;
        #pragma unroll
        for (int d = 0; d < HDK; d++) {
            float qv = qs[w][d];
            s0 = fmaf(qv, ks[lane][d], s0);
            if (lane < MTOK - 32) s1 = fmaf(qv, ks[lane + 32][d], s1);
        }
        s0 *= scale; s1 *= scale;
        float mx = fmaxf(s0, (lane < MTOK - 32) ? s1 : -1e30f);
        #pragma unroll
        for (int off = 16; off; off >>= 1)
            mx = fmaxf(mx, __shfl_xor_sync(0xffffffffu, mx, off));
        float e0 = expf(s0 - mx);
        float e1 = (lane < MTOK - 32) ? expf(s1 - mx) : 0.f;
        float sm = e0 + e1;
        #pragma unroll
        for (int off = 16; off; off >>= 1)
            sm += __shfl_xor_sync(0xffffffffu, sm, off);
        float inv = 1.f / sm;
        ps[w][lane] = e0 * inv;
        if (lane < MTOK - 32) ps[w][lane + 32] = e1 * inv;
        __syncwarp();
        float a0 = 0.f, a1 = 0.f;
        #pragma unroll
        for (int m = 0; m < MTOK; m++) {
            float p = ps[w][m];
            a0 = fmaf(p, vs[m][lane], a0);
            a1 = fmaf(p, vs[m][lane + 32], a1);
        }
        float* op = o + ((size_t)(b * NTOK + n)) * CDIM + h * HD;
        op[lane] = a0;
        op[lane + 32] = a1;
        __syncwarp();
    }
}

// ---------------------------------------------------------------------------
// Host launch
// ---------------------------------------------------------------------------
static inline int cdiv(int a, int b) { return (a + b - 1) / b; }

extern "C" void kernel_launch(void* const* d_in, const int* in_sizes, int n_in,
                              void* d_out, int out_size) {
    const float* x_in   = (const float*)d_in[0];
    const float* q_w    = (const float*)d_in[1];
    const float* dw_w   = (const float*)d_in[2];
    const float* dw_b   = (const float*)d_in[3];
    const float* pw_w   = (const float*)d_in[4];
    const float* pw_b   = (const float*)d_in[5];
    const float* lnr_g  = (const float*)d_in[6];
    const float* lnr_b  = (const float*)d_in[7];
    const float* k_w    = (const float*)d_in[8];
    const float* v_w    = (const float*)d_in[9];
    const float* proj_w = (const float*)d_in[10];
    const float* proj_b = (const float*)d_in[11];
    const float* ln1_g  = (const float*)d_in[12];
    const float* ln1_b  = (const float*)d_in[13];
    const float* ln2_g  = (const float*)d_in[14];
    const float* ln2_b  = (const float*)d_in[15];
    const float* fc1_w  = (const float*)d_in[16];
    const float* fc1_b  = (const float*)d_in[17];
    const float* fc2_w  = (const float*)d_in[18];
    const float* fc2_b  = (const float*)d_in[19];

    float* xcur = (float*)d_out;

    float *p_y, *p_q, *p_rconv, *p_r0, *p_r, *p_k, *p_v, *p_o, *p_h;
    cudaGetSymbolAddress((void**)&p_y,     g_y);
    cudaGetSymbolAddress((void**)&p_q,     g_q);
    cudaGetSymbolAddress((void**)&p_rconv, g_rconv);
    cudaGetSymbolAddress((void**)&p_r0,    g_r0);
    cudaGetSymbolAddress((void**)&p_r,     g_r);
    cudaGetSymbolAddress((void**)&p_k,     g_k);
    cudaGetSymbolAddress((void**)&p_v,     g_v);
    cudaGetSymbolAddress((void**)&p_o,     g_o);
    cudaGetSymbolAddress((void**)&p_h,     g_h);

    // x working copy lives in d_out
    cudaMemcpyAsync(xcur, x_in, (size_t)ROWS_X * CDIM * sizeof(float),
                    cudaMemcpyDeviceToDevice, 0);

    for (int l = 0; l < LAYERS; l++) {
        // --- attention branch ---
        // y = LN(x) with eps 1e-6
        ln_kernel<<<ROWS_X, 256>>>(xcur, p_y, ln1_g + l * CDIM, ln1_b + l * CDIM,
                                   CDIM, 1e-6f, 0);
        // depthwise 2x2 stride-2 reduction -> (B,49,C)
        dwconv_kernel<<<dim3(MTOK, BATCH), 256>>>(p_y, dw_w + (size_t)l * CDIM * 4,
                                                  dw_b + l * CDIM, p_rconv);
        // pointwise conv: r0 = rconv @ pw_w + pw_b   (3136 x 960, K=768)
        sgemm_kernel<1><<<dim3(CNEW / BN, cdiv(ROWS_R, BM)), 256>>>(
            p_rconv, pw_w + (size_t)l * CDIM * CNEW, pw_b + l * CNEW, nullptr,
            p_r0, ROWS_R, CNEW, CDIM);
        // r = gelu(LN(r0)) eps 1e-5
        ln_kernel<<<ROWS_R, 256>>>(p_r0, p_r, lnr_g + l * CNEW, lnr_b + l * CNEW,
                                   CNEW, 1e-5f, 1);
        // q = y @ q_w            (12544 x 960, K=768)
        sgemm_kernel<0><<<dim3(CNEW / BN, cdiv(ROWS_X, BM)), 256>>>(
            p_y, q_w + (size_t)l * CDIM * CNEW, nullptr, nullptr,
            p_q, ROWS_X, CNEW, CDIM);
        // k = r @ k_w            (3136 x 960, K=960)
        sgemm_kernel<0><<<dim3(CNEW / BN, cdiv(ROWS_R, BM)), 256>>>(
            p_r, k_w + (size_t)l * CNEW * CNEW, nullptr, nullptr,
            p_k, ROWS_R, CNEW, CNEW);
        // v = r @ v_w            (3136 x 768, K=960)
        sgemm_kernel<0><<<dim3(CDIM / BN, cdiv(ROWS_R, BM)), 256>>>(
            p_r, v_w + (size_t)l * CNEW * CDIM, nullptr, nullptr,
            p_v, ROWS_R, CDIM, CNEW);
        // attention -> o
        attn_kernel<<<BATCH * NHEAD, 128>>>(p_q, p_k, p_v, p_o);
        // x += o @ proj_w + proj_b
        sgemm_kernel<3><<<dim3(CDIM / BN, cdiv(ROWS_X, BM)), 256>>>(
            p_o, proj_w + (size_t)l * CDIM * CDIM, proj_b + l * CDIM, xcur,
            xcur, ROWS_X, CDIM, CDIM);

        // --- MLP branch ---
        // z = LN(x) eps 1e-6 (reuse g_y)
        ln_kernel<<<ROWS_X, 256>>>(xcur, p_y, ln2_g + l * CDIM, ln2_b + l * CDIM,
                                   CDIM, 1e-6f, 0);
        // h = gelu(z @ fc1 + b)  (12544 x 3072, K=768)
        sgemm_kernel<2><<<dim3(HIDDIM / BN, cdiv(ROWS_X, BM)), 256>>>(
            p_y, fc1_w + (size_t)l * CDIM * HIDDIM, fc1_b + l * HIDDIM, nullptr,
            p_h, ROWS_X, HIDDIM, CDIM);
        // x += h @ fc2 + b       (12544 x 768, K=3072)
        sgemm_kernel<3><<<dim3(CDIM / BN, cdiv(ROWS_X, BM)), 256>>>(
            p_h, fc2_w + (size_t)l * HIDDIM * CDIM, fc2_b + l * CDIM, xcur,
            xcur, ROWS_X, CDIM, HIDDIM);
    }
}

// round 4
// speedup vs baseline: 2.1774x; 2.1720x over previous
#include <cuda_runtime.h>
#include <cuda_bf16.h>
#include <math.h>
#include <stdint.h>

#define LAYERS 4
#define BATCH  64
#define NTOK   196
#define CDIM   768
#define CNEW   960
#define HIDDIM 3072
#define NHEAD  12
#define HD     64
#define HDK    80
#define MTOK   49
#define HW     14
#define ROWS_X (BATCH * NTOK)   // 12544
#define ROWS_R (BATCH * MTOK)   // 3136

// ---------------- scratch ----------------
__device__ float g_y[ROWS_X * CDIM];
__device__ __align__(16) __nv_bfloat16 g_yh[ROWS_X * CDIM], g_yl[ROWS_X * CDIM];
__device__ __align__(16) __nv_bfloat16 g_rch[ROWS_R * CDIM], g_rcl[ROWS_R * CDIM];
__device__ float g_r0[ROWS_R * CNEW];
__device__ __align__(16) __nv_bfloat16 g_rh[ROWS_R * CNEW], g_rl[ROWS_R * CNEW];
__device__ float g_q[ROWS_X * CNEW];
__device__ float g_k[ROWS_R * CNEW];
__device__ float g_v[ROWS_R * CDIM];
__device__ __align__(16) __nv_bfloat16 g_oh[ROWS_X * CDIM], g_ol[ROWS_X * CDIM];
__device__ __align__(16) __nv_bfloat16 g_hh[ROWS_X * HIDDIM], g_hl[ROWS_X * HIDDIM];

// transposed + split weights, [N][K] K-major bf16
__device__ __align__(16) __nv_bfloat16 g_wq_h [LAYERS*CNEW*CDIM],   g_wq_l [LAYERS*CNEW*CDIM];
__device__ __align__(16) __nv_bfloat16 g_wpw_h[LAYERS*CNEW*CDIM],   g_wpw_l[LAYERS*CNEW*CDIM];
__device__ __align__(16) __nv_bfloat16 g_wk_h [LAYERS*CNEW*CNEW],   g_wk_l [LAYERS*CNEW*CNEW];
__device__ __align__(16) __nv_bfloat16 g_wv_h [LAYERS*CDIM*CNEW],   g_wv_l [LAYERS*CDIM*CNEW];
__device__ __align__(16) __nv_bfloat16 g_wp_h [LAYERS*CDIM*CDIM],   g_wp_l [LAYERS*CDIM*CDIM];
__device__ __align__(16) __nv_bfloat16 g_w1_h [LAYERS*HIDDIM*CDIM], g_w1_l [LAYERS*HIDDIM*CDIM];
__device__ __align__(16) __nv_bfloat16 g_w2_h [LAYERS*CDIM*HIDDIM], g_w2_l [LAYERS*CDIM*HIDDIM];

// ---------------- helpers ----------------
__device__ __forceinline__ uint32_t smem_u32(const void* p) {
    uint32_t a;
    asm("{ .reg .u64 t; cvta.to.shared.u64 t, %1; cvt.u32.u64 %0, t; }" : "=r"(a) : "l"(p));
    return a;
}
__device__ __forceinline__ void cp16(uint32_t dst, const void* src) {
    asm volatile("cp.async.cg.shared.global [%0], [%1], 16;" :: "r"(dst), "l"(src));
}
__device__ __forceinline__ void cp_commit() { asm volatile("cp.async.commit_group;" ::: "memory"); }
template <int N> __device__ __forceinline__ void cp_wait() {
    asm volatile("cp.async.wait_group %0;" :: "n"(N) : "memory");
}
__device__ __forceinline__ void ldsm_x4(uint32_t (&r)[4], uint32_t addr) {
    asm volatile("ldmatrix.sync.aligned.m8n8.x4.shared.b16 {%0,%1,%2,%3}, [%4];"
        : "=r"(r[0]), "=r"(r[1]), "=r"(r[2]), "=r"(r[3]) : "r"(addr));
}
__device__ __forceinline__ void mma16816(float (&d)[4], const uint32_t (&a)[4],
                                         uint32_t b0, uint32_t b1) {
    asm volatile("mma.sync.aligned.m16n8k16.row.col.f32.bf16.bf16.f32 "
        "{%0,%1,%2,%3}, {%4,%5,%6,%7}, {%8,%9}, {%0,%1,%2,%3};"
        : "+f"(d[0]), "+f"(d[1]), "+f"(d[2]), "+f"(d[3])
        : "r"(a[0]), "r"(a[1]), "r"(a[2]), "r"(a[3]), "r"(b0), "r"(b1));
}
__device__ __forceinline__ float gelu_exact(float x) {
    return 0.5f * x * (1.0f + erff(x * 0.7071067811865476f));
}
__device__ __forceinline__ void split_bf16(float v, __nv_bfloat16& h, __nv_bfloat16& l) {
    h = __float2bfloat16(v);
    l = __float2bfloat16(v - __bfloat162float(h));
}

// ---------------- weight transpose + split ----------------
__global__ __launch_bounds__(256) void wsplit_kernel(
        const float* __restrict__ W, __nv_bfloat16* __restrict__ Th,
        __nv_bfloat16* __restrict__ Tl, int K, int N) {
    __shared__ float t[32][33];
    const int n0 = blockIdx.x * 32, k0 = blockIdx.y * 32;
    const int tx = threadIdx.x & 31, ty = threadIdx.x >> 5;
    #pragma unroll
    for (int i = 0; i < 4; i++) {
        int k = ty + i * 8;
        t[k][tx] = W[(size_t)(k0 + k) * N + n0 + tx];
    }
    __syncthreads();
    #pragma unroll
    for (int i = 0; i < 4; i++) {
        int n = ty + i * 8;
        float v = t[tx][n];
        __nv_bfloat16 h, l; split_bf16(v, h, l);
        size_t o = (size_t)(n0 + n) * K + k0 + tx;
        Th[o] = h; Tl[o] = l;
    }
}

// ---------------- LayerNorm (+gelu) ----------------
__global__ void ln_kernel(const float* __restrict__ in, float* __restrict__ outf,
                          __nv_bfloat16* __restrict__ oh, __nv_bfloat16* __restrict__ ol,
                          const float* __restrict__ gamma, const float* __restrict__ beta,
                          int W, float eps, int do_gelu) {
    const int row = blockIdx.x;
    const float* p = in + (size_t)row * W;
    float s = 0.f, ss = 0.f;
    for (int i = threadIdx.x; i < W; i += blockDim.x) { float v = p[i]; s += v; ss += v * v; }
    __shared__ float red_s[32], red_ss[32];
    int lane = threadIdx.x & 31, wid = threadIdx.x >> 5;
    #pragma unroll
    for (int off = 16; off; off >>= 1) {
        s  += __shfl_xor_sync(0xffffffffu, s, off);
        ss += __shfl_xor_sync(0xffffffffu, ss, off);
    }
    if (lane == 0) { red_s[wid] = s; red_ss[wid] = ss; }
    __syncthreads();
    int nw = blockDim.x >> 5;
    if (wid == 0) {
        s  = (lane < nw) ? red_s[lane]  : 0.f;
        ss = (lane < nw) ? red_ss[lane] : 0.f;
        #pragma unroll
        for (int off = 16; off; off >>= 1) {
            s  += __shfl_xor_sync(0xffffffffu, s, off);
            ss += __shfl_xor_sync(0xffffffffu, ss, off);
        }
        if (lane == 0) { red_s[0] = s; red_ss[0] = ss; }
    }
    __syncthreads();
    float mean = red_s[0] / (float)W;
    float var  = red_ss[0] / (float)W - mean * mean;
    float inv  = rsqrtf(var + eps);
    for (int i = threadIdx.x; i < W; i += blockDim.x) {
        float v = (p[i] - mean) * inv * gamma[i] + beta[i];
        if (do_gelu) v = gelu_exact(v);
        size_t o = (size_t)row * W + i;
        if (outf) outf[o] = v;
        if (oh) { __nv_bfloat16 h, l; split_bf16(v, h, l); oh[o] = h; ol[o] = l; }
    }
}

// ---------------- depthwise 2x2/s2 conv -> bf16 hi/lo ----------------
__global__ void dwconv_kernel(const float* __restrict__ y,
                              const float* __restrict__ w4, const float* __restrict__ bias,
                              __nv_bfloat16* __restrict__ oh, __nv_bfloat16* __restrict__ ol) {
    const int m = blockIdx.x, b = blockIdx.y;
    const int h7 = m / 7, w7 = m % 7;
    const int p00 = (h7 * 2) * HW + w7 * 2;
    const float* yb = y + (size_t)b * NTOK * CDIM;
    const size_t ob = ((size_t)b * MTOK + m) * CDIM;
    for (int c = threadIdx.x; c < CDIM; c += blockDim.x) {
        float acc = yb[(size_t)(p00         ) * CDIM + c] * w4[c * 4 + 0]
                  + yb[(size_t)(p00 + 1     ) * CDIM + c] * w4[c * 4 + 1]
                  + yb[(size_t)(p00 + HW    ) * CDIM + c] * w4[c * 4 + 2]
                  + yb[(size_t)(p00 + HW + 1) * CDIM + c] * w4[c * 4 + 3]
                  + bias[c];
        __nv_bfloat16 h, l; split_bf16(acc, h, l);
        oh[ob + c] = h; ol[ob + c] = l;
    }
}

// ---------------------------------------------------------------------------
// Split-bf16 3-pass GEMM on HMMA (mma.sync m16n8k16):
//   C[M,N] = (Ah+Al)[M,K] @ (Bh+Bl)[N,K]^T  ==  Ah*Bh + Al*Bh + Ah*Bl
// CTA tile 128 x BN, BK=32, 3-stage cp.async pipeline.
// smem rows padded to 80B -> ldmatrix conflict-free (slot = (5r+c) mod 8).
// EPI: 0 fp32, 1 +bias fp32, 2 +bias+gelu -> bf16 hi/lo, 3 +bias+resid fp32
// ---------------------------------------------------------------------------
#define RSTRIDE 80
#define AH_OFF  0
#define AL_OFF  (128 * RSTRIDE)            // 10240
#define BH_OFF  (2 * 128 * RSTRIDE)        // 20480

template <int BN, int EPI>
__global__ __launch_bounds__(256) void tcmm_kernel(
        const __nv_bfloat16* __restrict__ Ah, const __nv_bfloat16* __restrict__ Al,
        const __nv_bfloat16* __restrict__ Bh, const __nv_bfloat16* __restrict__ Bl,
        const float* __restrict__ bias, const float* __restrict__ resid,
        float* __restrict__ Cf, __nv_bfloat16* __restrict__ Ch, __nv_bfloat16* __restrict__ Cl,
        int M, int N, int K) {
    constexpr int SS   = BH_OFF + 2 * BN * RSTRIDE;   // stage bytes
    constexpr int WN   = BN / 2;
    constexpr int WN8  = WN / 8;
    constexpr int WN16 = WN / 16;
    extern __shared__ char smem[];
    const int tid = threadIdx.x, lane = tid & 31, wid = tid >> 5;
    const int wm = wid >> 1, wn = wid & 1;               // 4 x 2 warp grid
    const int row0 = blockIdx.y * 128, col0 = blockIdx.x * BN;
    const uint32_t tiles = (smem_u32(smem) + 1023) & ~1023u;

    float acc[2][WN8][4];
    #pragma unroll
    for (int a = 0; a < 2; a++)
        #pragma unroll
        for (int b = 0; b < WN8; b++)
            #pragma unroll
            for (int c = 0; c < 4; c++) acc[a][b][c] = 0.f;

    const int NC = K >> 5;   // BK = 32

    auto load_chunk = [&](int stage, int k0) {
        uint32_t sd = tiles + stage * SS;
        #pragma unroll
        for (int i = 0; i < 4; i++) {                // A hi+lo: 1024 cp16
            int idx = tid + i * 256;
            int half = idx >> 9, rem = idx & 511;
            int row = rem >> 2, c = rem & 3;
            int grow = row0 + row; if (grow > M - 1) grow = M - 1;
            const __nv_bfloat16* src = (half ? Al : Ah) + (size_t)grow * K + k0 + c * 8;
            cp16(sd + half * AL_OFF + row * RSTRIDE + c * 16, src);
        }
        #pragma unroll
        for (int i = 0; i < BN / 32; i++) {          // B hi+lo: 8*BN cp16
            int idx = tid + i * 256;
            int half = idx / (BN * 4), rem = idx % (BN * 4);
            int row = rem >> 2, c = rem & 3;
            const __nv_bfloat16* src = (half ? Bl : Bh) + (size_t)(col0 + row) * K + k0 + c * 8;
            cp16(sd + BH_OFF + half * (BN * RSTRIDE) + row * RSTRIDE + c * 16, src);
        }
    };

    load_chunk(0, 0);  cp_commit();
    load_chunk(1, 32); cp_commit();

    for (int c = 0; c < NC; c++) {
        if (c + 2 < NC) cp_wait<1>(); else cp_wait<0>();
        __syncthreads();
        if (c + 2 < NC) { load_chunk((c + 2) % 3, (c + 2) * 32); cp_commit(); }

        const uint32_t sA = tiles + (c % 3) * SS;
        const uint32_t sB = sA + BH_OFF;
        #pragma unroll
        for (int ks = 0; ks < 2; ks++) {
            uint32_t ah[2][4], al[2][4];
            #pragma unroll
            for (int mt = 0; mt < 2; mt++) {
                uint32_t r = sA + (wm * 32 + mt * 16 + (lane & 15)) * RSTRIDE
                           + (2 * ks + (lane >> 4)) * 16;
                ldsm_x4(ah[mt], r);
                ldsm_x4(al[mt], r + AL_OFF);
            }
            uint32_t bh[WN16][4], bl[WN16][4];
            #pragma unroll
            for (int g = 0; g < WN16; g++) {
                int rrow = wn * WN + g * 16 + (lane & 7) + ((lane >> 4) << 3);
                uint32_t r = sB + rrow * RSTRIDE + (2 * ks + ((lane >> 3) & 1)) * 16;
                ldsm_x4(bh[g], r);
                ldsm_x4(bl[g], r + BN * RSTRIDE);
            }
            #pragma unroll
            for (int mt = 0; mt < 2; mt++)
                #pragma unroll
                for (int g = 0; g < WN16; g++) {
                    mma16816(acc[mt][2*g],   ah[mt], bh[g][0], bh[g][1]);
                    mma16816(acc[mt][2*g],   al[mt], bh[g][0], bh[g][1]);
                    mma16816(acc[mt][2*g],   ah[mt], bl[g][0], bl[g][1]);
                    mma16816(acc[mt][2*g+1], ah[mt], bh[g][2], bh[g][3]);
                    mma16816(acc[mt][2*g+1], al[mt], bh[g][2], bh[g][3]);
                    mma16816(acc[mt][2*g+1], ah[mt], bl[g][2], bl[g][3]);
                }
        }
    }

    // epilogue
    const int er = lane >> 2, ec = (lane & 3) * 2;
    #pragma unroll
    for (int mt = 0; mt < 2; mt++) {
        #pragma unroll
        for (int g = 0; g < WN8; g++) {
            const int gn = col0 + wn * WN + g * 8 + ec;
            #pragma unroll
            for (int hrow = 0; hrow < 2; hrow++) {
                const int gm = row0 + wm * 32 + mt * 16 + er + hrow * 8;
                if (gm >= M) continue;
                float v0 = acc[mt][g][2 * hrow];
                float v1 = acc[mt][g][2 * hrow + 1];
                const size_t base = (size_t)gm * N + gn;
                if constexpr (EPI >= 1) { v0 += bias[gn]; v1 += bias[gn + 1]; }
                if constexpr (EPI == 2) {
                    v0 = gelu_exact(v0); v1 = gelu_exact(v1);
                    __nv_bfloat16 h0, l0, h1, l1;
                    split_bf16(v0, h0, l0); split_bf16(v1, h1, l1);
                    __nv_bfloat162 hp; hp.x = h0; hp.y = h1;
                    __nv_bfloat162 lp; lp.x = l0; lp.y = l1;
                    *(__nv_bfloat162*)(Ch + base) = hp;
                    *(__nv_bfloat162*)(Cl + base) = lp;
                } else {
                    if constexpr (EPI == 3) {
                        float2 rs = *(const float2*)(resid + base);
                        v0 += rs.x; v1 += rs.y;
                    }
                    float2 o; o.x = v0; o.y = v1;
                    *(float2*)(Cf + base) = o;
                }
            }
        }
    }
}

// ---------------- attention (fp32), outputs bf16 hi/lo ----------------
__global__ __launch_bounds__(128) void attn_kernel(
        const float* __restrict__ q, const float* __restrict__ k,
        const float* __restrict__ v,
        __nv_bfloat16* __restrict__ oh, __nv_bfloat16* __restrict__ ol) {
    const int b = blockIdx.x / NHEAD;
    const int hh = blockIdx.x % NHEAD;
    __shared__ float ks[MTOK][HDK + 1];
    __shared__ float vs[MTOK][HD + 1];
    __shared__ float qs[4][HDK];
    __shared__ float ps[4][MTOK];
    const int tid = threadIdx.x, w = tid >> 5, lane = tid & 31;
    const float* kb = k + (size_t)b * MTOK * CNEW + hh * HDK;
    const float* vb = v + (size_t)b * MTOK * CDIM + hh * HD;
    for (int i = tid; i < MTOK * HDK; i += 128) {
        int m = i / HDK, d = i % HDK;
        ks[m][d] = kb[(size_t)m * CNEW + d];
    }
    for (int i = tid; i < MTOK * HD; i += 128) {
        int m = i / HD, d = i % HD;
        vs[m][d] = vb[(size_t)m * CDIM + d];
    }
    __syncthreads();
    const float scale = rsqrtf(80.0f);
    for (int n = w; n < NTOK; n += 4) {
        const float* qp = q + ((size_t)(b * NTOK + n)) * CNEW + hh * HDK;
        for (int i = lane; i < HDK; i += 32) qs[w][i] = qp[i];
        __syncwarp();
        float s0 = 0.f, s1 = 0.f;
        #pragma unroll
        for (int d = 0; d < HDK; d++) {
            float qv = qs[w][d];
            s0 = fmaf(qv, ks[lane][d], s0);
            if (lane < MTOK - 32) s1 = fmaf(qv, ks[lane + 32][d], s1);
        }
        s0 *= scale; s1 *= scale;
        float mx = fmaxf(s0, (lane < MTOK - 32) ? s1 : -1e30f);
        #pragma unroll
        for (int off = 16; off; off >>= 1) mx = fmaxf(mx, __shfl_xor_sync(0xffffffffu, mx, off));
        float e0 = expf(s0 - mx);
        float e1 = (lane < MTOK - 32) ? expf(s1 - mx) : 0.f;
        float sm = e0 + e1;
        #pragma unroll
        for (int off = 16; off; off >>= 1) sm += __shfl_xor_sync(0xffffffffu, sm, off);
        float inv = 1.f / sm;
        ps[w][lane] = e0 * inv;
        if (lane < MTOK - 32) ps[w][lane + 32] = e1 * inv;
        __syncwarp();
        float a0 = 0.f, a1 = 0.f;
        #pragma unroll
        for (int m = 0; m < MTOK; m++) {
            float p = ps[w][m];
            a0 = fmaf(p, vs[m][lane], a0);
            a1 = fmaf(p, vs[m][lane + 32], a1);
        }
        size_t o0 = ((size_t)(b * NTOK + n)) * CDIM + hh * HD + lane;
        __nv_bfloat16 bh, bl;
        split_bf16(a0, bh, bl); oh[o0] = bh;      ol[o0] = bl;
        split_bf16(a1, bh, bl); oh[o0 + 32] = bh; ol[o0 + 32] = bl;
        __syncwarp();
    }
}

// ---------------- host ----------------
static inline int cdiv(int a, int b) { return (a + b - 1) / b; }
#define SMEM_BN64  (1024 + 3 * (BH_OFF + 2 * 64 * RSTRIDE))    // 1024 + 3*30720
#define SMEM_BN128 (1024 + 3 * (BH_OFF + 2 * 128 * RSTRIDE))   // 1024 + 3*40960

extern "C" void kernel_launch(void* const* d_in, const int* in_sizes, int n_in,
                              void* d_out, int out_size) {
    const float* x_in   = (const float*)d_in[0];
    const float* q_w    = (const float*)d_in[1];
    const float* dw_w   = (const float*)d_in[2];
    const float* dw_b   = (const float*)d_in[3];
    const float* pw_w   = (const float*)d_in[4];
    const float* pw_b   = (const float*)d_in[5];
    const float* lnr_g  = (const float*)d_in[6];
    const float* lnr_b  = (const float*)d_in[7];
    const float* k_w    = (const float*)d_in[8];
    const float* v_w    = (const float*)d_in[9];
    const float* proj_w = (const float*)d_in[10];
    const float* proj_b = (const float*)d_in[11];
    const float* ln1_g  = (const float*)d_in[12];
    const float* ln1_b  = (const float*)d_in[13];
    const float* ln2_g  = (const float*)d_in[14];
    const float* ln2_b  = (const float*)d_in[15];
    const float* fc1_w  = (const float*)d_in[16];
    const float* fc1_b  = (const float*)d_in[17];
    const float* fc2_w  = (const float*)d_in[18];
    const float* fc2_b  = (const float*)d_in[19];

    float* xcur = (float*)d_out;

    float *p_y, *p_r0, *p_q, *p_k, *p_v;
    __nv_bfloat16 *p_yh, *p_yl, *p_rch, *p_rcl, *p_rh, *p_rl, *p_oh, *p_ol, *p_hh, *p_hl;
    __nv_bfloat16 *wq_h, *wq_l, *wpw_h, *wpw_l, *wk_h, *wk_l, *wv_h, *wv_l;
    __nv_bfloat16 *wp_h, *wp_l, *w1_h, *w1_l, *w2_h, *w2_l;
    cudaGetSymbolAddress((void**)&p_y, g_y);     cudaGetSymbolAddress((void**)&p_r0, g_r0);
    cudaGetSymbolAddress((void**)&p_q, g_q);     cudaGetSymbolAddress((void**)&p_k, g_k);
    cudaGetSymbolAddress((void**)&p_v, g_v);
    cudaGetSymbolAddress((void**)&p_yh, g_yh);   cudaGetSymbolAddress((void**)&p_yl, g_yl);
    cudaGetSymbolAddress((void**)&p_rch, g_rch); cudaGetSymbolAddress((void**)&p_rcl, g_rcl);
    cudaGetSymbolAddress((void**)&p_rh, g_rh);   cudaGetSymbolAddress((void**)&p_rl, g_rl);
    cudaGetSymbolAddress((void**)&p_oh, g_oh);   cudaGetSymbolAddress((void**)&p_ol, g_ol);
    cudaGetSymbolAddress((void**)&p_hh, g_hh);   cudaGetSymbolAddress((void**)&p_hl, g_hl);
    cudaGetSymbolAddress((void**)&wq_h, g_wq_h);   cudaGetSymbolAddress((void**)&wq_l, g_wq_l);
    cudaGetSymbolAddress((void**)&wpw_h, g_wpw_h); cudaGetSymbolAddress((void**)&wpw_l, g_wpw_l);
    cudaGetSymbolAddress((void**)&wk_h, g_wk_h);   cudaGetSymbolAddress((void**)&wk_l, g_wk_l);
    cudaGetSymbolAddress((void**)&wv_h, g_wv_h);   cudaGetSymbolAddress((void**)&wv_l, g_wv_l);
    cudaGetSymbolAddress((void**)&wp_h, g_wp_h);   cudaGetSymbolAddress((void**)&wp_l, g_wp_l);
    cudaGetSymbolAddress((void**)&w1_h, g_w1_h);   cudaGetSymbolAddress((void**)&w1_l, g_w1_l);
    cudaGetSymbolAddress((void**)&w2_h, g_w2_h);   cudaGetSymbolAddress((void**)&w2_l, g_w2_l);

    cudaFuncSetAttribute(tcmm_kernel<64,0>,  cudaFuncAttributeMaxDynamicSharedMemorySize, SMEM_BN64);
    cudaFuncSetAttribute(tcmm_kernel<64,1>,  cudaFuncAttributeMaxDynamicSharedMemorySize, SMEM_BN64);
    cudaFuncSetAttribute(tcmm_kernel<128,0>, cudaFuncAttributeMaxDynamicSharedMemorySize, SMEM_BN128);
    cudaFuncSetAttribute(tcmm_kernel<128,2>, cudaFuncAttributeMaxDynamicSharedMemorySize, SMEM_BN128);
    cudaFuncSetAttribute(tcmm_kernel<128,3>, cudaFuncAttributeMaxDynamicSharedMemorySize, SMEM_BN128);

    cudaMemcpyAsync(xcur, x_in, (size_t)ROWS_X * CDIM * sizeof(float),
                    cudaMemcpyDeviceToDevice, 0);

    for (int l = 0; l < LAYERS; l++) {
        wsplit_kernel<<<dim3(CNEW/32, CDIM/32), 256>>>(q_w  + (size_t)l*CDIM*CNEW,
            wq_h  + (size_t)l*CNEW*CDIM, wq_l  + (size_t)l*CNEW*CDIM, CDIM, CNEW);
        wsplit_kernel<<<dim3(CNEW/32, CDIM/32), 256>>>(pw_w + (size_t)l*CDIM*CNEW,
            wpw_h + (size_t)l*CNEW*CDIM, wpw_l + (size_t)l*CNEW*CDIM, CDIM, CNEW);
        wsplit_kernel<<<dim3(CNEW/32, CNEW/32), 256>>>(k_w  + (size_t)l*CNEW*CNEW,
            wk_h  + (size_t)l*CNEW*CNEW, wk_l  + (size_t)l*CNEW*CNEW, CNEW, CNEW);
        wsplit_kernel<<<dim3(CDIM/32, CNEW/32), 256>>>(v_w  + (size_t)l*CNEW*CDIM,
            wv_h  + (size_t)l*CDIM*CNEW, wv_l  + (size_t)l*CDIM*CNEW, CNEW, CDIM);
        wsplit_kernel<<<dim3(CDIM/32, CDIM/32), 256>>>(proj_w + (size_t)l*CDIM*CDIM,
            wp_h  + (size_t)l*CDIM*CDIM, wp_l  + (size_t)l*CDIM*CDIM, CDIM, CDIM);
        wsplit_kernel<<<dim3(HIDDIM/32, CDIM/32), 256>>>(fc1_w + (size_t)l*CDIM*HIDDIM,
            w1_h  + (size_t)l*HIDDIM*CDIM, w1_l + (size_t)l*HIDDIM*CDIM, CDIM, HIDDIM);
        wsplit_kernel<<<dim3(CDIM/32, HIDDIM/32), 256>>>(fc2_w + (size_t)l*HIDDIM*CDIM,
            w2_h  + (size_t)l*CDIM*HIDDIM, w2_l + (size_t)l*CDIM*HIDDIM, HIDDIM, CDIM);
    }

    for (int l = 0; l < LAYERS; l++) {
        ln_kernel<<<ROWS_X, 256>>>(xcur, p_y, p_yh, p_yl,
                                   ln1_g + l*CDIM, ln1_b + l*CDIM, CDIM, 1e-6f, 0);
        dwconv_kernel<<<dim3(MTOK, BATCH), 256>>>(p_y, dw_w + (size_t)l*CDIM*4,
                                                  dw_b + l*CDIM, p_rch, p_rcl);
        // r0 = rconv @ pw + b   (3136 x 960, K=768)
        tcmm_kernel<64,1><<<dim3(CNEW/64, cdiv(ROWS_R,128)), 256, SMEM_BN64>>>(
            p_rch, p_rcl, wpw_h + (size_t)l*CNEW*CDIM, wpw_l + (size_t)l*CNEW*CDIM,
            pw_b + l*CNEW, nullptr, p_r0, nullptr, nullptr, ROWS_R, CNEW, CDIM);
        ln_kernel<<<ROWS_R, 256>>>(p_r0, nullptr, p_rh, p_rl,
                                   lnr_g + l*CNEW, lnr_b + l*CNEW, CNEW, 1e-5f, 1);
        // q = y @ q_w           (12544 x 960, K=768)
        tcmm_kernel<64,0><<<dim3(CNEW/64, cdiv(ROWS_X,128)), 256, SMEM_BN64>>>(
            p_yh, p_yl, wq_h + (size_t)l*CNEW*CDIM, wq_l + (size_t)l*CNEW*CDIM,
            nullptr, nullptr, p_q, nullptr, nullptr, ROWS_X, CNEW, CDIM);
        // k = r @ k_w           (3136 x 960, K=960)
        tcmm_kernel<64,0><<<dim3(CNEW/64, cdiv(ROWS_R,128)), 256, SMEM_BN64>>>(
            p_rh, p_rl, wk_h + (size_t)l*CNEW*CNEW, wk_l + (size_t)l*CNEW*CNEW,
            nullptr, nullptr, p_k, nullptr, nullptr, ROWS_R, CNEW, CNEW);
        // v = r @ v_w           (3136 x 768, K=960)
        tcmm_kernel<128,0><<<dim3(CDIM/128, cdiv(ROWS_R,128)), 256, SMEM_BN128>>>(
            p_rh, p_rl, wv_h + (size_t)l*CDIM*CNEW, wv_l + (size_t)l*CDIM*CNEW,
            nullptr, nullptr, p_v, nullptr, nullptr, ROWS_R, CDIM, CNEW);
        attn_kernel<<<BATCH*NHEAD, 128>>>(p_q, p_k, p_v, p_oh, p_ol);
        // x += o @ proj + b     (12544 x 768, K=768)
        tcmm_kernel<128,3><<<dim3(CDIM/128, cdiv(ROWS_X,128)), 256, SMEM_BN128>>>(
            p_oh, p_ol, wp_h + (size_t)l*CDIM*CDIM, wp_l + (size_t)l*CDIM*CDIM,
            proj_b + l*CDIM, xcur, xcur, nullptr, nullptr, ROWS_X, CDIM, CDIM);
        ln_kernel<<<ROWS_X, 256>>>(xcur, nullptr, p_yh, p_yl,
                                   ln2_g + l*CDIM, ln2_b + l*CDIM, CDIM, 1e-6f, 0);
        // h = gelu(z @ fc1 + b) (12544 x 3072, K=768)
        tcmm_kernel<128,2><<<dim3(HIDDIM/128, cdiv(ROWS_X,128)), 256, SMEM_BN128>>>(
            p_yh, p_yl, w1_h + (size_t)l*HIDDIM*CDIM, w1_l + (size_t)l*HIDDIM*CDIM,
            fc1_b + l*HIDDIM, nullptr, nullptr, p_hh, p_hl, ROWS_X, HIDDIM, CDIM);
        // x += h @ fc2 + b      (12544 x 768, K=3072)
        tcmm_kernel<128,3><<<dim3(CDIM/128, cdiv(ROWS_X,128)), 256, SMEM_BN128>>>(
            p_hh, p_hl, w2_h + (size_t)l*CDIM*HIDDIM, w2_l + (size_t)l*CDIM*HIDDIM,
            fc2_b + l*CDIM, xcur, xcur, nullptr, nullptr, ROWS_X, CDIM, HIDDIM);
    }
}

// round 5
// speedup vs baseline: 3.1061x; 1.4265x over previous
#include <cuda_runtime.h>
#include <cuda_fp16.h>
#include <math.h>
#include <stdint.h>

#define LAYERS 4
#define BATCH  64
#define NTOK   196
#define CDIM   768
#define CNEW   960
#define HIDDIM 3072
#define NHEAD  12
#define HD     64
#define HDK    80
#define MTOK   49
#define HW     14
#define ROWS_X (BATCH * NTOK)   // 12544
#define ROWS_R (BATCH * MTOK)   // 3136

// ---------------- scratch ----------------
__device__ float g_y[ROWS_X * CDIM];
__device__ __align__(16) __half g_yh[ROWS_X * CDIM], g_yl[ROWS_X * CDIM];
__device__ __align__(16) __half g_rch[ROWS_R * CDIM], g_rcl[ROWS_R * CDIM];
__device__ float g_r0[ROWS_R * CNEW];
__device__ __align__(16) __half g_rh[ROWS_R * CNEW], g_rl[ROWS_R * CNEW];
__device__ float g_q[ROWS_X * CNEW];
__device__ float g_k[ROWS_R * CNEW];
__device__ float g_v[ROWS_R * CDIM];
__device__ __align__(16) __half g_oh[ROWS_X * CDIM], g_ol[ROWS_X * CDIM];
__device__ __align__(16) __half g_hh[ROWS_X * HIDDIM], g_hl[ROWS_X * HIDDIM];

// transposed weights, [N][K] K-major, single fp16
__device__ __align__(16) __half g_wq [LAYERS*CNEW*CDIM];
__device__ __align__(16) __half g_wpw[LAYERS*CNEW*CDIM];
__device__ __align__(16) __half g_wk [LAYERS*CNEW*CNEW];
__device__ __align__(16) __half g_wv [LAYERS*CDIM*CNEW];
__device__ __align__(16) __half g_wp [LAYERS*CDIM*CDIM];
__device__ __align__(16) __half g_w1 [LAYERS*HIDDIM*CDIM];
__device__ __align__(16) __half g_w2 [LAYERS*CDIM*HIDDIM];

// ---------------- helpers ----------------
__device__ __forceinline__ uint32_t smem_u32(const void* p) {
    uint32_t a;
    asm("{ .reg .u64 t; cvta.to.shared.u64 t, %1; cvt.u32.u64 %0, t; }" : "=r"(a) : "l"(p));
    return a;
}
__device__ __forceinline__ void cp16(uint32_t dst, const void* src) {
    asm volatile("cp.async.cg.shared.global [%0], [%1], 16;" :: "r"(dst), "l"(src));
}
__device__ __forceinline__ void cp_commit() { asm volatile("cp.async.commit_group;" ::: "memory"); }
template <int N> __device__ __forceinline__ void cp_wait() {
    asm volatile("cp.async.wait_group %0;" :: "n"(N) : "memory");
}
__device__ __forceinline__ void ldsm_x4(uint32_t (&r)[4], uint32_t addr) {
    asm volatile("ldmatrix.sync.aligned.m8n8.x4.shared.b16 {%0,%1,%2,%3}, [%4];"
        : "=r"(r[0]), "=r"(r[1]), "=r"(r[2]), "=r"(r[3]) : "r"(addr));
}
__device__ __forceinline__ void mma16816(float (&d)[4], const uint32_t (&a)[4],
                                         uint32_t b0, uint32_t b1) {
    asm volatile("mma.sync.aligned.m16n8k16.row.col.f32.f16.f16.f32 "
        "{%0,%1,%2,%3}, {%4,%5,%6,%7}, {%8,%9}, {%0,%1,%2,%3};"
        : "+f"(d[0]), "+f"(d[1]), "+f"(d[2]), "+f"(d[3])
        : "r"(a[0]), "r"(a[1]), "r"(a[2]), "r"(a[3]), "r"(b0), "r"(b1));
}
__device__ __forceinline__ float gelu_exact(float x) {
    return 0.5f * x * (1.0f + erff(x * 0.7071067811865476f));
}
__device__ __forceinline__ void split_f16(float v, __half& h, __half& l) {
    h = __float2half_rn(v);
    l = __float2half_rn(v - __half2float(h));
}

// ---------------- weight transpose -> fp16 ----------------
__global__ __launch_bounds__(256) void wsplit_kernel(
        const float* __restrict__ W, __half* __restrict__ T, int K, int N) {
    __shared__ float t[32][33];
    const int n0 = blockIdx.x * 32, k0 = blockIdx.y * 32;
    const int tx = threadIdx.x & 31, ty = threadIdx.x >> 5;
    #pragma unroll
    for (int i = 0; i < 4; i++) {
        int k = ty + i * 8;
        t[k][tx] = W[(size_t)(k0 + k) * N + n0 + tx];
    }
    __syncthreads();
    #pragma unroll
    for (int i = 0; i < 4; i++) {
        int n = ty + i * 8;
        T[(size_t)(n0 + n) * K + k0 + tx] = __float2half_rn(t[tx][n]);
    }
}

// ---------------- LayerNorm (+gelu) ----------------
__global__ void ln_kernel(const float* __restrict__ in, float* __restrict__ outf,
                          __half* __restrict__ oh, __half* __restrict__ ol,
                          const float* __restrict__ gamma, const float* __restrict__ beta,
                          int W, float eps, int do_gelu) {
    const int row = blockIdx.x;
    const float* p = in + (size_t)row * W;
    float s = 0.f, ss = 0.f;
    for (int i = threadIdx.x; i < W; i += blockDim.x) { float v = p[i]; s += v; ss += v * v; }
    __shared__ float red_s[32], red_ss[32];
    int lane = threadIdx.x & 31, wid = threadIdx.x >> 5;
    #pragma unroll
    for (int off = 16; off; off >>= 1) {
        s  += __shfl_xor_sync(0xffffffffu, s, off);
        ss += __shfl_xor_sync(0xffffffffu, ss, off);
    }
    if (lane == 0) { red_s[wid] = s; red_ss[wid] = ss; }
    __syncthreads();
    int nw = blockDim.x >> 5;
    if (wid == 0) {
        s  = (lane < nw) ? red_s[lane]  : 0.f;
        ss = (lane < nw) ? red_ss[lane] : 0.f;
        #pragma unroll
        for (int off = 16; off; off >>= 1) {
            s  += __shfl_xor_sync(0xffffffffu, s, off);
            ss += __shfl_xor_sync(0xffffffffu, ss, off);
        }
        if (lane == 0) { red_s[0] = s; red_ss[0] = ss; }
    }
    __syncthreads();
    float mean = red_s[0] / (float)W;
    float var  = red_ss[0] / (float)W - mean * mean;
    float inv  = rsqrtf(var + eps);
    for (int i = threadIdx.x; i < W; i += blockDim.x) {
        float v = (p[i] - mean) * inv * gamma[i] + beta[i];
        if (do_gelu) v = gelu_exact(v);
        size_t o = (size_t)row * W + i;
        if (outf) outf[o] = v;
        if (oh) { __half h, l; split_f16(v, h, l); oh[o] = h; ol[o] = l; }
    }
}

// ---------------- depthwise 2x2/s2 conv -> fp16 hi/lo ----------------
__global__ void dwconv_kernel(const float* __restrict__ y,
                              const float* __restrict__ w4, const float* __restrict__ bias,
                              __half* __restrict__ oh, __half* __restrict__ ol) {
    const int m = blockIdx.x, b = blockIdx.y;
    const int h7 = m / 7, w7 = m % 7;
    const int p00 = (h7 * 2) * HW + w7 * 2;
    const float* yb = y + (size_t)b * NTOK * CDIM;
    const size_t ob = ((size_t)b * MTOK + m) * CDIM;
    for (int c = threadIdx.x; c < CDIM; c += blockDim.x) {
        float acc = yb[(size_t)(p00         ) * CDIM + c] * w4[c * 4 + 0]
                  + yb[(size_t)(p00 + 1     ) * CDIM + c] * w4[c * 4 + 1]
                  + yb[(size_t)(p00 + HW    ) * CDIM + c] * w4[c * 4 + 2]
                  + yb[(size_t)(p00 + HW + 1) * CDIM + c] * w4[c * 4 + 3]
                  + bias[c];
        __half h, l; split_f16(acc, h, l);
        oh[ob + c] = h; ol[ob + c] = l;
    }
}

// ---------------------------------------------------------------------------
// Split-fp16 2-pass GEMM on HMMA: C = (Ah+Al)[M,K] @ B[N,K]^T
// CTA tile 128 x BN, BK=32, 3-stage cp.async pipeline.
// smem rows padded to 80B -> ldmatrix conflict-free.
// EPI: 0 fp32, 1 +bias fp32, 2 +bias+gelu -> fp16 hi/lo, 3 +bias+resid fp32
// ---------------------------------------------------------------------------
#define RSTRIDE 80
#define AL_OFF  (128 * RSTRIDE)            // 10240
#define BH_OFF  (2 * 128 * RSTRIDE)        // 20480

template <int BN, int EPI>
__global__ __launch_bounds__(256) void tcmm_kernel(
        const __half* __restrict__ Ah, const __half* __restrict__ Al,
        const __half* __restrict__ B,
        const float* __restrict__ bias, const float* __restrict__ resid,
        float* __restrict__ Cf, __half* __restrict__ Ch, __half* __restrict__ Cl,
        int M, int N, int K) {
    constexpr int SS   = BH_OFF + BN * RSTRIDE;   // stage bytes
    constexpr int WN   = BN / 2;
    constexpr int WN8  = WN / 8;
    constexpr int WN16 = WN / 16;
    extern __shared__ char smem[];
    const int tid = threadIdx.x, lane = tid & 31, wid = tid >> 5;
    const int wm = wid >> 1, wn = wid & 1;               // 4 x 2 warp grid
    const int row0 = blockIdx.y * 128, col0 = blockIdx.x * BN;
    const uint32_t tiles = (smem_u32(smem) + 1023) & ~1023u;

    float acc[2][WN8][4];
    #pragma unroll
    for (int a = 0; a < 2; a++)
        #pragma unroll
        for (int b = 0; b < WN8; b++)
            #pragma unroll
            for (int c = 0; c < 4; c++) acc[a][b][c] = 0.f;

    const int NC = K >> 5;   // BK = 32

    auto load_chunk = [&](int stage, int k0) {
        uint32_t sd = tiles + stage * SS;
        #pragma unroll
        for (int i = 0; i < 4; i++) {                // A hi+lo: 1024 cp16
            int idx = tid + i * 256;
            int half = idx >> 9, rem = idx & 511;
            int row = rem >> 2, c = rem & 3;
            int grow = row0 + row; if (grow > M - 1) grow = M - 1;
            const __half* src = (half ? Al : Ah) + (size_t)grow * K + k0 + c * 8;
            cp16(sd + half * AL_OFF + row * RSTRIDE + c * 16, src);
        }
        #pragma unroll
        for (int i = 0; i < BN / 64; i++) {          // B: 4*BN cp16
            int idx = tid + i * 256;
            int row = idx >> 2, c = idx & 3;
            const __half* src = B + (size_t)(col0 + row) * K + k0 + c * 8;
            cp16(sd + BH_OFF + row * RSTRIDE + c * 16, src);
        }
    };

    load_chunk(0, 0);  cp_commit();
    load_chunk(1, 32); cp_commit();

    for (int c = 0; c < NC; c++) {
        if (c + 2 < NC) cp_wait<1>(); else cp_wait<0>();
        __syncthreads();
        if (c + 2 < NC) { load_chunk((c + 2) % 3, (c + 2) * 32); cp_commit(); }

        const uint32_t sA = tiles + (c % 3) * SS;
        const uint32_t sB = sA + BH_OFF;
        #pragma unroll
        for (int ks = 0; ks < 2; ks++) {
            uint32_t ah[2][4], al[2][4];
            #pragma unroll
            for (int mt = 0; mt < 2; mt++) {
                uint32_t r = sA + (wm * 32 + mt * 16 + (lane & 15)) * RSTRIDE
                           + (2 * ks + (lane >> 4)) * 16;
                ldsm_x4(ah[mt], r);
                ldsm_x4(al[mt], r + AL_OFF);
            }
            uint32_t bh[WN16][4];
            #pragma unroll
            for (int g = 0; g < WN16; g++) {
                int rrow = wn * WN + g * 16 + (lane & 7) + ((lane >> 4) << 3);
                uint32_t r = sB + rrow * RSTRIDE + (2 * ks + ((lane >> 3) & 1)) * 16;
                ldsm_x4(bh[g], r);
            }
            #pragma unroll
            for (int mt = 0; mt < 2; mt++)
                #pragma unroll
                for (int g = 0; g < WN16; g++) {
                    mma16816(acc[mt][2*g],   ah[mt], bh[g][0], bh[g][1]);
                    mma16816(acc[mt][2*g],   al[mt], bh[g][0], bh[g][1]);
                    mma16816(acc[mt][2*g+1], ah[mt], bh[g][2], bh[g][3]);
                    mma16816(acc[mt][2*g+1], al[mt], bh[g][2], bh[g][3]);
                }
        }
    }

    // epilogue
    const int er = lane >> 2, ec = (lane & 3) * 2;
    #pragma unroll
    for (int mt = 0; mt < 2; mt++) {
        #pragma unroll
        for (int g = 0; g < WN8; g++) {
            const int gn = col0 + wn * WN + g * 8 + ec;
            #pragma unroll
            for (int hrow = 0; hrow < 2; hrow++) {
                const int gm = row0 + wm * 32 + mt * 16 + er + hrow * 8;
                if (gm >= M) continue;
                float v0 = acc[mt][g][2 * hrow];
                float v1 = acc[mt][g][2 * hrow + 1];
                const size_t base = (size_t)gm * N + gn;
                if constexpr (EPI >= 1) { v0 += bias[gn]; v1 += bias[gn + 1]; }
                if constexpr (EPI == 2) {
                    v0 = gelu_exact(v0); v1 = gelu_exact(v1);
                    __half h0, l0, h1, l1;
                    split_f16(v0, h0, l0); split_f16(v1, h1, l1);
                    __half2 hp; hp.x = h0; hp.y = h1;
                    __half2 lp; lp.x = l0; lp.y = l1;
                    *(__half2*)(Ch + base) = hp;
                    *(__half2*)(Cl + base) = lp;
                } else {
                    if constexpr (EPI == 3) {
                        float2 rs = *(const float2*)(resid + base);
                        v0 += rs.x; v1 += rs.y;
                    }
                    float2 o; o.x = v0; o.y = v1;
                    *(float2*)(Cf + base) = o;
                }
            }
        }
    }
}

// ---------------- attention (fp32), outputs fp16 hi/lo ----------------
__global__ __launch_bounds__(128) void attn_kernel(
        const float* __restrict__ q, const float* __restrict__ k,
        const float* __restrict__ v,
        __half* __restrict__ oh, __half* __restrict__ ol) {
    const int b = blockIdx.x / NHEAD;
    const int hh = blockIdx.x % NHEAD;
    __shared__ float ks[MTOK][HDK + 1];
    __shared__ float vs[MTOK][HD + 1];
    __shared__ float qs[4][HDK];
    __shared__ float ps[4][MTOK];
    const int tid = threadIdx.x, w = tid >> 5, lane = tid & 31;
    const float* kb = k + (size_t)b * MTOK * CNEW + hh * HDK;
    const float* vb = v + (size_t)b * MTOK * CDIM + hh * HD;
    for (int i = tid; i < MTOK * HDK; i += 128) {
        int m = i / HDK, d = i % HDK;
        ks[m][d] = kb[(size_t)m * CNEW + d];
    }
    for (int i = tid; i < MTOK * HD; i += 128) {
        int m = i / HD, d = i % HD;
        vs[m][d] = vb[(size_t)m * CDIM + d];
    }
    __syncthreads();
    const float scale = rsqrtf(80.0f);
    for (int n = w; n < NTOK; n += 4) {
        const float* qp = q + ((size_t)(b * NTOK + n)) * CNEW + hh * HDK;
        for (int i = lane; i < HDK; i += 32) qs[w][i] = qp[i];
        __syncwarp();
        float s0 = 0.f, s1 = 0.f;
        #pragma unroll
        for (int d = 0; d < HDK; d++) {
            float qv = qs[w][d];
            s0 = fmaf(qv, ks[lane][d], s0);
            if (lane < MTOK - 32) s1 = fmaf(qv, ks[lane + 32][d], s1);
        }
        s0 *= scale; s1 *= scale;
        float mx = fmaxf(s0, (lane < MTOK - 32) ? s1 : -1e30f);
        #pragma unroll
        for (int off = 16; off; off >>= 1) mx = fmaxf(mx, __shfl_xor_sync(0xffffffffu, mx, off));
        float e0 = expf(s0 - mx);
        float e1 = (lane < MTOK - 32) ? expf(s1 - mx) : 0.f;
        float sm = e0 + e1;
        #pragma unroll
        for (int off = 16; off; off >>= 1) sm += __shfl_xor_sync(0xffffffffu, sm, off);
        float inv = 1.f / sm;
        ps[w][lane] = e0 * inv;
        if (lane < MTOK - 32) ps[w][lane + 32] = e1 * inv;
        __syncwarp();
        float a0 = 0.f, a1 = 0.f;
        #pragma unroll
        for (int m = 0; m < MTOK; m++) {
            float p = ps[w][m];
            a0 = fmaf(p, vs[m][lane], a0);
            a1 = fmaf(p, vs[m][lane + 32], a1);
        }
        size_t o0 = ((size_t)(b * NTOK + n)) * CDIM + hh * HD + lane;
        __half bh, bl;
        split_f16(a0, bh, bl); oh[o0] = bh;      ol[o0] = bl;
        split_f16(a1, bh, bl); oh[o0 + 32] = bh; ol[o0 + 32] = bl;
        __syncwarp();
    }
}

// ---------------- host ----------------
static inline int cdiv(int a, int b) { return (a + b - 1) / b; }
#define SMEM_BN64  (1024 + 3 * (BH_OFF + 64 * RSTRIDE))
#define SMEM_BN128 (1024 + 3 * (BH_OFF + 128 * RSTRIDE))

extern "C" void kernel_launch(void* const* d_in, const int* in_sizes, int n_in,
                              void* d_out, int out_size) {
    const float* x_in   = (const float*)d_in[0];
    const float* q_w    = (const float*)d_in[1];
    const float* dw_w   = (const float*)d_in[2];
    const float* dw_b   = (const float*)d_in[3];
    const float* pw_w   = (const float*)d_in[4];
    const float* pw_b   = (const float*)d_in[5];
    const float* lnr_g  = (const float*)d_in[6];
    const float* lnr_b  = (const float*)d_in[7];
    const float* k_w    = (const float*)d_in[8];
    const float* v_w    = (const float*)d_in[9];
    const float* proj_w = (const float*)d_in[10];
    const float* proj_b = (const float*)d_in[11];
    const float* ln1_g  = (const float*)d_in[12];
    const float* ln1_b  = (const float*)d_in[13];
    const float* ln2_g  = (const float*)d_in[14];
    const float* ln2_b  = (const float*)d_in[15];
    const float* fc1_w  = (const float*)d_in[16];
    const float* fc1_b  = (const float*)d_in[17];
    const float* fc2_w  = (const float*)d_in[18];
    const float* fc2_b  = (const float*)d_in[19];

    float* xcur = (float*)d_out;

    float *p_y, *p_r0, *p_q, *p_k, *p_v;
    __half *p_yh, *p_yl, *p_rch, *p_rcl, *p_rh, *p_rl, *p_oh, *p_ol, *p_hh, *p_hl;
    __half *wq, *wpw, *wk, *wv, *wp, *w1, *w2;
    cudaGetSymbolAddress((void**)&p_y, g_y);     cudaGetSymbolAddress((void**)&p_r0, g_r0);
    cudaGetSymbolAddress((void**)&p_q, g_q);     cudaGetSymbolAddress((void**)&p_k, g_k);
    cudaGetSymbolAddress((void**)&p_v, g_v);
    cudaGetSymbolAddress((void**)&p_yh, g_yh);   cudaGetSymbolAddress((void**)&p_yl, g_yl);
    cudaGetSymbolAddress((void**)&p_rch, g_rch); cudaGetSymbolAddress((void**)&p_rcl, g_rcl);
    cudaGetSymbolAddress((void**)&p_rh, g_rh);   cudaGetSymbolAddress((void**)&p_rl, g_rl);
    cudaGetSymbolAddress((void**)&p_oh, g_oh);   cudaGetSymbolAddress((void**)&p_ol, g_ol);
    cudaGetSymbolAddress((void**)&p_hh, g_hh);   cudaGetSymbolAddress((void**)&p_hl, g_hl);
    cudaGetSymbolAddress((void**)&wq, g_wq);     cudaGetSymbolAddress((void**)&wpw, g_wpw);
    cudaGetSymbolAddress((void**)&wk, g_wk);     cudaGetSymbolAddress((void**)&wv, g_wv);
    cudaGetSymbolAddress((void**)&wp, g_wp);     cudaGetSymbolAddress((void**)&w1, g_w1);
    cudaGetSymbolAddress((void**)&w2, g_w2);

    cudaFuncSetAttribute(tcmm_kernel<64,0>,  cudaFuncAttributeMaxDynamicSharedMemorySize, SMEM_BN64);
    cudaFuncSetAttribute(tcmm_kernel<64,1>,  cudaFuncAttributeMaxDynamicSharedMemorySize, SMEM_BN64);
    cudaFuncSetAttribute(tcmm_kernel<128,0>, cudaFuncAttributeMaxDynamicSharedMemorySize, SMEM_BN128);
    cudaFuncSetAttribute(tcmm_kernel<128,2>, cudaFuncAttributeMaxDynamicSharedMemorySize, SMEM_BN128);
    cudaFuncSetAttribute(tcmm_kernel<128,3>, cudaFuncAttributeMaxDynamicSharedMemorySize, SMEM_BN128);

    cudaMemcpyAsync(xcur, x_in, (size_t)ROWS_X * CDIM * sizeof(float),
                    cudaMemcpyDeviceToDevice, 0);

    for (int l = 0; l < LAYERS; l++) {
        wsplit_kernel<<<dim3(CNEW/32, CDIM/32), 256>>>(q_w  + (size_t)l*CDIM*CNEW,
            wq  + (size_t)l*CNEW*CDIM, CDIM, CNEW);
        wsplit_kernel<<<dim3(CNEW/32, CDIM/32), 256>>>(pw_w + (size_t)l*CDIM*CNEW,
            wpw + (size_t)l*CNEW*CDIM, CDIM, CNEW);
        wsplit_kernel<<<dim3(CNEW/32, CNEW/32), 256>>>(k_w  + (size_t)l*CNEW*CNEW,
            wk  + (size_t)l*CNEW*CNEW, CNEW, CNEW);
        wsplit_kernel<<<dim3(CDIM/32, CNEW/32), 256>>>(v_w  + (size_t)l*CNEW*CDIM,
            wv  + (size_t)l*CDIM*CNEW, CNEW, CDIM);
        wsplit_kernel<<<dim3(CDIM/32, CDIM/32), 256>>>(proj_w + (size_t)l*CDIM*CDIM,
            wp  + (size_t)l*CDIM*CDIM, CDIM, CDIM);
        wsplit_kernel<<<dim3(HIDDIM/32, CDIM/32), 256>>>(fc1_w + (size_t)l*CDIM*HIDDIM,
            w1  + (size_t)l*HIDDIM*CDIM, CDIM, HIDDIM);
        wsplit_kernel<<<dim3(CDIM/32, HIDDIM/32), 256>>>(fc2_w + (size_t)l*HIDDIM*CDIM,
            w2  + (size_t)l*CDIM*HIDDIM, HIDDIM, CDIM);
    }

    for (int l = 0; l < LAYERS; l++) {
        ln_kernel<<<ROWS_X, 256>>>(xcur, p_y, p_yh, p_yl,
                                   ln1_g + l*CDIM, ln1_b + l*CDIM, CDIM, 1e-6f, 0);
        dwconv_kernel<<<dim3(MTOK, BATCH), 256>>>(p_y, dw_w + (size_t)l*CDIM*4,
                                                  dw_b + l*CDIM, p_rch, p_rcl);
        // r0 = rconv @ pw + b   (3136 x 960, K=768)
        tcmm_kernel<64,1><<<dim3(CNEW/64, cdiv(ROWS_R,128)), 256, SMEM_BN64>>>(
            p_rch, p_rcl, wpw + (size_t)l*CNEW*CDIM,
            pw_b + l*CNEW, nullptr, p_r0, nullptr, nullptr, ROWS_R, CNEW, CDIM);
        ln_kernel<<<ROWS_R, 256>>>(p_r0, nullptr, p_rh, p_rl,
                                   lnr_g + l*CNEW, lnr_b + l*CNEW, CNEW, 1e-5f, 1);
        // q = y @ q_w           (12544 x 960, K=768)
        tcmm_kernel<64,0><<<dim3(CNEW/64, cdiv(ROWS_X,128)), 256, SMEM_BN64>>>(
            p_yh, p_yl, wq + (size_t)l*CNEW*CDIM,
            nullptr, nullptr, p_q, nullptr, nullptr, ROWS_X, CNEW, CDIM);
        // k = r @ k_w           (3136 x 960, K=960)
        tcmm_kernel<64,0><<<dim3(CNEW/64, cdiv(ROWS_R,128)), 256, SMEM_BN64>>>(
            p_rh, p_rl, wk + (size_t)l*CNEW*CNEW,
            nullptr, nullptr, p_k, nullptr, nullptr, ROWS_R, CNEW, CNEW);
        // v = r @ v_w           (3136 x 768, K=960)
        tcmm_kernel<128,0><<<dim3(CDIM/128, cdiv(ROWS_R,128)), 256, SMEM_BN128>>>(
            p_rh, p_rl, wv + (size_t)l*CDIM*CNEW,
            nullptr, nullptr, p_v, nullptr, nullptr, ROWS_R, CDIM, CNEW);
        attn_kernel<<<BATCH*NHEAD, 128>>>(p_q, p_k, p_v, p_oh, p_ol);
        // x += o @ proj + b     (12544 x 768, K=768)
        tcmm_kernel<128,3><<<dim3(CDIM/128, cdiv(ROWS_X,128)), 256, SMEM_BN128>>>(
            p_oh, p_ol, wp + (size_t)l*CDIM*CDIM,
            proj_b + l*CDIM, xcur, xcur, nullptr, nullptr, ROWS_X, CDIM, CDIM);
        ln_kernel<<<ROWS_X, 256>>>(xcur, nullptr, p_yh, p_yl,
                                   ln2_g + l*CDIM, ln2_b + l*CDIM, CDIM, 1e-6f, 0);
        // h = gelu(z @ fc1 + b) (12544 x 3072, K=768)
        tcmm_kernel<128,2><<<dim3(HIDDIM/128, cdiv(ROWS_X,128)), 256, SMEM_BN128>>>(
            p_yh, p_yl, w1 + (size_t)l*HIDDIM*CDIM,
            fc1_b + l*HIDDIM, nullptr, nullptr, p_hh, p_hl, ROWS_X, HIDDIM, CDIM);
        // x += h @ fc2 + b      (12544 x 768, K=3072)
        tcmm_kernel<128,3><<<dim3(CDIM/128, cdiv(ROWS_X,128)), 256, SMEM_BN128>>>(
            p_hh, p_hl, w2 + (size_t)l*CDIM*HIDDIM,
            fc2_b + l*CDIM, xcur, xcur, nullptr, nullptr, ROWS_X, CDIM, HIDDIM);
    }
}

// round 6
// speedup vs baseline: 4.1183x; 1.3259x over previous
#include <cuda_runtime.h>
#include <cuda_fp16.h>
#include <math.h>
#include <stdint.h>

#define LAYERS 4
#define BATCH  64
#define NTOK   196
#define CDIM   768
#define CNEW   960
#define HIDDIM 3072
#define NHEAD  12
#define HD     64
#define HDK    80
#define MTOK   49
#define HW     14
#define ROWS_X (BATCH * NTOK)   // 12544
#define ROWS_R (BATCH * MTOK)   // 3136

// ---------------- scratch ----------------
__device__ float g_y[ROWS_X * CDIM];
__device__ __align__(16) __half g_yh[ROWS_X * CDIM];
__device__ __align__(16) __half g_rch[ROWS_R * CDIM];
__device__ float g_r0[ROWS_R * CNEW];
__device__ __align__(16) __half g_rh[ROWS_R * CNEW];
__device__ float g_q[ROWS_X * CNEW];
__device__ float g_k[ROWS_R * CNEW];
__device__ float g_v[ROWS_R * CDIM];
__device__ __align__(16) __half g_oh[ROWS_X * CDIM];
__device__ __align__(16) __half g_hh[ROWS_X * HIDDIM];

// transposed weights, [N][K] K-major fp16
__device__ __align__(16) __half g_wq [LAYERS*CNEW*CDIM];
__device__ __align__(16) __half g_wpw[LAYERS*CNEW*CDIM];
__device__ __align__(16) __half g_wk [LAYERS*CNEW*CNEW];
__device__ __align__(16) __half g_wv [LAYERS*CDIM*CNEW];
__device__ __align__(16) __half g_wp [LAYERS*CDIM*CDIM];
__device__ __align__(16) __half g_w1 [LAYERS*HIDDIM*CDIM];
__device__ __align__(16) __half g_w2 [LAYERS*CDIM*HIDDIM];

// ---------------- helpers ----------------
__device__ __forceinline__ uint32_t smem_u32(const void* p) {
    uint32_t a;
    asm("{ .reg .u64 t; cvta.to.shared.u64 t, %1; cvt.u32.u64 %0, t; }" : "=r"(a) : "l"(p));
    return a;
}
__device__ __forceinline__ void cp16(uint32_t dst, const void* src) {
    asm volatile("cp.async.cg.shared.global [%0], [%1], 16;" :: "r"(dst), "l"(src));
}
__device__ __forceinline__ void cp_commit() { asm volatile("cp.async.commit_group;" ::: "memory"); }
template <int N> __device__ __forceinline__ void cp_wait() {
    asm volatile("cp.async.wait_group %0;" :: "n"(N) : "memory");
}
__device__ __forceinline__ void ldsm_x4(uint32_t (&r)[4], uint32_t addr) {
    asm volatile("ldmatrix.sync.aligned.m8n8.x4.shared.b16 {%0,%1,%2,%3}, [%4];"
        : "=r"(r[0]), "=r"(r[1]), "=r"(r[2]), "=r"(r[3]) : "r"(addr));
}
__device__ __forceinline__ void mma16816(float (&d)[4], const uint32_t (&a)[4],
                                         uint32_t b0, uint32_t b1) {
    asm volatile("mma.sync.aligned.m16n8k16.row.col.f32.f16.f16.f32 "
        "{%0,%1,%2,%3}, {%4,%5,%6,%7}, {%8,%9}, {%0,%1,%2,%3};"
        : "+f"(d[0]), "+f"(d[1]), "+f"(d[2]), "+f"(d[3])
        : "r"(a[0]), "r"(a[1]), "r"(a[2]), "r"(a[3]), "r"(b0), "r"(b1));
}
__device__ __forceinline__ float gelu_exact(float x) {
    return 0.5f * x * (1.0f + erff(x * 0.7071067811865476f));
}

// ---------------- weight transpose -> fp16 ----------------
__global__ __launch_bounds__(256) void wsplit_kernel(
        const float* __restrict__ W, __half* __restrict__ T, int K, int N) {
    __shared__ float t[32][33];
    const int n0 = blockIdx.x * 32, k0 = blockIdx.y * 32;
    const int tx = threadIdx.x & 31, ty = threadIdx.x >> 5;
    #pragma unroll
    for (int i = 0; i < 4; i++) {
        int k = ty + i * 8;
        t[k][tx] = W[(size_t)(k0 + k) * N + n0 + tx];
    }
    __syncthreads();
    #pragma unroll
    for (int i = 0; i < 4; i++) {
        int n = ty + i * 8;
        T[(size_t)(n0 + n) * K + k0 + tx] = __float2half_rn(t[tx][n]);
    }
}

// ---------------- LayerNorm (+gelu) ----------------
__global__ void ln_kernel(const float* __restrict__ in, float* __restrict__ outf,
                          __half* __restrict__ oh,
                          const float* __restrict__ gamma, const float* __restrict__ beta,
                          int W, float eps, int do_gelu) {
    const int row = blockIdx.x;
    const float* p = in + (size_t)row * W;
    float s = 0.f, ss = 0.f;
    for (int i = threadIdx.x; i < W; i += blockDim.x) { float v = p[i]; s += v; ss += v * v; }
    __shared__ float red_s[32], red_ss[32];
    int lane = threadIdx.x & 31, wid = threadIdx.x >> 5;
    #pragma unroll
    for (int off = 16; off; off >>= 1) {
        s  += __shfl_xor_sync(0xffffffffu, s, off);
        ss += __shfl_xor_sync(0xffffffffu, ss, off);
    }
    if (lane == 0) { red_s[wid] = s; red_ss[wid] = ss; }
    __syncthreads();
    int nw = blockDim.x >> 5;
    if (wid == 0) {
        s  = (lane < nw) ? red_s[lane]  : 0.f;
        ss = (lane < nw) ? red_ss[lane] : 0.f;
        #pragma unroll
        for (int off = 16; off; off >>= 1) {
            s  += __shfl_xor_sync(0xffffffffu, s, off);
            ss += __shfl_xor_sync(0xffffffffu, ss, off);
        }
        if (lane == 0) { red_s[0] = s; red_ss[0] = ss; }
    }
    __syncthreads();
    float mean = red_s[0] / (float)W;
    float var  = red_ss[0] / (float)W - mean * mean;
    float inv  = rsqrtf(var + eps);
    for (int i = threadIdx.x; i < W; i += blockDim.x) {
        float v = (p[i] - mean) * inv * gamma[i] + beta[i];
        if (do_gelu) v = gelu_exact(v);
        size_t o = (size_t)row * W + i;
        if (outf) outf[o] = v;
        if (oh) oh[o] = __float2half_rn(v);
    }
}

// ---------------- depthwise 2x2/s2 conv -> fp16 ----------------
__global__ void dwconv_kernel(const float* __restrict__ y,
                              const float* __restrict__ w4, const float* __restrict__ bias,
                              __half* __restrict__ oh) {
    const int m = blockIdx.x, b = blockIdx.y;
    const int h7 = m / 7, w7 = m % 7;
    const int p00 = (h7 * 2) * HW + w7 * 2;
    const float* yb = y + (size_t)b * NTOK * CDIM;
    const size_t ob = ((size_t)b * MTOK + m) * CDIM;
    for (int c = threadIdx.x; c < CDIM; c += blockDim.x) {
        float acc = yb[(size_t)(p00         ) * CDIM + c] * w4[c * 4 + 0]
                  + yb[(size_t)(p00 + 1     ) * CDIM + c] * w4[c * 4 + 1]
                  + yb[(size_t)(p00 + HW    ) * CDIM + c] * w4[c * 4 + 2]
                  + yb[(size_t)(p00 + HW + 1) * CDIM + c] * w4[c * 4 + 3]
                  + bias[c];
        oh[ob + c] = __float2half_rn(acc);
    }
}

// ---------------------------------------------------------------------------
// fp16 1-pass GEMM on HMMA: C = A[M,K] @ B[N,K]^T
// CTA tile 128 x BN, BK=32, 3-stage cp.async pipeline.
// smem rows padded to 80B -> ldmatrix conflict-free.
// EPI: 0 fp32, 1 +bias fp32, 2 +bias+gelu -> fp16, 3 +bias+resid fp32
// ---------------------------------------------------------------------------
#define RSTRIDE 80
#define B_OFF   (128 * RSTRIDE)            // 10240

template <int BN, int EPI>
__global__ __launch_bounds__(256) void tcmm_kernel(
        const __half* __restrict__ A, const __half* __restrict__ B,
        const float* __restrict__ bias, const float* __restrict__ resid,
        float* __restrict__ Cf, __half* __restrict__ Ch,
        int M, int N, int K) {
    constexpr int SS   = B_OFF + BN * RSTRIDE;   // stage bytes
    constexpr int WN   = BN / 2;
    constexpr int WN8  = WN / 8;
    constexpr int WN16 = WN / 16;
    extern __shared__ char smem[];
    const int tid = threadIdx.x, lane = tid & 31, wid = tid >> 5;
    const int wm = wid >> 1, wn = wid & 1;               // 4 x 2 warp grid
    const int row0 = blockIdx.y * 128, col0 = blockIdx.x * BN;
    const uint32_t tiles = (smem_u32(smem) + 1023) & ~1023u;

    float acc[2][WN8][4];
    #pragma unroll
    for (int a = 0; a < 2; a++)
        #pragma unroll
        for (int b = 0; b < WN8; b++)
            #pragma unroll
            for (int c = 0; c < 4; c++) acc[a][b][c] = 0.f;

    const int NC = K >> 5;   // BK = 32

    auto load_chunk = [&](int stage, int k0) {
        uint32_t sd = tiles + stage * SS;
        #pragma unroll
        for (int i = 0; i < 2; i++) {                // A: 512 cp16
            int idx = tid + i * 256;
            int row = idx >> 2, c = idx & 3;
            int grow = row0 + row; if (grow > M - 1) grow = M - 1;
            cp16(sd + row * RSTRIDE + c * 16, A + (size_t)grow * K + k0 + c * 8);
        }
        #pragma unroll
        for (int i = 0; i < BN / 64; i++) {          // B: 4*BN cp16
            int idx = tid + i * 256;
            int row = idx >> 2, c = idx & 3;
            cp16(sd + B_OFF + row * RSTRIDE + c * 16, B + (size_t)(col0 + row) * K + k0 + c * 8);
        }
    };

    load_chunk(0, 0);  cp_commit();
    load_chunk(1, 32); cp_commit();

    for (int c = 0; c < NC; c++) {
        if (c + 2 < NC) cp_wait<1>(); else cp_wait<0>();
        __syncthreads();
        if (c + 2 < NC) { load_chunk((c + 2) % 3, (c + 2) * 32); cp_commit(); }

        const uint32_t sA = tiles + (c % 3) * SS;
        const uint32_t sB = sA + B_OFF;
        #pragma unroll
        for (int ks = 0; ks < 2; ks++) {
            uint32_t ah[2][4];
            #pragma unroll
            for (int mt = 0; mt < 2; mt++) {
                uint32_t r = sA + (wm * 32 + mt * 16 + (lane & 15)) * RSTRIDE
                           + (2 * ks + (lane >> 4)) * 16;
                ldsm_x4(ah[mt], r);
            }
            uint32_t bh[WN16][4];
            #pragma unroll
            for (int g = 0; g < WN16; g++) {
                int rrow = wn * WN + g * 16 + (lane & 7) + ((lane >> 4) << 3);
                uint32_t r = sB + rrow * RSTRIDE + (2 * ks + ((lane >> 3) & 1)) * 16;
                ldsm_x4(bh[g], r);
            }
            #pragma unroll
            for (int mt = 0; mt < 2; mt++)
                #pragma unroll
                for (int g = 0; g < WN16; g++) {
                    mma16816(acc[mt][2*g],   ah[mt], bh[g][0], bh[g][1]);
                    mma16816(acc[mt][2*g+1], ah[mt], bh[g][2], bh[g][3]);
                }
        }
    }

    // epilogue
    const int er = lane >> 2, ec = (lane & 3) * 2;
    #pragma unroll
    for (int mt = 0; mt < 2; mt++) {
        #pragma unroll
        for (int g = 0; g < WN8; g++) {
            const int gn = col0 + wn * WN + g * 8 + ec;
            #pragma unroll
            for (int hrow = 0; hrow < 2; hrow++) {
                const int gm = row0 + wm * 32 + mt * 16 + er + hrow * 8;
                if (gm >= M) continue;
                float v0 = acc[mt][g][2 * hrow];
                float v1 = acc[mt][g][2 * hrow + 1];
                const size_t base = (size_t)gm * N + gn;
                if constexpr (EPI >= 1) { v0 += bias[gn]; v1 += bias[gn + 1]; }
                if constexpr (EPI == 2) {
                    v0 = gelu_exact(v0); v1 = gelu_exact(v1);
                    __half2 hp; hp.x = __float2half_rn(v0); hp.y = __float2half_rn(v1);
                    *(__half2*)(Ch + base) = hp;
                } else {
                    if constexpr (EPI == 3) {
                        float2 rs = *(const float2*)(resid + base);
                        v0 += rs.x; v1 += rs.y;
                    }
                    float2 o; o.x = v0; o.y = v1;
                    *(float2*)(Cf + base) = o;
                }
            }
        }
    }
}

// ---------------- attention (fp32), outputs fp16 ----------------
__global__ __launch_bounds__(128) void attn_kernel(
        const float* __restrict__ q, const float* __restrict__ k,
        const float* __restrict__ v, __half* __restrict__ oh) {
    const int b = blockIdx.x / NHEAD;
    const int hh = blockIdx.x % NHEAD;
    __shared__ float ks[MTOK][HDK + 1];
    __shared__ float vs[MTOK][HD + 1];
    __shared__ float qs[4][HDK];
    __shared__ float ps[4][MTOK];
    const int tid = threadIdx.x, w = tid >> 5, lane = tid & 31;
    const float* kb = k + (size_t)b * MTOK * CNEW + hh * HDK;
    const float* vb = v + (size_t)b * MTOK * CDIM + hh * HD;
    for (int i = tid; i < MTOK * HDK; i += 128) {
        int m = i / HDK, d = i % HDK;
        ks[m][d] = kb[(size_t)m * CNEW + d];
    }
    for (int i = tid; i < MTOK * HD; i += 128) {
        int m = i / HD, d = i % HD;
        vs[m][d] = vb[(size_t)m * CDIM + d];
    }
    __syncthreads();
    const float scale = rsqrtf(80.0f);
    for (int n = w; n < NTOK; n += 4) {
        const float* qp = q + ((size_t)(b * NTOK + n)) * CNEW + hh * HDK;
        for (int i = lane; i < HDK; i += 32) qs[w][i] = qp[i];
        __syncwarp();
        float s0 = 0.f, s1 = 0.f;
        #pragma unroll
        for (int d = 0; d < HDK; d++) {
            float qv = qs[w][d];
            s0 = fmaf(qv, ks[lane][d], s0);
            if (lane < MTOK - 32) s1 = fmaf(qv, ks[lane + 32][d], s1);
        }
        s0 *= scale; s1 *= scale;
        float mx = fmaxf(s0, (lane < MTOK - 32) ? s1 : -1e30f);
        #pragma unroll
        for (int off = 16; off; off >>= 1) mx = fmaxf(mx, __shfl_xor_sync(0xffffffffu, mx, off));
        float e0 = expf(s0 - mx);
        float e1 = (lane < MTOK - 32) ? expf(s1 - mx) : 0.f;
        float sm = e0 + e1;
        #pragma unroll
        for (int off = 16; off; off >>= 1) sm += __shfl_xor_sync(0xffffffffu, sm, off);
        float inv = 1.f / sm;
        ps[w][lane] = e0 * inv;
        if (lane < MTOK - 32) ps[w][lane + 32] = e1 * inv;
        __syncwarp();
        float a0 = 0.f, a1 = 0.f;
        #pragma unroll
        for (int m = 0; m < MTOK; m++) {
            float p = ps[w][m];
            a0 = fmaf(p, vs[m][lane], a0);
            a1 = fmaf(p, vs[m][lane + 32], a1);
        }
        size_t o0 = ((size_t)(b * NTOK + n)) * CDIM + hh * HD + lane;
        oh[o0]      = __float2half_rn(a0);
        oh[o0 + 32] = __float2half_rn(a1);
        __syncwarp();
    }
}

// ---------------- host ----------------
static inline int cdiv(int a, int b) { return (a + b - 1) / b; }
#define SMEM_BN64  (1024 + 3 * (B_OFF + 64 * RSTRIDE))
#define SMEM_BN128 (1024 + 3 * (B_OFF + 128 * RSTRIDE))

extern "C" void kernel_launch(void* const* d_in, const int* in_sizes, int n_in,
                              void* d_out, int out_size) {
    const float* x_in   = (const float*)d_in[0];
    const float* q_w    = (const float*)d_in[1];
    const float* dw_w   = (const float*)d_in[2];
    const float* dw_b   = (const float*)d_in[3];
    const float* pw_w   = (const float*)d_in[4];
    const float* pw_b   = (const float*)d_in[5];
    const float* lnr_g  = (const float*)d_in[6];
    const float* lnr_b  = (const float*)d_in[7];
    const float* k_w    = (const float*)d_in[8];
    const float* v_w    = (const float*)d_in[9];
    const float* proj_w = (const float*)d_in[10];
    const float* proj_b = (const float*)d_in[11];
    const float* ln1_g  = (const float*)d_in[12];
    const float* ln1_b  = (const float*)d_in[13];
    const float* ln2_g  = (const float*)d_in[14];
    const float* ln2_b  = (const float*)d_in[15];
    const float* fc1_w  = (const float*)d_in[16];
    const float* fc1_b  = (const float*)d_in[17];
    const float* fc2_w  = (const float*)d_in[18];
    const float* fc2_b  = (const float*)d_in[19];

    float* xcur = (float*)d_out;

    float *p_y, *p_r0, *p_q, *p_k, *p_v;
    __half *p_yh, *p_rch, *p_rh, *p_oh, *p_hh;
    __half *wq, *wpw, *wk, *wv, *wp, *w1, *w2;
    cudaGetSymbolAddress((void**)&p_y, g_y);     cudaGetSymbolAddress((void**)&p_r0, g_r0);
    cudaGetSymbolAddress((void**)&p_q, g_q);     cudaGetSymbolAddress((void**)&p_k, g_k);
    cudaGetSymbolAddress((void**)&p_v, g_v);
    cudaGetSymbolAddress((void**)&p_yh, g_yh);   cudaGetSymbolAddress((void**)&p_rch, g_rch);
    cudaGetSymbolAddress((void**)&p_rh, g_rh);   cudaGetSymbolAddress((void**)&p_oh, g_oh);
    cudaGetSymbolAddress((void**)&p_hh, g_hh);
    cudaGetSymbolAddress((void**)&wq, g_wq);     cudaGetSymbolAddress((void**)&wpw, g_wpw);
    cudaGetSymbolAddress((void**)&wk, g_wk);     cudaGetSymbolAddress((void**)&wv, g_wv);
    cudaGetSymbolAddress((void**)&wp, g_wp);     cudaGetSymbolAddress((void**)&w1, g_w1);
    cudaGetSymbolAddress((void**)&w2, g_w2);

    cudaFuncSetAttribute(tcmm_kernel<64,0>,  cudaFuncAttributeMaxDynamicSharedMemorySize, SMEM_BN64);
    cudaFuncSetAttribute(tcmm_kernel<64,1>,  cudaFuncAttributeMaxDynamicSharedMemorySize, SMEM_BN64);
    cudaFuncSetAttribute(tcmm_kernel<128,0>, cudaFuncAttributeMaxDynamicSharedMemorySize, SMEM_BN128);
    cudaFuncSetAttribute(tcmm_kernel<128,2>, cudaFuncAttributeMaxDynamicSharedMemorySize, SMEM_BN128);
    cudaFuncSetAttribute(tcmm_kernel<128,3>, cudaFuncAttributeMaxDynamicSharedMemorySize, SMEM_BN128);

    cudaMemcpyAsync(xcur, x_in, (size_t)ROWS_X * CDIM * sizeof(float),
                    cudaMemcpyDeviceToDevice, 0);

    for (int l = 0; l < LAYERS; l++) {
        wsplit_kernel<<<dim3(CNEW/32, CDIM/32), 256>>>(q_w  + (size_t)l*CDIM*CNEW,
            wq  + (size_t)l*CNEW*CDIM, CDIM, CNEW);
        wsplit_kernel<<<dim3(CNEW/32, CDIM/32), 256>>>(pw_w + (size_t)l*CDIM*CNEW,
            wpw + (size_t)l*CNEW*CDIM, CDIM, CNEW);
        wsplit_kernel<<<dim3(CNEW/32, CNEW/32), 256>>>(k_w  + (size_t)l*CNEW*CNEW,
            wk  + (size_t)l*CNEW*CNEW, CNEW, CNEW);
        wsplit_kernel<<<dim3(CDIM/32, CNEW/32), 256>>>(v_w  + (size_t)l*CNEW*CDIM,
            wv  + (size_t)l*CDIM*CNEW, CNEW, CDIM);
        wsplit_kernel<<<dim3(CDIM/32, CDIM/32), 256>>>(proj_w + (size_t)l*CDIM*CDIM,
            wp  + (size_t)l*CDIM*CDIM, CDIM, CDIM);
        wsplit_kernel<<<dim3(HIDDIM/32, CDIM/32), 256>>>(fc1_w + (size_t)l*CDIM*HIDDIM,
            w1  + (size_t)l*HIDDIM*CDIM, CDIM, HIDDIM);
        wsplit_kernel<<<dim3(CDIM/32, HIDDIM/32), 256>>>(fc2_w + (size_t)l*HIDDIM*CDIM,
            w2  + (size_t)l*CDIM*HIDDIM, HIDDIM, CDIM);
    }

    for (int l = 0; l < LAYERS; l++) {
        ln_kernel<<<ROWS_X, 256>>>(xcur, p_y, p_yh,
                                   ln1_g + l*CDIM, ln1_b + l*CDIM, CDIM, 1e-6f, 0);
        dwconv_kernel<<<dim3(MTOK, BATCH), 256>>>(p_y, dw_w + (size_t)l*CDIM*4,
                                                  dw_b + l*CDIM, p_rch);
        // r0 = rconv @ pw + b   (3136 x 960, K=768)
        tcmm_kernel<64,1><<<dim3(CNEW/64, cdiv(ROWS_R,128)), 256, SMEM_BN64>>>(
            p_rch, wpw + (size_t)l*CNEW*CDIM,
            pw_b + l*CNEW, nullptr, p_r0, nullptr, ROWS_R, CNEW, CDIM);
        ln_kernel<<<ROWS_R, 256>>>(p_r0, nullptr, p_rh,
                                   lnr_g + l*CNEW, lnr_b + l*CNEW, CNEW, 1e-5f, 1);
        // q = y @ q_w           (12544 x 960, K=768)
        tcmm_kernel<64,0><<<dim3(CNEW/64, cdiv(ROWS_X,128)), 256, SMEM_BN64>>>(
            p_yh, wq + (size_t)l*CNEW*CDIM,
            nullptr, nullptr, p_q, nullptr, ROWS_X, CNEW, CDIM);
        // k = r @ k_w           (3136 x 960, K=960)
        tcmm_kernel<64,0><<<dim3(CNEW/64, cdiv(ROWS_R,128)), 256, SMEM_BN64>>>(
            p_rh, wk + (size_t)l*CNEW*CNEW,
            nullptr, nullptr, p_k, nullptr, ROWS_R, CNEW, CNEW);
        // v = r @ v_w           (3136 x 768, K=960)
        tcmm_kernel<128,0><<<dim3(CDIM/128, cdiv(ROWS_R,128)), 256, SMEM_BN128>>>(
            p_rh, wv + (size_t)l*CDIM*CNEW,
            nullptr, nullptr, p_v, nullptr, ROWS_R, CDIM, CNEW);
        attn_kernel<<<BATCH*NHEAD, 128>>>(p_q, p_k, p_v, p_oh);
        // x += o @ proj + b     (12544 x 768, K=768)
        tcmm_kernel<128,3><<<dim3(CDIM/128, cdiv(ROWS_X,128)), 256, SMEM_BN128>>>(
            p_oh, wp + (size_t)l*CDIM*CDIM,
            proj_b + l*CDIM, xcur, xcur, nullptr, ROWS_X, CDIM, CDIM);
        ln_kernel<<<ROWS_X, 256>>>(xcur, nullptr, p_yh,
                                   ln2_g + l*CDIM, ln2_b + l*CDIM, CDIM, 1e-6f, 0);
        // h = gelu(z @ fc1 + b) (12544 x 3072, K=768)
        tcmm_kernel<128,2><<<dim3(HIDDIM/128, cdiv(ROWS_X,128)), 256, SMEM_BN128>>>(
            p_yh, w1 + (size_t)l*HIDDIM*CDIM,
            fc1_b + l*HIDDIM, nullptr, nullptr, p_hh, ROWS_X, HIDDIM, CDIM);
        // x += h @ fc2 + b      (12544 x 768, K=3072)
        tcmm_kernel<128,3><<<dim3(CDIM/128, cdiv(ROWS_X,128)), 256, SMEM_BN128>>>(
            p_hh, w2 + (size_t)l*CDIM*HIDDIM,
            fc2_b + l*CDIM, xcur, xcur, nullptr, ROWS_X, CDIM, HIDDIM);
    }
}

// round 7
// speedup vs baseline: 4.8212x; 1.1707x over previous
#include <cuda_runtime.h>
#include <cuda_fp16.h>
#include <math.h>
#include <stdint.h>

#define LAYERS 4
#define BATCH  64
#define NTOK   196
#define CDIM   768
#define CNEW   960
#define HIDDIM 3072
#define NHEAD  12
#define HD     64
#define HDK    80
#define MTOK   49
#define HW     14
#define ROWS_X (BATCH * NTOK)   // 12544
#define ROWS_R (BATCH * MTOK)   // 3136

// ---------------- scratch ----------------
__device__ float g_r0[ROWS_R * CNEW];
__device__ __align__(16) __half g_yh[ROWS_X * CDIM];
__device__ __align__(16) __half g_rch[ROWS_R * CDIM];
__device__ __align__(16) __half g_rh[ROWS_R * CNEW];
__device__ __align__(16) __half g_qh[ROWS_X * CNEW];
__device__ __align__(16) __half g_kh[ROWS_R * CNEW];
__device__ __align__(16) __half g_vh[ROWS_R * CDIM];
__device__ __align__(16) __half g_oh[ROWS_X * CDIM];
__device__ __align__(16) __half g_hh[ROWS_X * HIDDIM];

// transposed weights, [N][K] K-major fp16
__device__ __align__(16) __half g_wq [LAYERS*CNEW*CDIM];
__device__ __align__(16) __half g_wpw[LAYERS*CNEW*CDIM];
__device__ __align__(16) __half g_wk [LAYERS*CNEW*CNEW];
__device__ __align__(16) __half g_wv [LAYERS*CDIM*CNEW];
__device__ __align__(16) __half g_wp [LAYERS*CDIM*CDIM];
__device__ __align__(16) __half g_w1 [LAYERS*HIDDIM*CDIM];
__device__ __align__(16) __half g_w2 [LAYERS*CDIM*HIDDIM];

// ---------------- helpers ----------------
__device__ __forceinline__ uint32_t smem_u32(const void* p) {
    uint32_t a;
    asm("{ .reg .u64 t; cvta.to.shared.u64 t, %1; cvt.u32.u64 %0, t; }" : "=r"(a) : "l"(p));
    return a;
}
__device__ __forceinline__ void cp16(uint32_t dst, const void* src) {
    asm volatile("cp.async.cg.shared.global [%0], [%1], 16;" :: "r"(dst), "l"(src));
}
__device__ __forceinline__ void cp_commit() { asm volatile("cp.async.commit_group;" ::: "memory"); }
template <int N> __device__ __forceinline__ void cp_wait() {
    asm volatile("cp.async.wait_group %0;" :: "n"(N) : "memory");
}
__device__ __forceinline__ void ldsm_x4(uint32_t (&r)[4], uint32_t addr) {
    asm volatile("ldmatrix.sync.aligned.m8n8.x4.shared.b16 {%0,%1,%2,%3}, [%4];"
        : "=r"(r[0]), "=r"(r[1]), "=r"(r[2]), "=r"(r[3]) : "r"(addr));
}
__device__ __forceinline__ void mma16816(float (&d)[4], const uint32_t (&a)[4],
                                         uint32_t b0, uint32_t b1) {
    asm volatile("mma.sync.aligned.m16n8k16.row.col.f32.f16.f16.f32 "
        "{%0,%1,%2,%3}, {%4,%5,%6,%7}, {%8,%9}, {%0,%1,%2,%3};"
        : "+f"(d[0]), "+f"(d[1]), "+f"(d[2]), "+f"(d[3])
        : "r"(a[0]), "r"(a[1]), "r"(a[2]), "r"(a[3]), "r"(b0), "r"(b1));
}
__device__ __forceinline__ float gelu_exact(float x) {
    return 0.5f * x * (1.0f + erff(x * 0.7071067811865476f));
}

// ---------------- weight transpose -> fp16 (z = layer) ----------------
__global__ __launch_bounds__(256) void wsplit_kernel(
        const float* __restrict__ W, __half* __restrict__ T, int K, int N) {
    const float* Wl = W + (size_t)blockIdx.z * K * N;
    __half* Tl = T + (size_t)blockIdx.z * K * N;
    __shared__ float t[32][33];
    const int n0 = blockIdx.x * 32, k0 = blockIdx.y * 32;
    const int tx = threadIdx.x & 31, ty = threadIdx.x >> 5;
    #pragma unroll
    for (int i = 0; i < 4; i++) {
        int k = ty + i * 8;
        t[k][tx] = Wl[(size_t)(k0 + k) * N + n0 + tx];
    }
    __syncthreads();
    #pragma unroll
    for (int i = 0; i < 4; i++) {
        int n = ty + i * 8;
        Tl[(size_t)(n0 + n) * K + k0 + tx] = __float2half_rn(t[tx][n]);
    }
}

// ---------------- LayerNorm (+gelu) ----------------
__global__ void ln_kernel(const float* __restrict__ in, float* __restrict__ outf,
                          __half* __restrict__ oh,
                          const float* __restrict__ gamma, const float* __restrict__ beta,
                          int W, float eps, int do_gelu) {
    const int row = blockIdx.x;
    const float* p = in + (size_t)row * W;
    float s = 0.f, ss = 0.f;
    for (int i = threadIdx.x; i < W; i += blockDim.x) { float v = p[i]; s += v; ss += v * v; }
    __shared__ float red_s[32], red_ss[32];
    int lane = threadIdx.x & 31, wid = threadIdx.x >> 5;
    #pragma unroll
    for (int off = 16; off; off >>= 1) {
        s  += __shfl_xor_sync(0xffffffffu, s, off);
        ss += __shfl_xor_sync(0xffffffffu, ss, off);
    }
    if (lane == 0) { red_s[wid] = s; red_ss[wid] = ss; }
    __syncthreads();
    int nw = blockDim.x >> 5;
    if (wid == 0) {
        s  = (lane < nw) ? red_s[lane]  : 0.f;
        ss = (lane < nw) ? red_ss[lane] : 0.f;
        #pragma unroll
        for (int off = 16; off; off >>= 1) {
            s  += __shfl_xor_sync(0xffffffffu, s, off);
            ss += __shfl_xor_sync(0xffffffffu, ss, off);
        }
        if (lane == 0) { red_s[0] = s; red_ss[0] = ss; }
    }
    __syncthreads();
    float mean = red_s[0] / (float)W;
    float var  = red_ss[0] / (float)W - mean * mean;
    float inv  = rsqrtf(var + eps);
    for (int i = threadIdx.x; i < W; i += blockDim.x) {
        float v = (p[i] - mean) * inv * gamma[i] + beta[i];
        if (do_gelu) v = gelu_exact(v);
        size_t o = (size_t)row * W + i;
        if (outf) outf[o] = v;
        if (oh) oh[o] = __float2half_rn(v);
    }
}

// ---------------- depthwise 2x2/s2 conv, fp16 in -> fp16 out ----------------
__global__ void dwconv_kernel(const __half* __restrict__ y,
                              const float* __restrict__ w4, const float* __restrict__ bias,
                              __half* __restrict__ oh) {
    const int m = blockIdx.x, b = blockIdx.y;
    const int h7 = m / 7, w7 = m % 7;
    const int p00 = (h7 * 2) * HW + w7 * 2;
    const __half* yb = y + (size_t)b * NTOK * CDIM;
    const size_t ob = ((size_t)b * MTOK + m) * CDIM;
    for (int c = threadIdx.x; c < CDIM; c += blockDim.x) {
        float acc = __half2float(yb[(size_t)(p00         ) * CDIM + c]) * w4[c * 4 + 0]
                  + __half2float(yb[(size_t)(p00 + 1     ) * CDIM + c]) * w4[c * 4 + 1]
                  + __half2float(yb[(size_t)(p00 + HW    ) * CDIM + c]) * w4[c * 4 + 2]
                  + __half2float(yb[(size_t)(p00 + HW + 1) * CDIM + c]) * w4[c * 4 + 3]
                  + bias[c];
        oh[ob + c] = __float2half_rn(acc);
    }
}

// ---------------------------------------------------------------------------
// fp16 GEMM on HMMA: C = A[M,K] @ B[N,K]^T
// CTA tile BM x BN, BK=64, 3-stage cp.async pipeline, RSTRIDE=144 (conflict-free).
// EPI: 1 +bias fp32, 2 +bias+gelu fp16, 3 +bias+resid fp32, 4 plain fp16
// ---------------------------------------------------------------------------
#define RSTRIDE 144

template <int BM, int BN, int EPI>
__global__ __launch_bounds__(256) void tcmm_kernel(
        const __half* __restrict__ A, const __half* __restrict__ B,
        const float* __restrict__ bias, const float* __restrict__ resid,
        float* __restrict__ Cf, __half* __restrict__ Ch,
        int M, int N, int K) {
    constexpr int SS = (BM + BN) * RSTRIDE;      // stage bytes
    constexpr int WN_WARPS = (BM == 128) ? 2 : 4;
    constexpr int WN   = BN / WN_WARPS;
    constexpr int WN8  = WN / 8;
    constexpr int WN16 = WN / 16;
    extern __shared__ char smem[];
    const int tid = threadIdx.x, lane = tid & 31, wid = tid >> 5;
    const int wn = wid % WN_WARPS, wm = wid / WN_WARPS;
    const int row0 = blockIdx.y * BM, col0 = blockIdx.x * BN;
    const uint32_t tiles = (smem_u32(smem) + 1023) & ~1023u;

    float acc[2][WN8][4];
    #pragma unroll
    for (int a = 0; a < 2; a++)
        #pragma unroll
        for (int b = 0; b < WN8; b++)
            #pragma unroll
            for (int c = 0; c < 4; c++) acc[a][b][c] = 0.f;

    const int NC = K >> 6;   // BK = 64

    auto load_chunk = [&](int stage, int k0) {
        uint32_t sd = tiles + stage * SS;
        #pragma unroll
        for (int i = 0; i < BM * 8 / 256; i++) {     // A: BM rows x 128B
            int idx = tid + i * 256;
            int row = idx >> 3, cc = idx & 7;
            int grow = row0 + row; if (grow > M - 1) grow = M - 1;
            cp16(sd + row * RSTRIDE + cc * 16, A + (size_t)grow * K + k0 + cc * 8);
        }
        #pragma unroll
        for (int i = 0; i < BN * 8 / 256; i++) {     // B: BN rows x 128B
            int idx = tid + i * 256;
            int row = idx >> 3, cc = idx & 7;
            cp16(sd + BM * RSTRIDE + row * RSTRIDE + cc * 16,
                 B + (size_t)(col0 + row) * K + k0 + cc * 8);
        }
    };

    load_chunk(0, 0);  cp_commit();
    load_chunk(1, 64); cp_commit();

    for (int c = 0; c < NC; c++) {
        if (c + 2 < NC) cp_wait<1>(); else cp_wait<0>();
        __syncthreads();
        if (c + 2 < NC) { load_chunk((c + 2) % 3, (c + 2) * 64); cp_commit(); }

        const uint32_t sA = tiles + (c % 3) * SS;
        const uint32_t sB = sA + BM * RSTRIDE;
        #pragma unroll
        for (int ks = 0; ks < 4; ks++) {
            uint32_t ah[2][4];
            #pragma unroll
            for (int mt = 0; mt < 2; mt++) {
                uint32_t r = sA + (wm * 32 + mt * 16 + (lane & 15)) * RSTRIDE
                           + (2 * ks + (lane >> 4)) * 16;
                ldsm_x4(ah[mt], r);
            }
            uint32_t bh[WN16][4];
            #pragma unroll
            for (int g = 0; g < WN16; g++) {
                int rrow = wn * WN + g * 16 + (lane & 7) + ((lane >> 4) << 3);
                uint32_t r = sB + rrow * RSTRIDE + (2 * ks + ((lane >> 3) & 1)) * 16;
                ldsm_x4(bh[g], r);
            }
            #pragma unroll
            for (int mt = 0; mt < 2; mt++)
                #pragma unroll
                for (int g = 0; g < WN16; g++) {
                    mma16816(acc[mt][2*g],   ah[mt], bh[g][0], bh[g][1]);
                    mma16816(acc[mt][2*g+1], ah[mt], bh[g][2], bh[g][3]);
                }
        }
    }

    // epilogue
    const int er = lane >> 2, ec = (lane & 3) * 2;
    #pragma unroll
    for (int mt = 0; mt < 2; mt++) {
        #pragma unroll
        for (int g = 0; g < WN8; g++) {
            const int gn = col0 + wn * WN + g * 8 + ec;
            #pragma unroll
            for (int hrow = 0; hrow < 2; hrow++) {
                const int gm = row0 + wm * 32 + mt * 16 + er + hrow * 8;
                if (gm >= M) continue;
                float v0 = acc[mt][g][2 * hrow];
                float v1 = acc[mt][g][2 * hrow + 1];
                const size_t base = (size_t)gm * N + gn;
                if constexpr (EPI == 1 || EPI == 2 || EPI == 3) {
                    v0 += bias[gn]; v1 += bias[gn + 1];
                }
                if constexpr (EPI == 2 || EPI == 4) {
                    if constexpr (EPI == 2) { v0 = gelu_exact(v0); v1 = gelu_exact(v1); }
                    __half2 hp; hp.x = __float2half_rn(v0); hp.y = __float2half_rn(v1);
                    *(__half2*)(Ch + base) = hp;
                } else {
                    if constexpr (EPI == 3) {
                        float2 rs = *(const float2*)(resid + base);
                        v0 += rs.x; v1 += rs.y;
                    }
                    float2 o; o.x = v0; o.y = v1;
                    *(float2*)(Cf + base) = o;
                }
            }
        }
    }
}

// ---------------- attention: fp16 in, fp32 math, fp16 out ----------------
__global__ __launch_bounds__(128) void attn_kernel(
        const __half* __restrict__ q, const __half* __restrict__ k,
        const __half* __restrict__ v, __half* __restrict__ oh) {
    const int b = blockIdx.x / NHEAD;
    const int hh = blockIdx.x % NHEAD;
    __shared__ float ks[MTOK][HDK + 1];
    __shared__ float vs[MTOK][HD + 1];
    __shared__ float qs[4][HDK];
    __shared__ float ps[4][MTOK];
    const int tid = threadIdx.x, w = tid >> 5, lane = tid & 31;
    const __half* kb = k + (size_t)b * MTOK * CNEW + hh * HDK;
    const __half* vb = v + (size_t)b * MTOK * CDIM + hh * HD;
    for (int i = tid; i < MTOK * HDK; i += 128) {
        int m = i / HDK, d = i % HDK;
        ks[m][d] = __half2float(kb[(size_t)m * CNEW + d]);
    }
    for (int i = tid; i < MTOK * HD; i += 128) {
        int m = i / HD, d = i % HD;
        vs[m][d] = __half2float(vb[(size_t)m * CDIM + d]);
    }
    __syncthreads();
    const float scale = rsqrtf(80.0f);
    for (int n = w; n < NTOK; n += 4) {
        const __half* qp = q + ((size_t)(b * NTOK + n)) * CNEW + hh * HDK;
        for (int i = lane; i < HDK; i += 32) qs[w][i] = __half2float(qp[i]);
        __syncwarp();
        float s0 = 0.f, s1 = 0.f;
        #pragma unroll
        for (int d = 0; d < HDK; d++) {
            float qv = qs[w][d];
            s0 = fmaf(qv, ks[lane][d], s0);
            if (lane < MTOK - 32) s1 = fmaf(qv, ks[lane + 32][d], s1);
        }
        s0 *= scale; s1 *= scale;
        float mx = fmaxf(s0, (lane < MTOK - 32) ? s1 : -1e30f);
        #pragma unroll
        for (int off = 16; off; off >>= 1) mx = fmaxf(mx, __shfl_xor_sync(0xffffffffu, mx, off));
        float e0 = expf(s0 - mx);
        float e1 = (lane < MTOK - 32) ? expf(s1 - mx) : 0.f;
        float sm = e0 + e1;
        #pragma unroll
        for (int off = 16; off; off >>= 1) sm += __shfl_xor_sync(0xffffffffu, sm, off);
        float inv = 1.f / sm;
        ps[w][lane] = e0 * inv;
        if (lane < MTOK - 32) ps[w][lane + 32] = e1 * inv;
        __syncwarp();
        float a0 = 0.f, a1 = 0.f;
        #pragma unroll
        for (int m = 0; m < MTOK; m++) {
            float p = ps[w][m];
            a0 = fmaf(p, vs[m][lane], a0);
            a1 = fmaf(p, vs[m][lane + 32], a1);
        }
        size_t o0 = ((size_t)(b * NTOK + n)) * CDIM + hh * HD + lane;
        oh[o0]      = __float2half_rn(a0);
        oh[o0 + 32] = __float2half_rn(a1);
        __syncwarp();
    }
}

// ---------------- host ----------------
static inline int cdiv(int a, int b) { return (a + b - 1) / b; }
#define SMEM_OF(BM, BN) (1024 + 3 * ((BM + BN) * RSTRIDE))

extern "C" void kernel_launch(void* const* d_in, const int* in_sizes, int n_in,
                              void* d_out, int out_size) {
    const float* x_in   = (const float*)d_in[0];
    const float* q_w    = (const float*)d_in[1];
    const float* dw_w   = (const float*)d_in[2];
    const float* dw_b   = (const float*)d_in[3];
    const float* pw_w   = (const float*)d_in[4];
    const float* pw_b   = (const float*)d_in[5];
    const float* lnr_g  = (const float*)d_in[6];
    const float* lnr_b  = (const float*)d_in[7];
    const float* k_w    = (const float*)d_in[8];
    const float* v_w    = (const float*)d_in[9];
    const float* proj_w = (const float*)d_in[10];
    const float* proj_b = (const float*)d_in[11];
    const float* ln1_g  = (const float*)d_in[12];
    const float* ln1_b  = (const float*)d_in[13];
    const float* ln2_g  = (const float*)d_in[14];
    const float* ln2_b  = (const float*)d_in[15];
    const float* fc1_w  = (const float*)d_in[16];
    const float* fc1_b  = (const float*)d_in[17];
    const float* fc2_w  = (const float*)d_in[18];
    const float* fc2_b  = (const float*)d_in[19];

    float* xcur = (float*)d_out;

    float* p_r0;
    __half *p_yh, *p_rch, *p_rh, *p_qh, *p_kh, *p_vh, *p_oh, *p_hh;
    __half *wq, *wpw, *wk, *wv, *wp, *w1, *w2;
    cudaGetSymbolAddress((void**)&p_r0, g_r0);
    cudaGetSymbolAddress((void**)&p_yh, g_yh);   cudaGetSymbolAddress((void**)&p_rch, g_rch);
    cudaGetSymbolAddress((void**)&p_rh, g_rh);
    cudaGetSymbolAddress((void**)&p_qh, g_qh);   cudaGetSymbolAddress((void**)&p_kh, g_kh);
    cudaGetSymbolAddress((void**)&p_vh, g_vh);
    cudaGetSymbolAddress((void**)&p_oh, g_oh);   cudaGetSymbolAddress((void**)&p_hh, g_hh);
    cudaGetSymbolAddress((void**)&wq, g_wq);     cudaGetSymbolAddress((void**)&wpw, g_wpw);
    cudaGetSymbolAddress((void**)&wk, g_wk);     cudaGetSymbolAddress((void**)&wv, g_wv);
    cudaGetSymbolAddress((void**)&wp, g_wp);     cudaGetSymbolAddress((void**)&w1, g_w1);
    cudaGetSymbolAddress((void**)&w2, g_w2);

    cudaFuncSetAttribute(tcmm_kernel<64,64,1>,   cudaFuncAttributeMaxDynamicSharedMemorySize, SMEM_OF(64,64));
    cudaFuncSetAttribute(tcmm_kernel<64,64,4>,   cudaFuncAttributeMaxDynamicSharedMemorySize, SMEM_OF(64,64));
    cudaFuncSetAttribute(tcmm_kernel<64,128,4>,  cudaFuncAttributeMaxDynamicSharedMemorySize, SMEM_OF(64,128));
    cudaFuncSetAttribute(tcmm_kernel<128,64,4>,  cudaFuncAttributeMaxDynamicSharedMemorySize, SMEM_OF(128,64));
    cudaFuncSetAttribute(tcmm_kernel<128,128,2>, cudaFuncAttributeMaxDynamicSharedMemorySize, SMEM_OF(128,128));
    cudaFuncSetAttribute(tcmm_kernel<128,128,3>, cudaFuncAttributeMaxDynamicSharedMemorySize, SMEM_OF(128,128));

    cudaMemcpyAsync(xcur, x_in, (size_t)ROWS_X * CDIM * sizeof(float),
                    cudaMemcpyDeviceToDevice, 0);

    // weight transpose, all layers batched via grid.z
    wsplit_kernel<<<dim3(CNEW/32,   CDIM/32,   LAYERS), 256>>>(q_w,    wq,  CDIM,   CNEW);
    wsplit_kernel<<<dim3(CNEW/32,   CDIM/32,   LAYERS), 256>>>(pw_w,   wpw, CDIM,   CNEW);
    wsplit_kernel<<<dim3(CNEW/32,   CNEW/32,   LAYERS), 256>>>(k_w,    wk,  CNEW,   CNEW);
    wsplit_kernel<<<dim3(CDIM/32,   CNEW/32,   LAYERS), 256>>>(v_w,    wv,  CNEW,   CDIM);
    wsplit_kernel<<<dim3(CDIM/32,   CDIM/32,   LAYERS), 256>>>(proj_w, wp,  CDIM,   CDIM);
    wsplit_kernel<<<dim3(HIDDIM/32, CDIM/32,   LAYERS), 256>>>(fc1_w,  w1,  CDIM,   HIDDIM);
    wsplit_kernel<<<dim3(CDIM/32,   HIDDIM/32, LAYERS), 256>>>(fc2_w,  w2,  HIDDIM, CDIM);

    for (int l = 0; l < LAYERS; l++) {
        // y = LN1(x) -> fp16 only
        ln_kernel<<<ROWS_X, 256>>>(xcur, nullptr, p_yh,
                                   ln1_g + l*CDIM, ln1_b + l*CDIM, CDIM, 1e-6f, 0);
        dwconv_kernel<<<dim3(MTOK, BATCH), 256>>>(p_yh, dw_w + (size_t)l*CDIM*4,
                                                  dw_b + l*CDIM, p_rch);
        // r0 = rconv @ pw + b   (3136 x 960, K=768)
        tcmm_kernel<64,64,1><<<dim3(CNEW/64, ROWS_R/64), 256, SMEM_OF(64,64)>>>(
            p_rch, wpw + (size_t)l*CNEW*CDIM,
            pw_b + l*CNEW, nullptr, p_r0, nullptr, ROWS_R, CNEW, CDIM);
        // r = gelu(LN(r0)) -> fp16
        ln_kernel<<<ROWS_R, 256>>>(p_r0, nullptr, p_rh,
                                   lnr_g + l*CNEW, lnr_b + l*CNEW, CNEW, 1e-5f, 1);
        // q = y @ q_w -> fp16   (12544 x 960, K=768)
        tcmm_kernel<128,64,4><<<dim3(CNEW/64, ROWS_X/128), 256, SMEM_OF(128,64)>>>(
            p_yh, wq + (size_t)l*CNEW*CDIM,
            nullptr, nullptr, nullptr, p_qh, ROWS_X, CNEW, CDIM);
        // k = r @ k_w -> fp16   (3136 x 960, K=960)
        tcmm_kernel<64,64,4><<<dim3(CNEW/64, ROWS_R/64), 256, SMEM_OF(64,64)>>>(
            p_rh, wk + (size_t)l*CNEW*CNEW,
            nullptr, nullptr, nullptr, p_kh, ROWS_R, CNEW, CNEW);
        // v = r @ v_w -> fp16   (3136 x 768, K=960)
        tcmm_kernel<64,128,4><<<dim3(CDIM/128, ROWS_R/64), 256, SMEM_OF(64,128)>>>(
            p_rh, wv + (size_t)l*CDIM*CNEW,
            nullptr, nullptr, nullptr, p_vh, ROWS_R, CDIM, CNEW);
        attn_kernel<<<BATCH*NHEAD, 128>>>(p_qh, p_kh, p_vh, p_oh);
        // x += o @ proj + b     (12544 x 768, K=768)
        tcmm_kernel<128,128,3><<<dim3(CDIM/128, ROWS_X/128), 256, SMEM_OF(128,128)>>>(
            p_oh, wp + (size_t)l*CDIM*CDIM,
            proj_b + l*CDIM, xcur, xcur, nullptr, ROWS_X, CDIM, CDIM);
        // z = LN2(x) -> fp16
        ln_kernel<<<ROWS_X, 256>>>(xcur, nullptr, p_yh,
                                   ln2_g + l*CDIM, ln2_b + l*CDIM, CDIM, 1e-6f, 0);
        // h = gelu(z @ fc1 + b) -> fp16  (12544 x 3072, K=768)
        tcmm_kernel<128,128,2><<<dim3(HIDDIM/128, ROWS_X/128), 256, SMEM_OF(128,128)>>>(
            p_yh, w1 + (size_t)l*HIDDIM*CDIM,
            fc1_b + l*HIDDIM, nullptr, nullptr, p_hh, ROWS_X, HIDDIM, CDIM);
        // x += h @ fc2 + b      (12544 x 768, K=3072)
        tcmm_kernel<128,128,3><<<dim3(CDIM/128, ROWS_X/128), 256, SMEM_OF(128,128)>>>(
            p_hh, w2 + (size_t)l*CDIM*HIDDIM,
            fc2_b + l*CDIM, xcur, xcur, nullptr, ROWS_X, CDIM, HIDDIM);
    }
}

// round 9
// speedup vs baseline: 5.0455x; 1.0465x over previous
#include <cuda_runtime.h>
#include <cuda_fp16.h>
#include <math.h>
#include <stdint.h>

#define LAYERS 4
#define BATCH  64
#define NTOK   196
#define CDIM   768
#define CNEW   960
#define HIDDIM 3072
#define NHEAD  12
#define HD     64
#define HDK    80
#define MTOK   49
#define HW     14
#define ROWS_X (BATCH * NTOK)   // 12544
#define ROWS_R (BATCH * MTOK)   // 3136
#define NKV    (CNEW + CDIM)    // 1728

// ---------------- scratch ----------------
__device__ float g_r0[ROWS_R * CNEW];
__device__ __align__(16) __half g_yh[ROWS_X * CDIM];
__device__ __align__(16) __half g_rch[ROWS_R * CDIM];
__device__ __align__(16) __half g_rh[ROWS_R * CNEW];
__device__ __align__(16) __half g_qh[ROWS_X * CNEW];
__device__ __align__(16) __half g_kh[ROWS_R * CNEW];
__device__ __align__(16) __half g_vh[ROWS_R * CDIM];
__device__ __align__(16) __half g_oh[ROWS_X * CDIM];
__device__ __align__(16) __half g_hh[ROWS_X * HIDDIM];

// transposed weights, [N][K] K-major fp16
__device__ __align__(16) __half g_wq [LAYERS*CNEW*CDIM];
__device__ __align__(16) __half g_wpw[LAYERS*CNEW*CDIM];
__device__ __align__(16) __half g_wkv[LAYERS*NKV*CNEW];
__device__ __align__(16) __half g_wp [LAYERS*CDIM*CDIM];
__device__ __align__(16) __half g_w1 [LAYERS*HIDDIM*CDIM];
__device__ __align__(16) __half g_w2 [LAYERS*CDIM*HIDDIM];

// ---------------- helpers ----------------
__device__ __forceinline__ uint32_t smem_u32(const void* p) {
    uint32_t a;
    asm("{ .reg .u64 t; cvta.to.shared.u64 t, %1; cvt.u32.u64 %0, t; }" : "=r"(a) : "l"(p));
    return a;
}
__device__ __forceinline__ void cp16(uint32_t dst, const void* src) {
    asm volatile("cp.async.cg.shared.global [%0], [%1], 16;" :: "r"(dst), "l"(src));
}
__device__ __forceinline__ void cp_commit() { asm volatile("cp.async.commit_group;" ::: "memory"); }
template <int N> __device__ __forceinline__ void cp_wait() {
    asm volatile("cp.async.wait_group %0;" :: "n"(N) : "memory");
}
__device__ __forceinline__ void ldsm_x4(uint32_t (&r)[4], uint32_t addr) {
    asm volatile("ldmatrix.sync.aligned.m8n8.x4.shared.b16 {%0,%1,%2,%3}, [%4];"
        : "=r"(r[0]), "=r"(r[1]), "=r"(r[2]), "=r"(r[3]) : "r"(addr));
}
__device__ __forceinline__ void mma16816(float (&d)[4], const uint32_t (&a)[4],
                                         uint32_t b0, uint32_t b1) {
    asm volatile("mma.sync.aligned.m16n8k16.row.col.f32.f16.f16.f32 "
        "{%0,%1,%2,%3}, {%4,%5,%6,%7}, {%8,%9}, {%0,%1,%2,%3};"
        : "+f"(d[0]), "+f"(d[1]), "+f"(d[2]), "+f"(d[3])
        : "r"(a[0]), "r"(a[1]), "r"(a[2]), "r"(a[3]), "r"(b0), "r"(b1));
}
__device__ __forceinline__ float gelu_exact(float x) {
    return 0.5f * x * (1.0f + erff(x * 0.7071067811865476f));
}

// ---------------- weight transpose -> fp16 (z = layer) ----------------
__global__ __launch_bounds__(256) void wsplit_kernel(
        const float* __restrict__ W, __half* __restrict__ T, int K, int N,
        size_t dstStride) {
    const float* Wl = W + (size_t)blockIdx.z * K * N;
    __half* Tl = T + (size_t)blockIdx.z * dstStride;
    __shared__ float t[32][33];
    const int n0 = blockIdx.x * 32, k0 = blockIdx.y * 32;
    const int tx = threadIdx.x & 31, ty = threadIdx.x >> 5;
    #pragma unroll
    for (int i = 0; i < 4; i++) {
        int k = ty + i * 8;
        t[k][tx] = Wl[(size_t)(k0 + k) * N + n0 + tx];
    }
    __syncthreads();
    #pragma unroll
    for (int i = 0; i < 4; i++) {
        int n = ty + i * 8;
        Tl[(size_t)(n0 + n) * K + k0 + tx] = __float2half_rn(t[tx][n]);
    }
}

// ---------------- LayerNorm (+gelu), warp-per-row, fp16 out ----------------
__global__ __launch_bounds__(256) void ln_kernel(
        const float* __restrict__ in, __half* __restrict__ oh,
        const float* __restrict__ gamma, const float* __restrict__ beta,
        int W, float eps, int do_gelu, int rows) {
    const int w = threadIdx.x >> 5, lane = threadIdx.x & 31;
    const int row = blockIdx.x * 8 + w;
    if (row >= rows) return;
    const float2* p = (const float2*)(in + (size_t)row * W);
    const int W2 = W >> 1;
    float s = 0.f, ss = 0.f;
    for (int j = lane; j < W2; j += 32) {
        float2 v = p[j];
        s += v.x + v.y;
        ss += v.x * v.x + v.y * v.y;
    }
    #pragma unroll
    for (int off = 16; off; off >>= 1) {
        s  += __shfl_xor_sync(0xffffffffu, s, off);
        ss += __shfl_xor_sync(0xffffffffu, ss, off);
    }
    const float mean = s / (float)W;
    const float var  = ss / (float)W - mean * mean;
    const float inv  = rsqrtf(var + eps);
    const float2* g2 = (const float2*)gamma;
    const float2* b2 = (const float2*)beta;
    __half2* o2 = (__half2*)(oh + (size_t)row * W);
    for (int j = lane; j < W2; j += 32) {
        float2 v = p[j], g = g2[j], b = b2[j];
        float v0 = (v.x - mean) * inv * g.x + b.x;
        float v1 = (v.y - mean) * inv * g.y + b.y;
        if (do_gelu) { v0 = gelu_exact(v0); v1 = gelu_exact(v1); }
        __half2 hp; hp.x = __float2half_rn(v0); hp.y = __float2half_rn(v1);
        o2[j] = hp;
    }
}

// ---------------- depthwise 2x2/s2 conv, fp16 in -> fp16 out ----------------
__global__ void dwconv_kernel(const __half* __restrict__ y,
                              const float* __restrict__ w4, const float* __restrict__ bias,
                              __half* __restrict__ oh) {
    const int m = blockIdx.x, b = blockIdx.y;
    const int h7 = m / 7, w7 = m % 7;
    const int p00 = (h7 * 2) * HW + w7 * 2;
    const __half* yb = y + (size_t)b * NTOK * CDIM;
    const size_t ob = ((size_t)b * MTOK + m) * CDIM;
    for (int c = threadIdx.x; c < CDIM; c += blockDim.x) {
        float acc = __half2float(yb[(size_t)(p00         ) * CDIM + c]) * w4[c * 4 + 0]
                  + __half2float(yb[(size_t)(p00 + 1     ) * CDIM + c]) * w4[c * 4 + 1]
                  + __half2float(yb[(size_t)(p00 + HW    ) * CDIM + c]) * w4[c * 4 + 2]
                  + __half2float(yb[(size_t)(p00 + HW + 1) * CDIM + c]) * w4[c * 4 + 3]
                  + bias[c];
        oh[ob + c] = __float2half_rn(acc);
    }
}

// ---------------------------------------------------------------------------
// fp16 GEMM on HMMA: C = A[M,K] @ B[N,K]^T
// CTA tile BM x BN, BK=64, 3-stage cp.async pipeline, RSTRIDE=144 (conflict-free).
// EPI: 1 +bias fp32, 2 +bias+gelu fp16, 3 +bias+resid fp32, 4 plain fp16,
//      5 fp16 split kv (cols < CNEW -> Ch stride CNEW, else Ch2 stride CDIM)
// ---------------------------------------------------------------------------
#define RSTRIDE 144

template <int BM, int BN, int EPI>
__global__ __launch_bounds__(256, 2) void tcmm_kernel(
        const __half* __restrict__ A, const __half* __restrict__ B,
        const float* __restrict__ bias, const float* __restrict__ resid,
        float* __restrict__ Cf, __half* __restrict__ Ch, __half* __restrict__ Ch2,
        int M, int N, int K) {
    constexpr int SS = (BM + BN) * RSTRIDE;      // stage bytes
    constexpr int WN_WARPS = (BM == 128) ? 2 : 4;
    constexpr int WN   = BN / WN_WARPS;
    constexpr int WN8  = WN / 8;
    constexpr int WN16 = WN / 16;
    extern __shared__ char smem[];
    const int tid = threadIdx.x, lane = tid & 31, wid = tid >> 5;
    const int wn = wid % WN_WARPS, wm = wid / WN_WARPS;
    const int row0 = blockIdx.y * BM, col0 = blockIdx.x * BN;
    const uint32_t tiles = (smem_u32(smem) + 1023) & ~1023u;

    float acc[2][WN8][4];
    #pragma unroll
    for (int a = 0; a < 2; a++)
        #pragma unroll
        for (int b = 0; b < WN8; b++)
            #pragma unroll
            for (int c = 0; c < 4; c++) acc[a][b][c] = 0.f;

    const int NC = K >> 6;   // BK = 64

    auto load_chunk = [&](int stage, int k0) {
        uint32_t sd = tiles + stage * SS;
        #pragma unroll
        for (int i = 0; i < BM * 8 / 256; i++) {     // A: BM rows x 128B
            int idx = tid + i * 256;
            int row = idx >> 3, cc = idx & 7;
            int grow = row0 + row; if (grow > M - 1) grow = M - 1;
            cp16(sd + row * RSTRIDE + cc * 16, A + (size_t)grow * K + k0 + cc * 8);
        }
        #pragma unroll
        for (int i = 0; i < BN * 8 / 256; i++) {     // B: BN rows x 128B
            int idx = tid + i * 256;
            int row = idx >> 3, cc = idx & 7;
            cp16(sd + BM * RSTRIDE + row * RSTRIDE + cc * 16,
                 B + (size_t)(col0 + row) * K + k0 + cc * 8);
        }
    };

    load_chunk(0, 0);  cp_commit();
    load_chunk(1, 64); cp_commit();

    for (int c = 0; c < NC; c++) {
        if (c + 2 < NC) cp_wait<1>(); else cp_wait<0>();
        __syncthreads();
        if (c + 2 < NC) { load_chunk((c + 2) % 3, (c + 2) * 64); cp_commit(); }

        const uint32_t sA = tiles + (c % 3) * SS;
        const uint32_t sB = sA + BM * RSTRIDE;
        #pragma unroll
        for (int ks = 0; ks < 4; ks++) {
            uint32_t ah[2][4];
            #pragma unroll
            for (int mt = 0; mt < 2; mt++) {
                uint32_t r = sA + (wm * 32 + mt * 16 + (lane & 15)) * RSTRIDE
                           + (2 * ks + (lane >> 4)) * 16;
                ldsm_x4(ah[mt], r);
            }
            uint32_t bh[WN16][4];
            #pragma unroll
            for (int g = 0; g < WN16; g++) {
                int rrow = wn * WN + g * 16 + (lane & 7) + ((lane >> 4) << 3);
                uint32_t r = sB + rrow * RSTRIDE + (2 * ks + ((lane >> 3) & 1)) * 16;
                ldsm_x4(bh[g], r);
            }
            #pragma unroll
            for (int mt = 0; mt < 2; mt++)
                #pragma unroll
                for (int g = 0; g < WN16; g++) {
                    mma16816(acc[mt][2*g],   ah[mt], bh[g][0], bh[g][1]);
                    mma16816(acc[mt][2*g+1], ah[mt], bh[g][2], bh[g][3]);
                }
        }
    }

    // epilogue
    const int er = lane >> 2, ec = (lane & 3) * 2;
    #pragma unroll
    for (int mt = 0; mt < 2; mt++) {
        #pragma unroll
        for (int g = 0; g < WN8; g++) {
            const int gn = col0 + wn * WN + g * 8 + ec;
            #pragma unroll
            for (int hrow = 0; hrow < 2; hrow++) {
                const int gm = row0 + wm * 32 + mt * 16 + er + hrow * 8;
                if (gm >= M) continue;
                float v0 = acc[mt][g][2 * hrow];
                float v1 = acc[mt][g][2 * hrow + 1];
                if constexpr (EPI == 1 || EPI == 2 || EPI == 3) {
                    v0 += bias[gn]; v1 += bias[gn + 1];
                }
                if constexpr (EPI == 2) { v0 = gelu_exact(v0); v1 = gelu_exact(v1); }
                if constexpr (EPI == 2 || EPI == 4) {
                    __half2 hp; hp.x = __float2half_rn(v0); hp.y = __float2half_rn(v1);
                    *(__half2*)(Ch + (size_t)gm * N + gn) = hp;
                } else if constexpr (EPI == 5) {
                    __half2 hp; hp.x = __float2half_rn(v0); hp.y = __float2half_rn(v1);
                    if (gn < CNEW) *(__half2*)(Ch  + (size_t)gm * CNEW + gn) = hp;
                    else           *(__half2*)(Ch2 + (size_t)gm * CDIM + gn - CNEW) = hp;
                } else {
                    const size_t base = (size_t)gm * N + gn;
                    if constexpr (EPI == 3) {
                        float2 rs = *(const float2*)(resid + base);
                        v0 += rs.x; v1 += rs.y;
                    }
                    float2 o; o.x = v0; o.y = v1;
                    *(float2*)(Cf + base) = o;
                }
            }
        }
    }
}

// ---------------- attention: fp16 in, fp32 math, fp16 out, 256 thr ----------------
__global__ __launch_bounds__(256) void attn_kernel(
        const __half* __restrict__ q, const __half* __restrict__ k,
        const __half* __restrict__ v, __half* __restrict__ oh) {
    const int b = blockIdx.x / NHEAD;
    const int hh = blockIdx.x % NHEAD;
    __shared__ float ks[MTOK][HDK + 1];
    __shared__ float vs[MTOK][HD + 1];
    __shared__ float qs[8][HDK];
    __shared__ float ps[8][MTOK];
    const int tid = threadIdx.x, w = tid >> 5, lane = tid & 31;
    const __half* kb = k + (size_t)b * MTOK * CNEW + hh * HDK;
    const __half* vb = v + (size_t)b * MTOK * CDIM + hh * HD;
    for (int i = tid; i < MTOK * HDK; i += 256) {
        int m = i / HDK, d = i % HDK;
        ks[m][d] = __half2float(kb[(size_t)m * CNEW + d]);
    }
    for (int i = tid; i < MTOK * HD; i += 256) {
        int m = i / HD, d = i % HD;
        vs[m][d] = __half2float(vb[(size_t)m * CDIM + d]);
    }
    __syncthreads();
    const float scale = rsqrtf(80.0f);
    for (int n = w; n < NTOK; n += 8) {
        const __half* qp = q + ((size_t)(b * NTOK + n)) * CNEW + hh * HDK;
        for (int i = lane; i < HDK; i += 32) qs[w][i] = __half2float(qp[i]);
        __syncwarp();
        float s0 = 0.f, s1 = 0.f;
        #pragma unroll
        for (int d = 0; d < HDK; d++) {
            float qv = qs[w][d];
            s0 = fmaf(qv, ks[lane][d], s0);
            if (lane < MTOK - 32) s1 = fmaf(qv, ks[lane + 32][d], s1);
        }
        s0 *= scale; s1 *= scale;
        float mx = fmaxf(s0, (lane < MTOK - 32) ? s1 : -1e30f);
        #pragma unroll
        for (int off = 16; off; off >>= 1) mx = fmaxf(mx, __shfl_xor_sync(0xffffffffu, mx, off));
        float e0 = expf(s0 - mx);
        float e1 = (lane < MTOK - 32) ? expf(s1 - mx) : 0.f;
        float sm = e0 + e1;
        #pragma unroll
        for (int off = 16; off; off >>= 1) sm += __shfl_xor_sync(0xffffffffu, sm, off);
        float inv = 1.f / sm;
        ps[w][lane] = e0 * inv;
        if (lane < MTOK - 32) ps[w][lane + 32] = e1 * inv;
        __syncwarp();
        float a0 = 0.f, a1 = 0.f;
        #pragma unroll
        for (int m = 0; m < MTOK; m++) {
            float p = ps[w][m];
            a0 = fmaf(p, vs[m][lane], a0);
            a1 = fmaf(p, vs[m][lane + 32], a1);
        }
        size_t o0 = ((size_t)(b * NTOK + n)) * CDIM + hh * HD + lane;
        oh[o0]      = __float2half_rn(a0);
        oh[o0 + 32] = __float2half_rn(a1);
        __syncwarp();
    }
}

// ---------------- host ----------------
static inline int cdiv(int a, int b) { return (a + b - 1) / b; }
#define SMEM_OF(BM, BN) (1024 + 3 * ((BM + BN) * RSTRIDE))

extern "C" void kernel_launch(void* const* d_in, const int* in_sizes, int n_in,
                              void* d_out, int out_size) {
    const float* x_in   = (const float*)d_in[0];
    const float* q_w    = (const float*)d_in[1];
    const float* dw_w   = (const float*)d_in[2];
    const float* dw_b   = (const float*)d_in[3];
    const float* pw_w   = (const float*)d_in[4];
    const float* pw_b   = (const float*)d_in[5];
    const float* lnr_g  = (const float*)d_in[6];
    const float* lnr_b  = (const float*)d_in[7];
    const float* k_w    = (const float*)d_in[8];
    const float* v_w    = (const float*)d_in[9];
    const float* proj_w = (const float*)d_in[10];
    const float* proj_b = (const float*)d_in[11];
    const float* ln1_g  = (const float*)d_in[12];
    const float* ln1_b  = (const float*)d_in[13];
    const float* ln2_g  = (const float*)d_in[14];
    const float* ln2_b  = (const float*)d_in[15];
    const float* fc1_w  = (const float*)d_in[16];
    const float* fc1_b  = (const float*)d_in[17];
    const float* fc2_w  = (const float*)d_in[18];
    const float* fc2_b  = (const float*)d_in[19];

    float* xcur = (float*)d_out;

    float* p_r0;
    __half *p_yh, *p_rch, *p_rh, *p_qh, *p_kh, *p_vh, *p_oh, *p_hh;
    __half *wq, *wpw, *wkv, *wp, *w1, *w2;
    cudaGetSymbolAddress((void**)&p_r0, g_r0);
    cudaGetSymbolAddress((void**)&p_yh, g_yh);   cudaGetSymbolAddress((void**)&p_rch, g_rch);
    cudaGetSymbolAddress((void**)&p_rh, g_rh);
    cudaGetSymbolAddress((void**)&p_qh, g_qh);   cudaGetSymbolAddress((void**)&p_kh, g_kh);
    cudaGetSymbolAddress((void**)&p_vh, g_vh);
    cudaGetSymbolAddress((void**)&p_oh, g_oh);   cudaGetSymbolAddress((void**)&p_hh, g_hh);
    cudaGetSymbolAddress((void**)&wq, g_wq);     cudaGetSymbolAddress((void**)&wpw, g_wpw);
    cudaGetSymbolAddress((void**)&wkv, g_wkv);
    cudaGetSymbolAddress((void**)&wp, g_wp);     cudaGetSymbolAddress((void**)&w1, g_w1);
    cudaGetSymbolAddress((void**)&w2, g_w2);

    cudaFuncSetAttribute(tcmm_kernel<64,64,1>,   cudaFuncAttributeMaxDynamicSharedMemorySize, SMEM_OF(64,64));
    cudaFuncSetAttribute(tcmm_kernel<64,64,5>,   cudaFuncAttributeMaxDynamicSharedMemorySize, SMEM_OF(64,64));
    cudaFuncSetAttribute(tcmm_kernel<128,64,4>,  cudaFuncAttributeMaxDynamicSharedMemorySize, SMEM_OF(128,64));
    cudaFuncSetAttribute(tcmm_kernel<128,128,2>, cudaFuncAttributeMaxDynamicSharedMemorySize, SMEM_OF(128,128));
    cudaFuncSetAttribute(tcmm_kernel<128,128,3>, cudaFuncAttributeMaxDynamicSharedMemorySize, SMEM_OF(128,128));

    cudaMemcpyAsync(xcur, x_in, (size_t)ROWS_X * CDIM * sizeof(float),
                    cudaMemcpyDeviceToDevice, 0);

    // weight transpose, all layers batched via grid.z
    wsplit_kernel<<<dim3(CNEW/32,   CDIM/32,   LAYERS), 256>>>(q_w,    wq,  CDIM,   CNEW, (size_t)CDIM*CNEW);
    wsplit_kernel<<<dim3(CNEW/32,   CDIM/32,   LAYERS), 256>>>(pw_w,   wpw, CDIM,   CNEW, (size_t)CDIM*CNEW);
    wsplit_kernel<<<dim3(CNEW/32,   CNEW/32,   LAYERS), 256>>>(k_w,    wkv, CNEW,   CNEW, (size_t)NKV*CNEW);
    wsplit_kernel<<<dim3(CDIM/32,   CNEW/32,   LAYERS), 256>>>(v_w,    wkv + (size_t)CNEW*CNEW,
                                                               CNEW,   CDIM, (size_t)NKV*CNEW);
    wsplit_kernel<<<dim3(CDIM/32,   CDIM/32,   LAYERS), 256>>>(proj_w, wp,  CDIM,   CDIM, (size_t)CDIM*CDIM);
    wsplit_kernel<<<dim3(HIDDIM/32, CDIM/32,   LAYERS), 256>>>(fc1_w,  w1,  CDIM,   HIDDIM, (size_t)CDIM*HIDDIM);
    wsplit_kernel<<<dim3(CDIM/32,   HIDDIM/32, LAYERS), 256>>>(fc2_w,  w2,  HIDDIM, CDIM, (size_t)HIDDIM*CDIM);

    for (int l = 0; l < LAYERS; l++) {
        // y = LN1(x) -> fp16
        ln_kernel<<<cdiv(ROWS_X,8), 256>>>(xcur, p_yh,
            ln1_g + l*CDIM, ln1_b + l*CDIM, CDIM, 1e-6f, 0, ROWS_X);
        dwconv_kernel<<<dim3(MTOK, BATCH), 256>>>(p_yh, dw_w + (size_t)l*CDIM*4,
                                                  dw_b + l*CDIM, p_rch);
        // r0 = rconv @ pw + b   (3136 x 960, K=768)
        tcmm_kernel<64,64,1><<<dim3(CNEW/64, ROWS_R/64), 256, SMEM_OF(64,64)>>>(
            p_rch, wpw + (size_t)l*CNEW*CDIM,
            pw_b + l*CNEW, nullptr, p_r0, nullptr, nullptr, ROWS_R, CNEW, CDIM);
        // r = gelu(LN(r0)) -> fp16
        ln_kernel<<<cdiv(ROWS_R,8), 256>>>(p_r0, p_rh,
            lnr_g + l*CNEW, lnr_b + l*CNEW, CNEW, 1e-5f, 1, ROWS_R);
        // q = y @ q_w -> fp16   (12544 x 960, K=768)
        tcmm_kernel<128,64,4><<<dim3(CNEW/64, ROWS_X/128), 256, SMEM_OF(128,64)>>>(
            p_yh, wq + (size_t)l*CNEW*CDIM,
            nullptr, nullptr, nullptr, p_qh, nullptr, ROWS_X, CNEW, CDIM);
        // k|v = r @ [k_w; v_w] -> fp16 split   (3136 x 1728, K=960)
        tcmm_kernel<64,64,5><<<dim3(NKV/64, ROWS_R/64), 256, SMEM_OF(64,64)>>>(
            p_rh, wkv + (size_t)l*NKV*CNEW,
            nullptr, nullptr, nullptr, p_kh, p_vh, ROWS_R, NKV, CNEW);
        attn_kernel<<<BATCH*NHEAD, 256>>>(p_qh, p_kh, p_vh, p_oh);
        // x += o @ proj + b     (12544 x 768, K=768)
        tcmm_kernel<128,128,3><<<dim3(CDIM/128, ROWS_X/128), 256, SMEM_OF(128,128)>>>(
            p_oh, wp + (size_t)l*CDIM*CDIM,
            proj_b + l*CDIM, xcur, xcur, nullptr, nullptr, ROWS_X, CDIM, CDIM);
        // z = LN2(x) -> fp16
        ln_kernel<<<cdiv(ROWS_X,8), 256>>>(xcur, p_yh,
            ln2_g + l*CDIM, ln2_b + l*CDIM, CDIM, 1e-6f, 0, ROWS_X);
        // h = gelu(z @ fc1 + b) -> fp16  (12544 x 3072, K=768)
        tcmm_kernel<128,128,2><<<dim3(HIDDIM/128, ROWS_X/128), 256, SMEM_OF(128,128)>>>(
            p_yh, w1 + (size_t)l*HIDDIM*CDIM,
            fc1_b + l*HIDDIM, nullptr, nullptr, p_hh, nullptr, ROWS_X, HIDDIM, CDIM);
        // x += h @ fc2 + b      (12544 x 768, K=3072)
        tcmm_kernel<128,128,3><<<dim3(CDIM/128, ROWS_X/128), 256, SMEM_OF(128,128)>>>(
            p_hh, w2 + (size_t)l*CDIM*HIDDIM,
            fc2_b + l*CDIM, xcur, xcur, nullptr, nullptr, ROWS_X, CDIM, HIDDIM);
    }
}

// round 11
// speedup vs baseline: 5.1417x; 1.0191x over previous
#include <cuda_runtime.h>
#include <cuda_fp16.h>
#include <math.h>
#include <stdint.h>

#define LAYERS 4
#define BATCH  64
#define NTOK   196
#define CDIM   768
#define CNEW   960
#define HIDDIM 3072
#define NHEAD  12
#define HD     64
#define HDK    80
#define MTOK   49
#define HW     14
#define ROWS_X (BATCH * NTOK)   // 12544
#define ROWS_R (BATCH * MTOK)   // 3136
#define NKV    (CNEW + CDIM)    // 1728

// ---------------- scratch ----------------
__device__ float g_r0[ROWS_R * CNEW];
__device__ __align__(16) __half g_yh[ROWS_X * CDIM];
__device__ __align__(16) __half g_rch[ROWS_R * CDIM];
__device__ __align__(16) __half g_rh[ROWS_R * CNEW];
__device__ __align__(16) __half g_qh[ROWS_X * CNEW];
__device__ __align__(16) __half g_kh[ROWS_R * CNEW];
__device__ __align__(16) __half g_vh[ROWS_R * CDIM];
__device__ __align__(16) __half g_oh[ROWS_X * CDIM];
__device__ __align__(16) __half g_hh[ROWS_X * HIDDIM];

// transposed weights, [N][K] K-major fp16
__device__ __align__(16) __half g_wq [LAYERS*CNEW*CDIM];
__device__ __align__(16) __half g_wpw[LAYERS*CNEW*CDIM];
__device__ __align__(16) __half g_wkv[LAYERS*NKV*CNEW];
__device__ __align__(16) __half g_wp [LAYERS*CDIM*CDIM];
__device__ __align__(16) __half g_w1 [LAYERS*HIDDIM*CDIM];
__device__ __align__(16) __half g_w2 [LAYERS*CDIM*HIDDIM];

// ---------------- helpers ----------------
__device__ __forceinline__ uint32_t smem_u32(const void* p) {
    uint32_t a;
    asm("{ .reg .u64 t; cvta.to.shared.u64 t, %1; cvt.u32.u64 %0, t; }" : "=r"(a) : "l"(p));
    return a;
}
__device__ __forceinline__ void cp16(uint32_t dst, const void* src) {
    asm volatile("cp.async.cg.shared.global [%0], [%1], 16;" :: "r"(dst), "l"(src));
}
__device__ __forceinline__ void cp_commit() { asm volatile("cp.async.commit_group;" ::: "memory"); }
template <int N> __device__ __forceinline__ void cp_wait() {
    asm volatile("cp.async.wait_group %0;" :: "n"(N) : "memory");
}
__device__ __forceinline__ void ldsm_x4(uint32_t (&r)[4], uint32_t addr) {
    asm volatile("ldmatrix.sync.aligned.m8n8.x4.shared.b16 {%0,%1,%2,%3}, [%4];"
        : "=r"(r[0]), "=r"(r[1]), "=r"(r[2]), "=r"(r[3]) : "r"(addr));
}
__device__ __forceinline__ void mma16816(float (&d)[4], const uint32_t (&a)[4],
                                         uint32_t b0, uint32_t b1) {
    asm volatile("mma.sync.aligned.m16n8k16.row.col.f32.f16.f16.f32 "
        "{%0,%1,%2,%3}, {%4,%5,%6,%7}, {%8,%9}, {%0,%1,%2,%3};"
        : "+f"(d[0]), "+f"(d[1]), "+f"(d[2]), "+f"(d[3])
        : "r"(a[0]), "r"(a[1]), "r"(a[2]), "r"(a[3]), "r"(b0), "r"(b1));
}
__device__ __forceinline__ float gelu_exact(float x) {
    return 0.5f * x * (1.0f + erff(x * 0.7071067811865476f));
}

// ---------------- weight transpose -> fp16 (z = layer) ----------------
__global__ __launch_bounds__(256) void wsplit_kernel(
        const float* __restrict__ W, __half* __restrict__ T, int K, int N,
        size_t dstStride) {
    const float* Wl = W + (size_t)blockIdx.z * K * N;
    __half* Tl = T + (size_t)blockIdx.z * dstStride;
    __shared__ float t[32][33];
    const int n0 = blockIdx.x * 32, k0 = blockIdx.y * 32;
    const int tx = threadIdx.x & 31, ty = threadIdx.x >> 5;
    #pragma unroll
    for (int i = 0; i < 4; i++) {
        int k = ty + i * 8;
        t[k][tx] = Wl[(size_t)(k0 + k) * N + n0 + tx];
    }
    __syncthreads();
    #pragma unroll
    for (int i = 0; i < 4; i++) {
        int n = ty + i * 8;
        Tl[(size_t)(n0 + n) * K + k0 + tx] = __float2half_rn(t[tx][n]);
    }
}

// ---------------- LayerNorm (+gelu), warp-per-row, fp16 out ----------------
__global__ __launch_bounds__(256) void ln_kernel(
        const float* __restrict__ in, __half* __restrict__ oh,
        const float* __restrict__ gamma, const float* __restrict__ beta,
        int W, float eps, int do_gelu, int rows) {
    const int w = threadIdx.x >> 5, lane = threadIdx.x & 31;
    const int row = blockIdx.x * 8 + w;
    if (row >= rows) return;
    const float2* p = (const float2*)(in + (size_t)row * W);
    const int W2 = W >> 1;
    float s = 0.f, ss = 0.f;
    for (int j = lane; j < W2; j += 32) {
        float2 v = p[j];
        s += v.x + v.y;
        ss += v.x * v.x + v.y * v.y;
    }
    #pragma unroll
    for (int off = 16; off; off >>= 1) {
        s  += __shfl_xor_sync(0xffffffffu, s, off);
        ss += __shfl_xor_sync(0xffffffffu, ss, off);
    }
    const float mean = s / (float)W;
    const float var  = ss / (float)W - mean * mean;
    const float inv  = rsqrtf(var + eps);
    const float2* g2 = (const float2*)gamma;
    const float2* b2 = (const float2*)beta;
    __half2* o2 = (__half2*)(oh + (size_t)row * W);
    for (int j = lane; j < W2; j += 32) {
        float2 v = p[j], g = g2[j], b = b2[j];
        float v0 = (v.x - mean) * inv * g.x + b.x;
        float v1 = (v.y - mean) * inv * g.y + b.y;
        if (do_gelu) { v0 = gelu_exact(v0); v1 = gelu_exact(v1); }
        __half2 hp; hp.x = __float2half_rn(v0); hp.y = __float2half_rn(v1);
        o2[j] = hp;
    }
}

// ---------------- depthwise 2x2/s2 conv, fp16 in -> fp16 out ----------------
__global__ void dwconv_kernel(const __half* __restrict__ y,
                              const float* __restrict__ w4, const float* __restrict__ bias,
                              __half* __restrict__ oh) {
    const int m = blockIdx.x, b = blockIdx.y;
    const int h7 = m / 7, w7 = m % 7;
    const int p00 = (h7 * 2) * HW + w7 * 2;
    const __half* yb = y + (size_t)b * NTOK * CDIM;
    const size_t ob = ((size_t)b * MTOK + m) * CDIM;
    for (int c = threadIdx.x; c < CDIM; c += blockDim.x) {
        float acc = __half2float(yb[(size_t)(p00         ) * CDIM + c]) * w4[c * 4 + 0]
                  + __half2float(yb[(size_t)(p00 + 1     ) * CDIM + c]) * w4[c * 4 + 1]
                  + __half2float(yb[(size_t)(p00 + HW    ) * CDIM + c]) * w4[c * 4 + 2]
                  + __half2float(yb[(size_t)(p00 + HW + 1) * CDIM + c]) * w4[c * 4 + 3]
                  + bias[c];
        oh[ob + c] = __float2half_rn(acc);
    }
}

// ---------------------------------------------------------------------------
// fp16 GEMM on HMMA: C = A[M,K] @ B[N,K]^T
// CTA tile BM x BN, warp grid NM x NN (each warp covers 32 x BN/NN),
// BK=64, 3-stage cp.async pipeline, RSTRIDE=144 (conflict-free ldmatrix).
// EPI: 1 +bias fp32, 2 +bias+gelu fp16, 3 +bias+resid fp32, 4 plain fp16,
//      5 fp16 split kv (cols < CNEW -> Ch stride CNEW, else Ch2 stride CDIM)
// ---------------------------------------------------------------------------
#define RSTRIDE 144

template <int BM, int BN, int NM, int NN, int EPI>
__global__ __launch_bounds__(32*NM*NN, 512/(32*NM*NN)) void tcmm_kernel(
        const __half* __restrict__ A, const __half* __restrict__ B,
        const float* __restrict__ bias, const float* __restrict__ resid,
        float* __restrict__ Cf, __half* __restrict__ Ch, __half* __restrict__ Ch2,
        int M, int N, int K) {
    constexpr int NT   = 32 * NM * NN;
    constexpr int SS   = (BM + BN) * RSTRIDE;    // stage bytes
    constexpr int WN   = BN / NN;
    constexpr int WN8  = WN / 8;
    constexpr int WN16 = WN / 16;
    static_assert(BM / NM == 32, "each warp covers 32 rows (2 mt tiles)");
    extern __shared__ char smem[];
    const int tid = threadIdx.x, lane = tid & 31, wid = tid >> 5;
    const int wn = wid % NN, wm = wid / NN;
    const int row0 = blockIdx.y * BM, col0 = blockIdx.x * BN;
    const uint32_t tiles = (smem_u32(smem) + 1023) & ~1023u;

    float acc[2][WN8][4];
    #pragma unroll
    for (int a = 0; a < 2; a++)
        #pragma unroll
        for (int b = 0; b < WN8; b++)
            #pragma unroll
            for (int c = 0; c < 4; c++) acc[a][b][c] = 0.f;

    const int NC = K >> 6;   // BK = 64

    auto load_chunk = [&](int stage, int k0) {
        uint32_t sd = tiles + stage * SS;
        #pragma unroll
        for (int i = 0; i < BM * 8 / NT; i++) {      // A: BM rows x 128B
            int idx = tid + i * NT;
            int row = idx >> 3, cc = idx & 7;
            int grow = row0 + row; if (grow > M - 1) grow = M - 1;
            cp16(sd + row * RSTRIDE + cc * 16, A + (size_t)grow * K + k0 + cc * 8);
        }
        #pragma unroll
        for (int i = 0; i < BN * 8 / NT; i++) {      // B: BN rows x 128B
            int idx = tid + i * NT;
            int row = idx >> 3, cc = idx & 7;
            cp16(sd + BM * RSTRIDE + row * RSTRIDE + cc * 16,
                 B + (size_t)(col0 + row) * K + k0 + cc * 8);
        }
    };

    load_chunk(0, 0);  cp_commit();
    load_chunk(1, 64); cp_commit();

    for (int c = 0; c < NC; c++) {
        if (c + 2 < NC) cp_wait<1>(); else cp_wait<0>();
        __syncthreads();
        if (c + 2 < NC) { load_chunk((c + 2) % 3, (c + 2) * 64); cp_commit(); }

        const uint32_t sA = tiles + (c % 3) * SS;
        const uint32_t sB = sA + BM * RSTRIDE;
        #pragma unroll
        for (int ks = 0; ks < 4; ks++) {
            uint32_t ah[2][4];
            #pragma unroll
            for (int mt = 0; mt < 2; mt++) {
                uint32_t r = sA + (wm * 32 + mt * 16 + (lane & 15)) * RSTRIDE
                           + (2 * ks + (lane >> 4)) * 16;
                ldsm_x4(ah[mt], r);
            }
            uint32_t bh[WN16][4];
            #pragma unroll
            for (int g = 0; g < WN16; g++) {
                int rrow = wn * WN + g * 16 + (lane & 7) + ((lane >> 4) << 3);
                uint32_t r = sB + rrow * RSTRIDE + (2 * ks + ((lane >> 3) & 1)) * 16;
                ldsm_x4(bh[g], r);
            }
            #pragma unroll
            for (int mt = 0; mt < 2; mt++)
                #pragma unroll
                for (int g = 0; g < WN16; g++) {
                    mma16816(acc[mt][2*g],   ah[mt], bh[g][0], bh[g][1]);
                    mma16816(acc[mt][2*g+1], ah[mt], bh[g][2], bh[g][3]);
                }
        }
    }

    // epilogue
    const int er = lane >> 2, ec = (lane & 3) * 2;
    #pragma unroll
    for (int mt = 0; mt < 2; mt++) {
        #pragma unroll
        for (int g = 0; g < WN8; g++) {
            const int gn = col0 + wn * WN + g * 8 + ec;
            #pragma unroll
            for (int hrow = 0; hrow < 2; hrow++) {
                const int gm = row0 + wm * 32 + mt * 16 + er + hrow * 8;
                if (gm >= M) continue;
                float v0 = acc[mt][g][2 * hrow];
                float v1 = acc[mt][g][2 * hrow + 1];
                if constexpr (EPI == 1 || EPI == 2 || EPI == 3) {
                    v0 += bias[gn]; v1 += bias[gn + 1];
                }
                if constexpr (EPI == 2) { v0 = gelu_exact(v0); v1 = gelu_exact(v1); }
                if constexpr (EPI == 2 || EPI == 4) {
                    __half2 hp; hp.x = __float2half_rn(v0); hp.y = __float2half_rn(v1);
                    *(__half2*)(Ch + (size_t)gm * N + gn) = hp;
                } else if constexpr (EPI == 5) {
                    __half2 hp; hp.x = __float2half_rn(v0); hp.y = __float2half_rn(v1);
                    if (gn < CNEW) *(__half2*)(Ch  + (size_t)gm * CNEW + gn) = hp;
                    else           *(__half2*)(Ch2 + (size_t)gm * CDIM + gn - CNEW) = hp;
                } else {
                    const size_t base = (size_t)gm * N + gn;
                    if constexpr (EPI == 3) {
                        float2 rs = *(const float2*)(resid + base);
                        v0 += rs.x; v1 += rs.y;
                    }
                    float2 o; o.x = v0; o.y = v1;
                    *(float2*)(Cf + base) = o;
                }
            }
        }
    }
}

// ---------------- attention: fp16 in, fp32 math, fp16 out, 256 thr ----------------
__global__ __launch_bounds__(256) void attn_kernel(
        const __half* __restrict__ q, const __half* __restrict__ k,
        const __half* __restrict__ v, __half* __restrict__ oh) {
    const int b = blockIdx.x / NHEAD;
    const int hh = blockIdx.x % NHEAD;
    __shared__ float ks[MTOK][HDK + 1];
    __shared__ float vs[MTOK][HD + 1];
    __shared__ float qs[8][HDK];
    __shared__ float ps[8][MTOK];
    const int tid = threadIdx.x, w = tid >> 5, lane = tid & 31;
    const __half* kb = k + (size_t)b * MTOK * CNEW + hh * HDK;
    const __half* vb = v + (size_t)b * MTOK * CDIM + hh * HD;
    for (int i = tid; i < MTOK * HDK; i += 256) {
        int m = i / HDK, d = i % HDK;
        ks[m][d] = __half2float(kb[(size_t)m * CNEW + d]);
    }
    for (int i = tid; i < MTOK * HD; i += 256) {
        int m = i / HD, d = i % HD;
        vs[m][d] = __half2float(vb[(size_t)m * CDIM + d]);
    }
    __syncthreads();
    const float scale = rsqrtf(80.0f);
    for (int n = w; n < NTOK; n += 8) {
        const __half* qp = q + ((size_t)(b * NTOK + n)) * CNEW + hh * HDK;
        for (int i = lane; i < HDK; i += 32) qs[w][i] = __half2float(qp[i]);
        __syncwarp();
        float s0 = 0.f, s1 = 0.f;
        #pragma unroll
        for (int d = 0; d < HDK; d++) {
            float qv = qs[w][d];
            s0 = fmaf(qv, ks[lane][d], s0);
            if (lane < MTOK - 32) s1 = fmaf(qv, ks[lane + 32][d], s1);
        }
        s0 *= scale; s1 *= scale;
        float mx = fmaxf(s0, (lane < MTOK - 32) ? s1 : -1e30f);
        #pragma unroll
        for (int off = 16; off; off >>= 1) mx = fmaxf(mx, __shfl_xor_sync(0xffffffffu, mx, off));
        float e0 = expf(s0 - mx);
        float e1 = (lane < MTOK - 32) ? expf(s1 - mx) : 0.f;
        float sm = e0 + e1;
        #pragma unroll
        for (int off = 16; off; off >>= 1) sm += __shfl_xor_sync(0xffffffffu, sm, off);
        float inv = 1.f / sm;
        ps[w][lane] = e0 * inv;
        if (lane < MTOK - 32) ps[w][lane + 32] = e1 * inv;
        __syncwarp();
        float a0 = 0.f, a1 = 0.f;
        #pragma unroll
        for (int m = 0; m < MTOK; m++) {
            float p = ps[w][m];
            a0 = fmaf(p, vs[m][lane], a0);
            a1 = fmaf(p, vs[m][lane + 32], a1);
        }
        size_t o0 = ((size_t)(b * NTOK + n)) * CDIM + hh * HD + lane;
        oh[o0]      = __float2half_rn(a0);
        oh[o0 + 32] = __float2half_rn(a1);
        __syncwarp();
    }
}

// ---------------- host ----------------
static inline int cdiv(int a, int b) { return (a + b - 1) / b; }
#define SMEM_OF(BM, BN) (1024 + 3 * ((BM + BN) * RSTRIDE))

extern "C" void kernel_launch(void* const* d_in, const int* in_sizes, int n_in,
                              void* d_out, int out_size) {
    const float* x_in   = (const float*)d_in[0];
    const float* q_w    = (const float*)d_in[1];
    const float* dw_w   = (const float*)d_in[2];
    const float* dw_b   = (const float*)d_in[3];
    const float* pw_w   = (const float*)d_in[4];
    const float* pw_b   = (const float*)d_in[5];
    const float* lnr_g  = (const float*)d_in[6];
    const float* lnr_b  = (const float*)d_in[7];
    const float* k_w    = (const float*)d_in[8];
    const float* v_w    = (const float*)d_in[9];
    const float* proj_w = (const float*)d_in[10];
    const float* proj_b = (const float*)d_in[11];
    const float* ln1_g  = (const float*)d_in[12];
    const float* ln1_b  = (const float*)d_in[13];
    const float* ln2_g  = (const float*)d_in[14];
    const float* ln2_b  = (const float*)d_in[15];
    const float* fc1_w  = (const float*)d_in[16];
    const float* fc1_b  = (const float*)d_in[17];
    const float* fc2_w  = (const float*)d_in[18];
    const float* fc2_b  = (const float*)d_in[19];

    float* xcur = (float*)d_out;

    float* p_r0;
    __half *p_yh, *p_rch, *p_rh, *p_qh, *p_kh, *p_vh, *p_oh, *p_hh;
    __half *wq, *wpw, *wkv, *wp, *w1, *w2;
    cudaGetSymbolAddress((void**)&p_r0, g_r0);
    cudaGetSymbolAddress((void**)&p_yh, g_yh);   cudaGetSymbolAddress((void**)&p_rch, g_rch);
    cudaGetSymbolAddress((void**)&p_rh, g_rh);
    cudaGetSymbolAddress((void**)&p_qh, g_qh);   cudaGetSymbolAddress((void**)&p_kh, g_kh);
    cudaGetSymbolAddress((void**)&p_vh, g_vh);
    cudaGetSymbolAddress((void**)&p_oh, g_oh);   cudaGetSymbolAddress((void**)&p_hh, g_hh);
    cudaGetSymbolAddress((void**)&wq, g_wq);     cudaGetSymbolAddress((void**)&wpw, g_wpw);
    cudaGetSymbolAddress((void**)&wkv, g_wkv);
    cudaGetSymbolAddress((void**)&wp, g_wp);     cudaGetSymbolAddress((void**)&w1, g_w1);
    cudaGetSymbolAddress((void**)&w2, g_w2);

    cudaFuncSetAttribute(tcmm_kernel<64,64,2,2,1>,    cudaFuncAttributeMaxDynamicSharedMemorySize, SMEM_OF(64,64));
    cudaFuncSetAttribute(tcmm_kernel<64,64,2,2,5>,    cudaFuncAttributeMaxDynamicSharedMemorySize, SMEM_OF(64,64));
    cudaFuncSetAttribute(tcmm_kernel<128,64,4,2,4>,   cudaFuncAttributeMaxDynamicSharedMemorySize, SMEM_OF(128,64));
    cudaFuncSetAttribute(tcmm_kernel<128,128,4,2,2>,  cudaFuncAttributeMaxDynamicSharedMemorySize, SMEM_OF(128,128));
    cudaFuncSetAttribute(tcmm_kernel<128,128,4,2,3>,  cudaFuncAttributeMaxDynamicSharedMemorySize, SMEM_OF(128,128));

    // weight transpose, all layers batched via grid.z
    wsplit_kernel<<<dim3(CNEW/32,   CDIM/32,   LAYERS), 256>>>(q_w,    wq,  CDIM,   CNEW, (size_t)CDIM*CNEW);
    wsplit_kernel<<<dim3(CNEW/32,   CDIM/32,   LAYERS), 256>>>(pw_w,   wpw, CDIM,   CNEW, (size_t)CDIM*CNEW);
    wsplit_kernel<<<dim3(CNEW/32,   CNEW/32,   LAYERS), 256>>>(k_w,    wkv, CNEW,   CNEW, (size_t)NKV*CNEW);
    wsplit_kernel<<<dim3(CDIM/32,   CNEW/32,   LAYERS), 256>>>(v_w,    wkv + (size_t)CNEW*CNEW,
                                                               CNEW,   CDIM, (size_t)NKV*CNEW);
    wsplit_kernel<<<dim3(CDIM/32,   CDIM/32,   LAYERS), 256>>>(proj_w, wp,  CDIM,   CDIM, (size_t)CDIM*CDIM);
    wsplit_kernel<<<dim3(HIDDIM/32, CDIM/32,   LAYERS), 256>>>(fc1_w,  w1,  CDIM,   HIDDIM, (size_t)CDIM*HIDDIM);
    wsplit_kernel<<<dim3(CDIM/32,   HIDDIM/32, LAYERS), 256>>>(fc2_w,  w2,  HIDDIM, CDIM, (size_t)HIDDIM*CDIM);

    for (int l = 0; l < LAYERS; l++) {
        const float* xin = (l == 0) ? x_in : xcur;   // layer 0 reads harness input
        // y = LN1(x) -> fp16
        ln_kernel<<<cdiv(ROWS_X,8), 256>>>(xin, p_yh,
            ln1_g + l*CDIM, ln1_b + l*CDIM, CDIM, 1e-6f, 0, ROWS_X);
        dwconv_kernel<<<dim3(MTOK, BATCH), 256>>>(p_yh, dw_w + (size_t)l*CDIM*4,
                                                  dw_b + l*CDIM, p_rch);
        // r0 = rconv @ pw + b   (3136 x 960, K=768)
        tcmm_kernel<64,64,2,2,1><<<dim3(CNEW/64, ROWS_R/64), 128, SMEM_OF(64,64)>>>(
            p_rch, wpw + (size_t)l*CNEW*CDIM,
            pw_b + l*CNEW, nullptr, p_r0, nullptr, nullptr, ROWS_R, CNEW, CDIM);
        // r = gelu(LN(r0)) -> fp16
        ln_kernel<<<cdiv(ROWS_R,8), 256>>>(p_r0, p_rh,
            lnr_g + l*CNEW, lnr_b + l*CNEW, CNEW, 1e-5f, 1, ROWS_R);
        // q = y @ q_w -> fp16   (12544 x 960, K=768)
        tcmm_kernel<128,64,4,2,4><<<dim3(CNEW/64, ROWS_X/128), 256, SMEM_OF(128,64)>>>(
            p_yh, wq + (size_t)l*CNEW*CDIM,
            nullptr, nullptr, nullptr, p_qh, nullptr, ROWS_X, CNEW, CDIM);
        // k|v = r @ [k_w; v_w] -> fp16 split   (3136 x 1728, K=960)
        tcmm_kernel<64,64,2,2,5><<<dim3(NKV/64, ROWS_R/64), 128, SMEM_OF(64,64)>>>(
            p_rh, wkv + (size_t)l*NKV*CNEW,
            nullptr, nullptr, nullptr, p_kh, p_vh, ROWS_R, NKV, CNEW);
        attn_kernel<<<BATCH*NHEAD, 256>>>(p_qh, p_kh, p_vh, p_oh);
        // x(out) = resid + o @ proj + b   (12544 x 768, K=768)
        tcmm_kernel<128,128,4,2,3><<<dim3(CDIM/128, ROWS_X/128), 256, SMEM_OF(128,128)>>>(
            p_oh, wp + (size_t)l*CDIM*CDIM,
            proj_b + l*CDIM, xin, xcur, nullptr, nullptr, ROWS_X, CDIM, CDIM);
        // z = LN2(x) -> fp16
        ln_kernel<<<cdiv(ROWS_X,8), 256>>>(xcur, p_yh,
            ln2_g + l*CDIM, ln2_b + l*CDIM, CDIM, 1e-6f, 0, ROWS_X);
        // h = gelu(z @ fc1 + b) -> fp16  (12544 x 3072, K=768)
        tcmm_kernel<128,128,4,2,2><<<dim3(HIDDIM/128, ROWS_X/128), 256, SMEM_OF(128,128)>>>(
            p_yh, w1 + (size_t)l*HIDDIM*CDIM,
            fc1_b + l*HIDDIM, nullptr, nullptr, p_hh, nullptr, ROWS_X, HIDDIM, CDIM);
        // x += h @ fc2 + b      (12544 x 768, K=3072)
        tcmm_kernel<128,128,4,2,3><<<dim3(CDIM/128, ROWS_X/128), 256, SMEM_OF(128,128)>>>(
            p_hh, w2 + (size_t)l*CDIM*HIDDIM,
            fc2_b + l*CDIM, xcur, xcur, nullptr, nullptr, ROWS_X, CDIM, HIDDIM);
    }
}

// round 12
// speedup vs baseline: 5.1513x; 1.0019x over previous
#include <cuda_runtime.h>
#include <cuda_fp16.h>
#include <math.h>
#include <stdint.h>

#define LAYERS 4
#define BATCH  64
#define NTOK   196
#define CDIM   768
#define CNEW   960
#define HIDDIM 3072
#define NHEAD  12
#define HD     64
#define HDK    80
#define MTOK   49
#define HW     14
#define ROWS_X (BATCH * NTOK)   // 12544
#define ROWS_R (BATCH * MTOK)   // 3136
#define NKV    (CNEW + CDIM)    // 1728

// ---------------- scratch ----------------
__device__ float g_r0[ROWS_R * CNEW];
__device__ __align__(16) __half g_yh[ROWS_X * CDIM];
__device__ __align__(16) __half g_rch[ROWS_R * CDIM];
__device__ __align__(16) __half g_rh[ROWS_R * CNEW];
__device__ __align__(16) __half g_qh[ROWS_X * CNEW];
__device__ __align__(16) __half g_kh[ROWS_R * CNEW];
__device__ __align__(16) __half g_vh[ROWS_R * CDIM];
__device__ __align__(16) __half g_oh[ROWS_X * CDIM];
__device__ __align__(16) __half g_hh[ROWS_X * HIDDIM];

// transposed weights, [N][K] K-major fp16
__device__ __align__(16) __half g_wq [LAYERS*CNEW*CDIM];
__device__ __align__(16) __half g_wpw[LAYERS*CNEW*CDIM];
__device__ __align__(16) __half g_wkv[LAYERS*NKV*CNEW];
__device__ __align__(16) __half g_wp [LAYERS*CDIM*CDIM];
__device__ __align__(16) __half g_w1 [LAYERS*HIDDIM*CDIM];
__device__ __align__(16) __half g_w2 [LAYERS*CDIM*HIDDIM];

// ---------------- helpers ----------------
__device__ __forceinline__ uint32_t smem_u32(const void* p) {
    uint32_t a;
    asm("{ .reg .u64 t; cvta.to.shared.u64 t, %1; cvt.u32.u64 %0, t; }" : "=r"(a) : "l"(p));
    return a;
}
__device__ __forceinline__ void cp16(uint32_t dst, const void* src) {
    asm volatile("cp.async.cg.shared.global [%0], [%1], 16;" :: "r"(dst), "l"(src));
}
__device__ __forceinline__ void cp_commit() { asm volatile("cp.async.commit_group;" ::: "memory"); }
template <int N> __device__ __forceinline__ void cp_wait() {
    asm volatile("cp.async.wait_group %0;" :: "n"(N) : "memory");
}
__device__ __forceinline__ void ldsm_x4(uint32_t (&r)[4], uint32_t addr) {
    asm volatile("ldmatrix.sync.aligned.m8n8.x4.shared.b16 {%0,%1,%2,%3}, [%4];"
        : "=r"(r[0]), "=r"(r[1]), "=r"(r[2]), "=r"(r[3]) : "r"(addr));
}
__device__ __forceinline__ void mma16816(float (&d)[4], const uint32_t (&a)[4],
                                         uint32_t b0, uint32_t b1) {
    asm volatile("mma.sync.aligned.m16n8k16.row.col.f32.f16.f16.f32 "
        "{%0,%1,%2,%3}, {%4,%5,%6,%7}, {%8,%9}, {%0,%1,%2,%3};"
        : "+f"(d[0]), "+f"(d[1]), "+f"(d[2]), "+f"(d[3])
        : "r"(a[0]), "r"(a[1]), "r"(a[2]), "r"(a[3]), "r"(b0), "r"(b1));
}
__device__ __forceinline__ float gelu_exact(float x) {
    return 0.5f * x * (1.0f + erff(x * 0.7071067811865476f));
}

// ---------------- weight transpose -> fp16 (z = layer) ----------------
__global__ __launch_bounds__(256) void wsplit_kernel(
        const float* __restrict__ W, __half* __restrict__ T, int K, int N,
        size_t dstStride) {
    const float* Wl = W + (size_t)blockIdx.z * K * N;
    __half* Tl = T + (size_t)blockIdx.z * dstStride;
    __shared__ float t[32][33];
    const int n0 = blockIdx.x * 32, k0 = blockIdx.y * 32;
    const int tx = threadIdx.x & 31, ty = threadIdx.x >> 5;
    #pragma unroll
    for (int i = 0; i < 4; i++) {
        int k = ty + i * 8;
        t[k][tx] = Wl[(size_t)(k0 + k) * N + n0 + tx];
    }
    __syncthreads();
    #pragma unroll
    for (int i = 0; i < 4; i++) {
        int n = ty + i * 8;
        Tl[(size_t)(n0 + n) * K + k0 + tx] = __float2half_rn(t[tx][n]);
    }
}

// ---------------- LayerNorm (+gelu), warp-per-row, fp16 out ----------------
__global__ __launch_bounds__(256) void ln_kernel(
        const float* __restrict__ in, __half* __restrict__ oh,
        const float* __restrict__ gamma, const float* __restrict__ beta,
        int W, float eps, int do_gelu, int rows) {
    const int w = threadIdx.x >> 5, lane = threadIdx.x & 31;
    const int row = blockIdx.x * 8 + w;
    if (row >= rows) return;
    const float2* p = (const float2*)(in + (size_t)row * W);
    const int W2 = W >> 1;
    float s = 0.f, ss = 0.f;
    for (int j = lane; j < W2; j += 32) {
        float2 v = p[j];
        s += v.x + v.y;
        ss += v.x * v.x + v.y * v.y;
    }
    #pragma unroll
    for (int off = 16; off; off >>= 1) {
        s  += __shfl_xor_sync(0xffffffffu, s, off);
        ss += __shfl_xor_sync(0xffffffffu, ss, off);
    }
    const float mean = s / (float)W;
    const float var  = ss / (float)W - mean * mean;
    const float inv  = rsqrtf(var + eps);
    const float2* g2 = (const float2*)gamma;
    const float2* b2 = (const float2*)beta;
    __half2* o2 = (__half2*)(oh + (size_t)row * W);
    for (int j = lane; j < W2; j += 32) {
        float2 v = p[j], g = g2[j], b = b2[j];
        float v0 = (v.x - mean) * inv * g.x + b.x;
        float v1 = (v.y - mean) * inv * g.y + b.y;
        if (do_gelu) { v0 = gelu_exact(v0); v1 = gelu_exact(v1); }
        __half2 hp; hp.x = __float2half_rn(v0); hp.y = __float2half_rn(v1);
        o2[j] = hp;
    }
}

// ---------------- depthwise 2x2/s2 conv, fp16 in -> fp16 out ----------------
__global__ void dwconv_kernel(const __half* __restrict__ y,
                              const float* __restrict__ w4, const float* __restrict__ bias,
                              __half* __restrict__ oh) {
    const int m = blockIdx.x, b = blockIdx.y;
    const int h7 = m / 7, w7 = m % 7;
    const int p00 = (h7 * 2) * HW + w7 * 2;
    const __half* yb = y + (size_t)b * NTOK * CDIM;
    const size_t ob = ((size_t)b * MTOK + m) * CDIM;
    for (int c = threadIdx.x; c < CDIM; c += blockDim.x) {
        float acc = __half2float(yb[(size_t)(p00         ) * CDIM + c]) * w4[c * 4 + 0]
                  + __half2float(yb[(size_t)(p00 + 1     ) * CDIM + c]) * w4[c * 4 + 1]
                  + __half2float(yb[(size_t)(p00 + HW    ) * CDIM + c]) * w4[c * 4 + 2]
                  + __half2float(yb[(size_t)(p00 + HW + 1) * CDIM + c]) * w4[c * 4 + 3]
                  + bias[c];
        oh[ob + c] = __float2half_rn(acc);
    }
}

// ---------------------------------------------------------------------------
// fp16 GEMM on HMMA: C = A[M,K] @ B[N,K]^T
// CTA tile BM x BN, warp grid NM x NN, BK=64, 3-stage cp.async pipeline,
// RSTRIDE=144 (conflict-free ldmatrix).
// EPI: 1 +bias fp32, 2 +bias+gelu fp16, 3 +bias+resid fp32, 4 plain fp16,
//      5 fp16 split kv (cols < CNEW -> Ch stride CNEW, else Ch2 stride CDIM)
// ---------------------------------------------------------------------------
#define RSTRIDE 144

template <int BM, int BN, int NM, int NN, int EPI>
__global__ __launch_bounds__(32*NM*NN, 512/(32*NM*NN)) void tcmm_kernel(
        const __half* __restrict__ A, const __half* __restrict__ B,
        const float* __restrict__ bias, const float* __restrict__ resid,
        float* __restrict__ Cf, __half* __restrict__ Ch, __half* __restrict__ Ch2,
        int M, int N, int K) {
    constexpr int NT   = 32 * NM * NN;
    constexpr int SS   = (BM + BN) * RSTRIDE;    // stage bytes
    constexpr int WN   = BN / NN;
    constexpr int WN8  = WN / 8;
    constexpr int WN16 = WN / 16;
    static_assert(BM / NM == 32, "each warp covers 32 rows (2 mt tiles)");
    extern __shared__ char smem[];
    const int tid = threadIdx.x, lane = tid & 31, wid = tid >> 5;
    const int wn = wid % NN, wm = wid / NN;
    const int row0 = blockIdx.y * BM, col0 = blockIdx.x * BN;
    const uint32_t tiles = (smem_u32(smem) + 1023) & ~1023u;

    float acc[2][WN8][4];
    #pragma unroll
    for (int a = 0; a < 2; a++)
        #pragma unroll
        for (int b = 0; b < WN8; b++)
            #pragma unroll
            for (int c = 0; c < 4; c++) acc[a][b][c] = 0.f;

    const int NC = K >> 6;   // BK = 64

    auto load_chunk = [&](int stage, int k0) {
        uint32_t sd = tiles + stage * SS;
        #pragma unroll
        for (int i = 0; i < BM * 8 / NT; i++) {      // A: BM rows x 128B
            int idx = tid + i * NT;
            int row = idx >> 3, cc = idx & 7;
            int grow = row0 + row; if (grow > M - 1) grow = M - 1;
            cp16(sd + row * RSTRIDE + cc * 16, A + (size_t)grow * K + k0 + cc * 8);
        }
        #pragma unroll
        for (int i = 0; i < BN * 8 / NT; i++) {      // B: BN rows x 128B
            int idx = tid + i * NT;
            int row = idx >> 3, cc = idx & 7;
            cp16(sd + BM * RSTRIDE + row * RSTRIDE + cc * 16,
                 B + (size_t)(col0 + row) * K + k0 + cc * 8);
        }
    };

    load_chunk(0, 0);  cp_commit();
    load_chunk(1, 64); cp_commit();

    for (int c = 0; c < NC; c++) {
        if (c + 2 < NC) cp_wait<1>(); else cp_wait<0>();
        __syncthreads();
        if (c + 2 < NC) { load_chunk((c + 2) % 3, (c + 2) * 64); cp_commit(); }

        const uint32_t sA = tiles + (c % 3) * SS;
        const uint32_t sB = sA + BM * RSTRIDE;
        #pragma unroll
        for (int ks = 0; ks < 4; ks++) {
            uint32_t ah[2][4];
            #pragma unroll
            for (int mt = 0; mt < 2; mt++) {
                uint32_t r = sA + (wm * 32 + mt * 16 + (lane & 15)) * RSTRIDE
                           + (2 * ks + (lane >> 4)) * 16;
                ldsm_x4(ah[mt], r);
            }
            uint32_t bh[WN16][4];
            #pragma unroll
            for (int g = 0; g < WN16; g++) {
                int rrow = wn * WN + g * 16 + (lane & 7) + ((lane >> 4) << 3);
                uint32_t r = sB + rrow * RSTRIDE + (2 * ks + ((lane >> 3) & 1)) * 16;
                ldsm_x4(bh[g], r);
            }
            #pragma unroll
            for (int mt = 0; mt < 2; mt++)
                #pragma unroll
                for (int g = 0; g < WN16; g++) {
                    mma16816(acc[mt][2*g],   ah[mt], bh[g][0], bh[g][1]);
                    mma16816(acc[mt][2*g+1], ah[mt], bh[g][2], bh[g][3]);
                }
        }
    }

    // epilogue
    const int er = lane >> 2, ec = (lane & 3) * 2;
    #pragma unroll
    for (int mt = 0; mt < 2; mt++) {
        #pragma unroll
        for (int g = 0; g < WN8; g++) {
            const int gn = col0 + wn * WN + g * 8 + ec;
            #pragma unroll
            for (int hrow = 0; hrow < 2; hrow++) {
                const int gm = row0 + wm * 32 + mt * 16 + er + hrow * 8;
                if (gm >= M) continue;
                float v0 = acc[mt][g][2 * hrow];
                float v1 = acc[mt][g][2 * hrow + 1];
                if constexpr (EPI == 1 || EPI == 2 || EPI == 3) {
                    v0 += bias[gn]; v1 += bias[gn + 1];
                }
                if constexpr (EPI == 2) { v0 = gelu_exact(v0); v1 = gelu_exact(v1); }
                if constexpr (EPI == 2 || EPI == 4) {
                    __half2 hp; hp.x = __float2half_rn(v0); hp.y = __float2half_rn(v1);
                    *(__half2*)(Ch + (size_t)gm * N + gn) = hp;
                } else if constexpr (EPI == 5) {
                    __half2 hp; hp.x = __float2half_rn(v0); hp.y = __float2half_rn(v1);
                    if (gn < CNEW) *(__half2*)(Ch  + (size_t)gm * CNEW + gn) = hp;
                    else           *(__half2*)(Ch2 + (size_t)gm * CDIM + gn - CNEW) = hp;
                } else {
                    const size_t base = (size_t)gm * N + gn;
                    if constexpr (EPI == 3) {
                        float2 rs = *(const float2*)(resid + base);
                        v0 += rs.x; v1 += rs.y;
                    }
                    float2 o; o.x = v0; o.y = v1;
                    *(float2*)(Cf + base) = o;
                }
            }
        }
    }
}

// ---------------- attention: fp16 in, fp32 math, fp16 out, 256 thr ----------------
__global__ __launch_bounds__(256) void attn_kernel(
        const __half* __restrict__ q, const __half* __restrict__ k,
        const __half* __restrict__ v, __half* __restrict__ oh) {
    const int b = blockIdx.x / NHEAD;
    const int hh = blockIdx.x % NHEAD;
    __shared__ float ks[MTOK][HDK + 1];
    __shared__ float vs[MTOK][HD + 1];
    __shared__ float qs[8][HDK];
    __shared__ float ps[8][MTOK];
    const int tid = threadIdx.x, w = tid >> 5, lane = tid & 31;
    const __half* kb = k + (size_t)b * MTOK * CNEW + hh * HDK;
    const __half* vb = v + (size_t)b * MTOK * CDIM + hh * HD;
    for (int i = tid; i < MTOK * HDK; i += 256) {
        int m = i / HDK, d = i % HDK;
        ks[m][d] = __half2float(kb[(size_t)m * CNEW + d]);
    }
    for (int i = tid; i < MTOK * HD; i += 256) {
        int m = i / HD, d = i % HD;
        vs[m][d] = __half2float(vb[(size_t)m * CDIM + d]);
    }
    __syncthreads();
    const float scale = rsqrtf(80.0f);
    for (int n = w; n < NTOK; n += 8) {
        const __half* qp = q + ((size_t)(b * NTOK + n)) * CNEW + hh * HDK;
        for (int i = lane; i < HDK; i += 32) qs[w][i] = __half2float(qp[i]);
        __syncwarp();
        float s0 = 0.f, s1 = 0.f;
        #pragma unroll
        for (int d = 0; d < HDK; d++) {
            float qv = qs[w][d];
            s0 = fmaf(qv, ks[lane][d], s0);
            if (lane < MTOK - 32) s1 = fmaf(qv, ks[lane + 32][d], s1);
        }
        s0 *= scale; s1 *= scale;
        float mx = fmaxf(s0, (lane < MTOK - 32) ? s1 : -1e30f);
        #pragma unroll
        for (int off = 16; off; off >>= 1) mx = fmaxf(mx, __shfl_xor_sync(0xffffffffu, mx, off));
        float e0 = expf(s0 - mx);
        float e1 = (lane < MTOK - 32) ? expf(s1 - mx) : 0.f;
        float sm = e0 + e1;
        #pragma unroll
        for (int off = 16; off; off >>= 1) sm += __shfl_xor_sync(0xffffffffu, sm, off);
        float inv = 1.f / sm;
        ps[w][lane] = e0 * inv;
        if (lane < MTOK - 32) ps[w][lane + 32] = e1 * inv;
        __syncwarp();
        float a0 = 0.f, a1 = 0.f;
        #pragma unroll
        for (int m = 0; m < MTOK; m++) {
            float p = ps[w][m];
            a0 = fmaf(p, vs[m][lane], a0);
            a1 = fmaf(p, vs[m][lane + 32], a1);
        }
        size_t o0 = ((size_t)(b * NTOK + n)) * CDIM + hh * HD + lane;
        oh[o0]      = __float2half_rn(a0);
        oh[o0 + 32] = __float2half_rn(a1);
        __syncwarp();
    }
}

// ---------------- host ----------------
static inline int cdiv(int a, int b) { return (a + b - 1) / b; }
#define SMEM_OF(BM, BN) (1024 + 3 * ((BM + BN) * RSTRIDE))

extern "C" void kernel_launch(void* const* d_in, const int* in_sizes, int n_in,
                              void* d_out, int out_size) {
    const float* x_in   = (const float*)d_in[0];
    const float* q_w    = (const float*)d_in[1];
    const float* dw_w   = (const float*)d_in[2];
    const float* dw_b   = (const float*)d_in[3];
    const float* pw_w   = (const float*)d_in[4];
    const float* pw_b   = (const float*)d_in[5];
    const float* lnr_g  = (const float*)d_in[6];
    const float* lnr_b  = (const float*)d_in[7];
    const float* k_w    = (const float*)d_in[8];
    const float* v_w    = (const float*)d_in[9];
    const float* proj_w = (const float*)d_in[10];
    const float* proj_b = (const float*)d_in[11];
    const float* ln1_g  = (const float*)d_in[12];
    const float* ln1_b  = (const float*)d_in[13];
    const float* ln2_g  = (const float*)d_in[14];
    const float* ln2_b  = (const float*)d_in[15];
    const float* fc1_w  = (const float*)d_in[16];
    const float* fc1_b  = (const float*)d_in[17];
    const float* fc2_w  = (const float*)d_in[18];
    const float* fc2_b  = (const float*)d_in[19];

    float* xcur = (float*)d_out;

    float* p_r0;
    __half *p_yh, *p_rch, *p_rh, *p_qh, *p_kh, *p_vh, *p_oh, *p_hh;
    __half *wq, *wpw, *wkv, *wp, *w1, *w2;
    cudaGetSymbolAddress((void**)&p_r0, g_r0);
    cudaGetSymbolAddress((void**)&p_yh, g_yh);   cudaGetSymbolAddress((void**)&p_rch, g_rch);
    cudaGetSymbolAddress((void**)&p_rh, g_rh);
    cudaGetSymbolAddress((void**)&p_qh, g_qh);   cudaGetSymbolAddress((void**)&p_kh, g_kh);
    cudaGetSymbolAddress((void**)&p_vh, g_vh);
    cudaGetSymbolAddress((void**)&p_oh, g_oh);   cudaGetSymbolAddress((void**)&p_hh, g_hh);
    cudaGetSymbolAddress((void**)&wq, g_wq);     cudaGetSymbolAddress((void**)&wpw, g_wpw);
    cudaGetSymbolAddress((void**)&wkv, g_wkv);
    cudaGetSymbolAddress((void**)&wp, g_wp);     cudaGetSymbolAddress((void**)&w1, g_w1);
    cudaGetSymbolAddress((void**)&w2, g_w2);

    cudaFuncSetAttribute(tcmm_kernel<64,64,2,2,1>,    cudaFuncAttributeMaxDynamicSharedMemorySize, SMEM_OF(64,64));
    cudaFuncSetAttribute(tcmm_kernel<64,64,2,2,5>,    cudaFuncAttributeMaxDynamicSharedMemorySize, SMEM_OF(64,64));
    cudaFuncSetAttribute(tcmm_kernel<128,64,4,2,4>,   cudaFuncAttributeMaxDynamicSharedMemorySize, SMEM_OF(128,64));
    cudaFuncSetAttribute(tcmm_kernel<128,128,4,2,2>,  cudaFuncAttributeMaxDynamicSharedMemorySize, SMEM_OF(128,128));
    cudaFuncSetAttribute(tcmm_kernel<128,128,4,2,3>,  cudaFuncAttributeMaxDynamicSharedMemorySize, SMEM_OF(128,128));

    // side stream + fork/join events (host-side resources only; created per
    // call and intentionally not destroyed — kernel_launch runs only a few
    // times outside the timed graph replay)
    cudaStream_t s1;
    cudaStreamCreateWithFlags(&s1, cudaStreamNonBlocking);
    cudaEvent_t evFork, evJoin;
    cudaEventCreateWithFlags(&evFork, cudaEventDisableTiming);
    cudaEventCreateWithFlags(&evJoin, cudaEventDisableTiming);

    // weight transpose, all layers batched via grid.z
    wsplit_kernel<<<dim3(CNEW/32,   CDIM/32,   LAYERS), 256>>>(q_w,    wq,  CDIM,   CNEW, (size_t)CDIM*CNEW);
    wsplit_kernel<<<dim3(CNEW/32,   CDIM/32,   LAYERS), 256>>>(pw_w,   wpw, CDIM,   CNEW, (size_t)CDIM*CNEW);
    wsplit_kernel<<<dim3(CNEW/32,   CNEW/32,   LAYERS), 256>>>(k_w,    wkv, CNEW,   CNEW, (size_t)NKV*CNEW);
    wsplit_kernel<<<dim3(CDIM/32,   CNEW/32,   LAYERS), 256>>>(v_w,    wkv + (size_t)CNEW*CNEW,
                                                               CNEW,   CDIM, (size_t)NKV*CNEW);
    wsplit_kernel<<<dim3(CDIM/32,   CDIM/32,   LAYERS), 256>>>(proj_w, wp,  CDIM,   CDIM, (size_t)CDIM*CDIM);
    wsplit_kernel<<<dim3(HIDDIM/32, CDIM/32,   LAYERS), 256>>>(fc1_w,  w1,  CDIM,   HIDDIM, (size_t)CDIM*HIDDIM);
    wsplit_kernel<<<dim3(CDIM/32,   HIDDIM/32, LAYERS), 256>>>(fc2_w,  w2,  HIDDIM, CDIM, (size_t)HIDDIM*CDIM);

    for (int l = 0; l < LAYERS; l++) {
        const float* xin = (l == 0) ? x_in : xcur;   // layer 0 reads harness input
        // y = LN1(x) -> fp16
        ln_kernel<<<cdiv(ROWS_X,8), 256>>>(xin, p_yh,
            ln1_g + l*CDIM, ln1_b + l*CDIM, CDIM, 1e-6f, 0, ROWS_X);

        // ---- fork: reduction branch on s1, q GEMM on main stream ----
        cudaEventRecord(evFork, 0);
        cudaStreamWaitEvent(s1, evFork, 0);

        dwconv_kernel<<<dim3(MTOK, BATCH), 256, 0, s1>>>(p_yh, dw_w + (size_t)l*CDIM*4,
                                                         dw_b + l*CDIM, p_rch);
        // r0 = rconv @ pw + b   (3136 x 960, K=768)
        tcmm_kernel<64,64,2,2,1><<<dim3(CNEW/64, ROWS_R/64), 128, SMEM_OF(64,64), s1>>>(
            p_rch, wpw + (size_t)l*CNEW*CDIM,
            pw_b + l*CNEW, nullptr, p_r0, nullptr, nullptr, ROWS_R, CNEW, CDIM);
        // r = gelu(LN(r0)) -> fp16
        ln_kernel<<<cdiv(ROWS_R,8), 256, 0, s1>>>(p_r0, p_rh,
            lnr_g + l*CNEW, lnr_b + l*CNEW, CNEW, 1e-5f, 1, ROWS_R);
        // k|v = r @ [k_w; v_w] -> fp16 split   (3136 x 1728, K=960)
        tcmm_kernel<64,64,2,2,5><<<dim3(NKV/64, ROWS_R/64), 128, SMEM_OF(64,64), s1>>>(
            p_rh, wkv + (size_t)l*NKV*CNEW,
            nullptr, nullptr, nullptr, p_kh, p_vh, ROWS_R, NKV, CNEW);
        cudaEventRecord(evJoin, s1);

        // q = y @ q_w -> fp16   (12544 x 960, K=768)  [concurrent with s1 chain]
        tcmm_kernel<128,64,4,2,4><<<dim3(CNEW/64, ROWS_X/128), 256, SMEM_OF(128,64)>>>(
            p_yh, wq + (size_t)l*CNEW*CDIM,
            nullptr, nullptr, nullptr, p_qh, nullptr, ROWS_X, CNEW, CDIM);

        // ---- join ----
        cudaStreamWaitEvent(0, evJoin, 0);

        attn_kernel<<<BATCH*NHEAD, 256>>>(p_qh, p_kh, p_vh, p_oh);
        // x(out) = resid + o @ proj + b   (12544 x 768, K=768)
        tcmm_kernel<128,128,4,2,3><<<dim3(CDIM/128, ROWS_X/128), 256, SMEM_OF(128,128)>>>(
            p_oh, wp + (size_t)l*CDIM*CDIM,
            proj_b + l*CDIM, xin, xcur, nullptr, nullptr, ROWS_X, CDIM, CDIM);
        // z = LN2(x) -> fp16
        ln_kernel<<<cdiv(ROWS_X,8), 256>>>(xcur, p_yh,
            ln2_g + l*CDIM, ln2_b + l*CDIM, CDIM, 1e-6f, 0, ROWS_X);
        // h = gelu(z @ fc1 + b) -> fp16  (12544 x 3072, K=768)
        tcmm_kernel<128,128,4,2,2><<<dim3(HIDDIM/128, ROWS_X/128), 256, SMEM_OF(128,128)>>>(
            p_yh, w1 + (size_t)l*HIDDIM*CDIM,
            fc1_b + l*HIDDIM, nullptr, nullptr, p_hh, nullptr, ROWS_X, HIDDIM, CDIM);
        // x += h @ fc2 + b      (12544 x 768, K=3072)
        tcmm_kernel<128,128,4,2,3><<<dim3(CDIM/128, ROWS_X/128), 256, SMEM_OF(128,128)>>>(
            p_hh, w2 + (size_t)l*CDIM*HIDDIM,
            fc2_b + l*CDIM, xcur, xcur, nullptr, nullptr, ROWS_X, CDIM, HIDDIM);
    }
}